// round 5
// baseline (speedup 1.0000x reference)
#include <cuda_runtime.h>
#include <math.h>

#define B_ 32
#define S_ 128
#define BS_ 4096
#define FEAT_D_ 28224
#define SPLITK 4
#define KSPLIT_LEN (FEAT_D_ / SPLITK)   // 7056

// ---------------- scratch ----------------
__device__ float g_feat[(size_t)BS_ * FEAT_D_];
__device__ float g_ig[BS_ * 192];
__device__ float g_part[(size_t)SPLITK * BS_ * 192];
__device__ float g_allh[BS_ * 64];

// ---------------- bool-mask dtype detection ----------------
__device__ __forceinline__ int detect_bool_mode(const unsigned char* p) {
    bool any80 = false, nz = false;
    for (int i = 0; i < 256; i++) {
        unsigned char v = p[i];
        int m = i & 3;
        if (m == 2 && v == 0x80) any80 = true;
        if (m != 0 && v != 0) nz = true;
    }
    if (!nz) return 1;
    if (any80) return 2;
    return 0;
}
__device__ __forceinline__ bool get_mask(const void* p, int i, int mode) {
    if (mode == 1) return ((const int*)p)[i] != 0;
    if (mode == 2) return ((const float*)p)[i] != 0.0f;
    return ((const unsigned char*)p)[i] != 0;
}

// ---------------- packed f32x2 helpers (sm_100+) ----------------
__device__ __forceinline__ unsigned long long pack2(float v) {
    unsigned long long r;
    asm("mov.b64 %0, {%1, %1};" : "=l"(r) : "f"(v));
    return r;
}
__device__ __forceinline__ void fma2(unsigned long long& acc, unsigned long long a,
                                     unsigned long long b) {
    asm("fma.rn.f32x2 %0, %1, %2, %0;" : "+l"(acc) : "l"(a), "l"(b));
}
__device__ __forceinline__ void unpack2(unsigned long long v, float& lo, float& hi) {
    asm("mov.b64 {%0, %1}, %2;" : "=f"(lo), "=f"(hi) : "l"(v));
}

// ---------------- conv building block (f32x2 packed) ----------------
template<int Cin, int Cout, int Win, bool GLOBAL>
__device__ __forceinline__ void conv2x2(const float* __restrict__ si,
                                        float* __restrict__ so,
                                        float* __restrict__ go,
                                        const float* __restrict__ wsm,
                                        const float* __restrict__ bsm) {
    constexpr int Wout = Win - 1;
    constexpr int Npix = Wout * Wout;
    constexpr int HWin = Win * Win;
    constexpr int NPAIR = (Npix + 1) / 2;
    constexpr int NG = Cout / 16;
    constexpr int ITEMS = NPAIR * NG;
    constexpr int WSTEP = Cout / 4;   // ulonglong2 (16B) stride per ci

    for (int it = threadIdx.x; it < ITEMS; it += 256) {
        int pr = it % NPAIR, cg = it / NPAIR;
        int p0 = pr, p1 = pr + NPAIR;
        bool has1 = (p1 < Npix);
        int p1c = has1 ? p1 : p0;
        int y0 = p0 / Wout, x0 = p0 - y0 * Wout;
        int y1 = p1c / Wout, x1 = p1c - y1 * Wout;
        int in0 = y0 * Win + x0, in1 = y1 * Win + x1;
        unsigned long long acc0p[8], acc1p[8];
#pragma unroll
        for (int j = 0; j < 8; j++) { acc0p[j] = 0ULL; acc1p[j] = 0ULL; }
#pragma unroll
        for (int d = 0; d < 4; d++) {
            int dy = d >> 1, dx = d & 1;
            const float* ip0 = si + in0 + dy * Win + dx;
            const float* ip1 = si + in1 + dy * Win + dx;
            const ulonglong2* wq = (const ulonglong2*)(wsm + (d * Cin) * Cout) + cg * 4;
#pragma unroll 8
            for (int ci = 0; ci < Cin; ci++) {
                unsigned long long v0p = pack2(ip0[ci * HWin]);
                unsigned long long v1p = pack2(ip1[ci * HWin]);
                ulonglong2 w0 = wq[ci * WSTEP + 0];
                ulonglong2 w1 = wq[ci * WSTEP + 1];
                ulonglong2 w2 = wq[ci * WSTEP + 2];
                ulonglong2 w3 = wq[ci * WSTEP + 3];
                fma2(acc0p[0], v0p, w0.x); fma2(acc1p[0], v1p, w0.x);
                fma2(acc0p[1], v0p, w0.y); fma2(acc1p[1], v1p, w0.y);
                fma2(acc0p[2], v0p, w1.x); fma2(acc1p[2], v1p, w1.x);
                fma2(acc0p[3], v0p, w1.y); fma2(acc1p[3], v1p, w1.y);
                fma2(acc0p[4], v0p, w2.x); fma2(acc1p[4], v1p, w2.x);
                fma2(acc0p[5], v0p, w2.y); fma2(acc1p[5], v1p, w2.y);
                fma2(acc0p[6], v0p, w3.x); fma2(acc1p[6], v1p, w3.x);
                fma2(acc0p[7], v0p, w3.y); fma2(acc1p[7], v1p, w3.y);
            }
        }
        float acc0[16], acc1[16];
#pragma unroll
        for (int j = 0; j < 8; j++) {
            unpack2(acc0p[j], acc0[2 * j], acc0[2 * j + 1]);
            unpack2(acc1p[j], acc1[2 * j], acc1[2 * j + 1]);
        }
        if constexpr (GLOBAL) {
            float4* g0 = (float4*)(go + p0 * Cout + cg * 16);
#pragma unroll
            for (int q = 0; q < 4; q++) {
                float4 v;
                v.x = fmaxf(acc0[q * 4 + 0] + bsm[cg * 16 + q * 4 + 0], 0.f);
                v.y = fmaxf(acc0[q * 4 + 1] + bsm[cg * 16 + q * 4 + 1], 0.f);
                v.z = fmaxf(acc0[q * 4 + 2] + bsm[cg * 16 + q * 4 + 2], 0.f);
                v.w = fmaxf(acc0[q * 4 + 3] + bsm[cg * 16 + q * 4 + 3], 0.f);
                g0[q] = v;
            }
            if (has1) {
                float4* g1 = (float4*)(go + p1 * Cout + cg * 16);
#pragma unroll
                for (int q = 0; q < 4; q++) {
                    float4 v;
                    v.x = fmaxf(acc1[q * 4 + 0] + bsm[cg * 16 + q * 4 + 0], 0.f);
                    v.y = fmaxf(acc1[q * 4 + 1] + bsm[cg * 16 + q * 4 + 1], 0.f);
                    v.z = fmaxf(acc1[q * 4 + 2] + bsm[cg * 16 + q * 4 + 2], 0.f);
                    v.w = fmaxf(acc1[q * 4 + 3] + bsm[cg * 16 + q * 4 + 3], 0.f);
                    g1[q] = v;
                }
            }
        } else {
#pragma unroll
            for (int j = 0; j < 16; j++) {
                float bj = bsm[cg * 16 + j];
                so[(cg * 16 + j) * Npix + p0] = fmaxf(acc0[j] + bj, 0.f);
            }
            if (has1) {
#pragma unroll
                for (int j = 0; j < 16; j++) {
                    float bj = bsm[cg * 16 + j];
                    so[(cg * 16 + j) * Npix + p1] = fmaxf(acc1[j] + bj, 0.f);
                }
            }
        }
    }
}

#define CONV_SMEM_FLOATS 35840

__global__ void __launch_bounds__(256) conv_kernel(
    const int* __restrict__ positions, const void* __restrict__ umask,
    const int* __restrict__ tile_type, const int* __restrict__ rpos,
    const void* __restrict__ rmask, const float* __restrict__ reward,
    const float* __restrict__ emb_tile, const float* __restrict__ emb_unit,
    const float* __restrict__ w1, const float* __restrict__ b1,
    const float* __restrict__ w2, const float* __restrict__ b2,
    const float* __restrict__ w3, const float* __restrict__ b3) {
    extern __shared__ float sm[];
    float* bufA = sm;          // 15488
    float* bufB = sm + 15488;  // 8464
    float* wb1 = sm + 23952;   // 1536
    float* wb2 = sm + 25488;   // 2048
    float* wb3 = sm + 27536;   // 8192
    float* sb  = sm + 35728;   // 112
    int tid = threadIdx.x, bs = blockIdx.x;

    for (int i = tid; i < 1536; i += 256) wb1[i] = w1[i];
    for (int i = tid; i < 2048; i += 256) wb2[i] = w2[i];
    for (int i = tid; i < 8192; i += 256) wb3[i] = w3[i];
    if (tid < 16) sb[tid] = b1[tid];
    else if (tid < 48) sb[tid] = b2[tid - 16];
    else if (tid < 112) sb[tid] = b3[tid - 48];

    for (int i = tid; i < 19 * 576; i += 256) bufA[4 * 576 + i] = 0.f;
    float rw = reward[bs];
    for (int p = tid; p < 576; p += 256) {
        int tt = tile_type[bs * 576 + p] * 4;
        bufA[p] = emb_tile[tt];
        bufA[576 + p] = emb_tile[tt + 1];
        bufA[1152 + p] = emb_tile[tt + 2];
        bufA[1728 + p] = emb_tile[tt + 3];
        bufA[23 * 576 + p] = rw;
    }
    __syncthreads();
    if (tid < 32) {
        int mode = detect_bool_mode((const unsigned char*)umask);
        if (get_mask(umask, bs * 32 + tid, mode)) {
            int t = tid >> 4, u = tid & 15;
            int pb = (bs * 32 + tid) * 2;
            int y = positions[pb], x = positions[pb + 1];
            int cell = y * 24 + x;
            atomicAdd(&bufA[(4 + t) * 576 + cell], 0.0625f);
#pragma unroll
            for (int e = 0; e < 8; e++)
                atomicAdd(&bufA[(6 + t * 8 + e) * 576 + cell], emb_unit[u * 8 + e]);
        }
    } else if (tid < 38) {
        int r = tid - 32;
        int mode = detect_bool_mode((const unsigned char*)rmask);
        if (get_mask(rmask, bs * 6 + r, mode)) {
            int pb = (bs * 6 + r) * 2;
            int y = rpos[pb], x = rpos[pb + 1];
            atomicAdd(&bufA[22 * 576 + y * 24 + x], 1.0f);
        }
    }
    __syncthreads();
    conv2x2<24, 16, 24, false>(bufA, bufB, nullptr, wb1, sb);
    __syncthreads();
    conv2x2<16, 32, 23, false>(bufB, bufA, nullptr, wb2, sb + 16);
    __syncthreads();
    conv2x2<32, 64, 22, true>(bufA, nullptr, g_feat + (size_t)bs * FEAT_D_, wb3, sb + 48);
}

// ---------------- 3xTF32 tensor-core GEMM ----------------
__device__ __forceinline__ unsigned cvt_tf32(float v) {
    unsigned o;
    asm("cvt.rna.tf32.f32 %0, %1;" : "=r"(o) : "f"(v));
    return o;
}
__device__ __forceinline__ void split_tf32(float x, unsigned& hi, unsigned& lo) {
    hi = cvt_tf32(x);
    float r = x - __uint_as_float(hi);
    lo = cvt_tf32(r);
}
__device__ __forceinline__ void mma_tf32(float* acc, const unsigned* a, const unsigned* b) {
    asm volatile(
        "mma.sync.aligned.m16n8k8.row.col.f32.tf32.tf32.f32 "
        "{%0,%1,%2,%3}, {%4,%5,%6,%7}, {%8,%9}, {%0,%1,%2,%3};"
        : "+f"(acc[0]), "+f"(acc[1]), "+f"(acc[2]), "+f"(acc[3])
        : "r"(a[0]), "r"(a[1]), "r"(a[2]), "r"(a[3]), "r"(b[0]), "r"(b[1]));
}

#define SPAD 72

__global__ void __launch_bounds__(256) gemm_tf32_kernel(const float* __restrict__ Bmat) {
    __shared__ unsigned Ah[16][SPAD];
    __shared__ unsigned Al[16][SPAD];
    __shared__ unsigned Bh[16][SPAD];
    __shared__ unsigned Bl[16][SPAD];
    const int K = FEAT_D_;
    int tid = threadIdx.x;
    int m0 = blockIdx.x * 64, n0 = blockIdx.y * 64;
    int kz = blockIdx.z;
    int kbeg = kz * KSPLIT_LEN;

    int warp = tid >> 5, lane = tid & 31;
    int wm = (warp & 1) * 32;
    int wn = (warp >> 1) * 16;
    int grp = lane >> 2, tig = lane & 3;

    int lr = tid >> 2;
    int lk = (tid & 3) * 4;

    const float* A = g_feat;
    const float* Bp = Bmat;

    float4 pa = *(const float4*)&A[(size_t)(m0 + lr) * K + kbeg + lk];
    float4 pb = *(const float4*)&Bp[(size_t)(n0 + lr) * K + kbeg + lk];

    float acc[2][2][4];
#pragma unroll
    for (int i = 0; i < 2; i++)
#pragma unroll
        for (int j = 0; j < 2; j++)
#pragma unroll
            for (int q = 0; q < 4; q++) acc[i][j][q] = 0.f;

    const int NIT = KSPLIT_LEN / 16;  // 441
    for (int it = 0; it < NIT; it++) {
        {
            unsigned h, l;
            split_tf32(pa.x, h, l); Ah[lk + 0][lr] = h; Al[lk + 0][lr] = l;
            split_tf32(pa.y, h, l); Ah[lk + 1][lr] = h; Al[lk + 1][lr] = l;
            split_tf32(pa.z, h, l); Ah[lk + 2][lr] = h; Al[lk + 2][lr] = l;
            split_tf32(pa.w, h, l); Ah[lk + 3][lr] = h; Al[lk + 3][lr] = l;
            split_tf32(pb.x, h, l); Bh[lk + 0][lr] = h; Bl[lk + 0][lr] = l;
            split_tf32(pb.y, h, l); Bh[lk + 1][lr] = h; Bl[lk + 1][lr] = l;
            split_tf32(pb.z, h, l); Bh[lk + 2][lr] = h; Bl[lk + 2][lr] = l;
            split_tf32(pb.w, h, l); Bh[lk + 3][lr] = h; Bl[lk + 3][lr] = l;
        }
        __syncthreads();
        if (it + 1 < NIT) {
            int kn = kbeg + (it + 1) * 16;
            pa = *(const float4*)&A[(size_t)(m0 + lr) * K + kn + lk];
            pb = *(const float4*)&Bp[(size_t)(n0 + lr) * K + kn + lk];
        }
#pragma unroll
        for (int k8 = 0; k8 < 2; k8++) {
            int kr = k8 * 8;
            unsigned afh[2][4], afl[2][4], bfh[2][2], bfl[2][2];
#pragma unroll
            for (int mi = 0; mi < 2; mi++) {
                int mb = wm + mi * 16 + grp;
                afh[mi][0] = Ah[kr + tig][mb];
                afh[mi][1] = Ah[kr + tig][mb + 8];
                afh[mi][2] = Ah[kr + tig + 4][mb];
                afh[mi][3] = Ah[kr + tig + 4][mb + 8];
                afl[mi][0] = Al[kr + tig][mb];
                afl[mi][1] = Al[kr + tig][mb + 8];
                afl[mi][2] = Al[kr + tig + 4][mb];
                afl[mi][3] = Al[kr + tig + 4][mb + 8];
            }
#pragma unroll
            for (int ni = 0; ni < 2; ni++) {
                int nb = wn + ni * 8 + grp;
                bfh[ni][0] = Bh[kr + tig][nb];
                bfh[ni][1] = Bh[kr + tig + 4][nb];
                bfl[ni][0] = Bl[kr + tig][nb];
                bfl[ni][1] = Bl[kr + tig + 4][nb];
            }
#pragma unroll
            for (int mi = 0; mi < 2; mi++)
#pragma unroll
                for (int ni = 0; ni < 2; ni++) {
                    mma_tf32(acc[mi][ni], afl[mi], bfh[ni]);
                    mma_tf32(acc[mi][ni], afh[mi], bfl[ni]);
                    mma_tf32(acc[mi][ni], afh[mi], bfh[ni]);
                }
        }
        __syncthreads();
    }

    float* out = g_part + (size_t)kz * (BS_ * 192);
#pragma unroll
    for (int mi = 0; mi < 2; mi++) {
#pragma unroll
        for (int ni = 0; ni < 2; ni++) {
            int col = n0 + wn + ni * 8 + 2 * tig;
            int row0 = m0 + wm + mi * 16 + grp;
            float2 v0 = make_float2(acc[mi][ni][0], acc[mi][ni][1]);
            float2 v1 = make_float2(acc[mi][ni][2], acc[mi][ni][3]);
            *(float2*)&out[(size_t)row0 * 192 + col] = v0;
            *(float2*)&out[(size_t)(row0 + 8) * 192 + col] = v1;
        }
    }
}

__global__ void __launch_bounds__(256) reduce_kernel(const float* __restrict__ bi) {
    int idx = blockIdx.x * 256 + threadIdx.x;
    if (idx >= BS_ * 192) return;
    int n = idx % 192;
    float s = bi[n];
#pragma unroll
    for (int z = 0; z < SPLITK; z++) s += g_part[(size_t)z * (BS_ * 192) + idx];
    g_ig[idx] = s;
}

// ---------------- GRU scan (latency-hidden) ----------------
__global__ void __launch_bounds__(192) gru_kernel(const float* __restrict__ h0,
                                                  const float* __restrict__ Wh,
                                                  const float* __restrict__ bn,
                                                  float* __restrict__ hfinal) {
    int b = blockIdx.x, g = threadIdx.x;
    __shared__ float h[64];
    __shared__ float hg[192];
    __shared__ float sig[192];
    float w[64];
#pragma unroll
    for (int k = 0; k < 64; k++) w[k] = Wh[g * 64 + k];
    float bnv = (g < 64) ? bn[g] : 0.f;
    if (g < 64) h[g] = h0[b * 64 + g];
    float igv = g_ig[(b * 128 + 0) * 192 + g];  // prefetch t=0
    __syncthreads();
    for (int t = 0; t < 128; t++) {
        float a0 = 0.f, a1 = 0.f, a2 = 0.f, a3 = 0.f;
#pragma unroll
        for (int k = 0; k < 64; k += 4) {
            a0 += w[k] * h[k];
            a1 += w[k + 1] * h[k + 1];
            a2 += w[k + 2] * h[k + 2];
            a3 += w[k + 3] * h[k + 3];
        }
        hg[g] = (a0 + a1) + (a2 + a3);
        sig[g] = igv;
        __syncthreads();
        // prefetch next step's ig while gates compute
        int tn = (t < 127) ? t + 1 : 127;
        igv = g_ig[(b * 128 + tn) * 192 + g];
        if (g < 64) {
            float rr = 1.f / (1.f + __expf(-(sig[g] + hg[g])));
            float zz = 1.f / (1.f + __expf(-(sig[64 + g] + hg[64 + g])));
            float nn = tanhf(sig[128 + g] + rr * (hg[128 + g] + bnv));
            float hn = (1.f - zz) * nn + zz * h[g];
            h[g] = hn;
            g_allh[(b * 128 + t) * 64 + g] = hn;
        }
        __syncthreads();
    }
    if (g < 64) hfinal[b * 64 + g] = h[g];
}

// ---------------- heads ----------------
#define HEADS_SMEM_BYTES (14816 * 4)
__global__ void __launch_bounds__(128) heads_kernel(
    const float* __restrict__ Wa1, const float* __restrict__ ba1,
    const float* __restrict__ Wa2, const float* __restrict__ ba2,
    const float* __restrict__ Wc1, const float* __restrict__ bc1,
    const float* __restrict__ Wc2, const float* __restrict__ bc2,
    float* __restrict__ logits, float* __restrict__ values) {
    extern __shared__ float s[];
    float* sWa1 = s;
    float* sWc1 = s + 4096;
    float* sWa2 = s + 8192;
    float* sWc2 = s + 14336;
    float* sba1 = s + 14400;
    float* sbc1 = s + 14464;
    float* sba2 = s + 14528;
    float* sh   = s + 14624;
    float* sa   = s + 14688;
    float* sc   = s + 14752;
    int tid = threadIdx.x;
    for (int i = tid; i < 4096; i += 128) { sWa1[i] = Wa1[i]; sWc1[i] = Wc1[i]; }
    for (int i = tid; i < 6144; i += 128) sWa2[i] = Wa2[i];
    if (tid < 64) { sWc2[tid] = Wc2[tid]; sba1[tid] = ba1[tid]; sbc1[tid] = bc1[tid]; }
    if (tid < 96) sba2[tid] = ba2[tid];
    float bc2v = bc2[0];
    __syncthreads();
    for (int r = blockIdx.x * 32; r < blockIdx.x * 32 + 32; r++) {
        if (tid < 64) sh[tid] = g_allh[r * 64 + tid];
        __syncthreads();
        {
            int j = tid & 63;
            const float* W = (tid < 64) ? sWa1 : sWc1;
            float acc = 0.f;
#pragma unroll
            for (int i = 0; i < 64; i++) acc += sh[i] * W[i * 64 + j];
            float v = tanhf(acc + ((tid < 64) ? sba1[j] : sbc1[j]));
            if (tid < 64) sa[j] = v; else sc[j] = v;
        }
        __syncthreads();
        if (tid < 96) {
            float acc = sba2[tid];
#pragma unroll
            for (int j = 0; j < 64; j++) acc += sa[j] * sWa2[j * 96 + tid];
            logits[r * 96 + tid] = acc;
        } else if (tid == 96) {
            float acc = bc2v;
#pragma unroll
            for (int j = 0; j < 64; j++) acc += sc[j] * sWc2[j];
            values[r] = acc;
        }
        __syncthreads();
    }
}

// ---------------- launch ----------------
extern "C" void kernel_launch(void* const* d_in, const int* in_sizes, int n_in,
                              void* d_out, int out_size) {
    const int*   positions = (const int*)d_in[0];
    const void*  umask     = d_in[1];
    const int*   tile      = (const int*)d_in[2];
    const int*   rpos      = (const int*)d_in[3];
    const void*  rmask     = d_in[4];
    const float* reward    = (const float*)d_in[5];
    const float* hidden    = (const float*)d_in[6];
    const float* emb_tile  = (const float*)d_in[7];
    const float* emb_unit  = (const float*)d_in[8];
    const float* w1 = (const float*)d_in[9];
    const float* b1 = (const float*)d_in[10];
    const float* w2 = (const float*)d_in[11];
    const float* b2 = (const float*)d_in[12];
    const float* w3 = (const float*)d_in[13];
    const float* b3 = (const float*)d_in[14];
    const float* Wi = (const float*)d_in[15];
    const float* Wh = (const float*)d_in[16];
    const float* bi = (const float*)d_in[17];
    const float* bn = (const float*)d_in[18];
    const float* Wa1 = (const float*)d_in[19];
    const float* ba1 = (const float*)d_in[20];
    const float* Wa2 = (const float*)d_in[21];
    const float* ba2 = (const float*)d_in[22];
    const float* Wc1 = (const float*)d_in[23];
    const float* bc1 = (const float*)d_in[24];
    const float* Wc2 = (const float*)d_in[25];
    const float* bc2 = (const float*)d_in[26];
    float* out = (float*)d_out;

    float* out_logits = out;
    float* out_values = out + 393216;
    float* out_hidden = out + 397312;

    const int conv_smem = CONV_SMEM_FLOATS * (int)sizeof(float);
    cudaFuncSetAttribute(conv_kernel, cudaFuncAttributeMaxDynamicSharedMemorySize, conv_smem);
    cudaFuncSetAttribute(heads_kernel, cudaFuncAttributeMaxDynamicSharedMemorySize, HEADS_SMEM_BYTES);

    conv_kernel<<<BS_, 256, conv_smem>>>(positions, umask, tile, rpos, rmask, reward,
                                         emb_tile, emb_unit, w1, b1, w2, b2, w3, b3);
    gemm_tf32_kernel<<<dim3(64, 3, SPLITK), 256>>>(Wi);
    reduce_kernel<<<(BS_ * 192 + 255) / 256, 256>>>(bi);
    gru_kernel<<<32, 192>>>(hidden, Wh, bn, out_hidden);
    heads_kernel<<<128, 128, HEADS_SMEM_BYTES>>>(Wa1, ba1, Wa2, ba2, Wc1, bc1, Wc2, bc2,
                                                 out_logits, out_values);
}

// round 6
// speedup vs baseline: 1.0993x; 1.0993x over previous
#include <cuda_runtime.h>
#include <math.h>

#define B_ 32
#define S_ 128
#define BS_ 4096
#define FEAT_D_ 28224
#define SPLITK 4
#define KSPLIT_LEN (FEAT_D_ / SPLITK)   // 7056

// ---------------- scratch ----------------
__device__ float g_feat[(size_t)BS_ * FEAT_D_];
__device__ float g_ig[BS_ * 192];
__device__ float g_part[(size_t)SPLITK * BS_ * 192];
__device__ float g_allh[BS_ * 64];

// ---------------- bool-mask dtype detection ----------------
__device__ __forceinline__ int detect_bool_mode(const unsigned char* p) {
    bool any80 = false, nz = false;
    for (int i = 0; i < 256; i++) {
        unsigned char v = p[i];
        int m = i & 3;
        if (m == 2 && v == 0x80) any80 = true;
        if (m != 0 && v != 0) nz = true;
    }
    if (!nz) return 1;
    if (any80) return 2;
    return 0;
}
__device__ __forceinline__ bool get_mask(const void* p, int i, int mode) {
    if (mode == 1) return ((const int*)p)[i] != 0;
    if (mode == 2) return ((const float*)p)[i] != 0.0f;
    return ((const unsigned char*)p)[i] != 0;
}

// ---------------- conv building block (FFMA, reverted from f32x2) ----------------
template<int Cin, int Cout, int Win, bool GLOBAL>
__device__ __forceinline__ void conv2x2(const float* __restrict__ si,
                                        float* __restrict__ so,
                                        float* __restrict__ go,
                                        const float* __restrict__ wsm,
                                        const float* __restrict__ bsm) {
    constexpr int Wout = Win - 1;
    constexpr int Npix = Wout * Wout;
    constexpr int HWin = Win * Win;
    constexpr int NPAIR = (Npix + 1) / 2;
    constexpr int NG = Cout / 16;
    constexpr int ITEMS = NPAIR * NG;
    constexpr int WSTEP = Cout / 4;

    for (int it = threadIdx.x; it < ITEMS; it += 256) {
        int pr = it % NPAIR, cg = it / NPAIR;
        int p0 = pr, p1 = pr + NPAIR;
        bool has1 = (p1 < Npix);
        int p1c = has1 ? p1 : p0;
        int y0 = p0 / Wout, x0 = p0 - y0 * Wout;
        int y1 = p1c / Wout, x1 = p1c - y1 * Wout;
        int in0 = y0 * Win + x0, in1 = y1 * Win + x1;
        float acc0[16], acc1[16];
#pragma unroll
        for (int j = 0; j < 16; j++) { acc0[j] = 0.f; acc1[j] = 0.f; }
#pragma unroll
        for (int d = 0; d < 4; d++) {
            int dy = d >> 1, dx = d & 1;
            const float* ip0 = si + in0 + dy * Win + dx;
            const float* ip1 = si + in1 + dy * Win + dx;
            const float4* wq = (const float4*)(wsm + (d * Cin) * Cout) + cg * 4;
#pragma unroll 8
            for (int ci = 0; ci < Cin; ci++) {
                float v0 = ip0[ci * HWin];
                float v1 = ip1[ci * HWin];
                float4 wv[4];
                wv[0] = wq[ci * WSTEP + 0];
                wv[1] = wq[ci * WSTEP + 1];
                wv[2] = wq[ci * WSTEP + 2];
                wv[3] = wq[ci * WSTEP + 3];
#pragma unroll
                for (int q = 0; q < 4; q++) {
                    acc0[q * 4 + 0] += v0 * wv[q].x;
                    acc0[q * 4 + 1] += v0 * wv[q].y;
                    acc0[q * 4 + 2] += v0 * wv[q].z;
                    acc0[q * 4 + 3] += v0 * wv[q].w;
                    acc1[q * 4 + 0] += v1 * wv[q].x;
                    acc1[q * 4 + 1] += v1 * wv[q].y;
                    acc1[q * 4 + 2] += v1 * wv[q].z;
                    acc1[q * 4 + 3] += v1 * wv[q].w;
                }
            }
        }
        if constexpr (GLOBAL) {
            float4* g0 = (float4*)(go + p0 * Cout + cg * 16);
#pragma unroll
            for (int q = 0; q < 4; q++) {
                float4 v;
                v.x = fmaxf(acc0[q * 4 + 0] + bsm[cg * 16 + q * 4 + 0], 0.f);
                v.y = fmaxf(acc0[q * 4 + 1] + bsm[cg * 16 + q * 4 + 1], 0.f);
                v.z = fmaxf(acc0[q * 4 + 2] + bsm[cg * 16 + q * 4 + 2], 0.f);
                v.w = fmaxf(acc0[q * 4 + 3] + bsm[cg * 16 + q * 4 + 3], 0.f);
                g0[q] = v;
            }
            if (has1) {
                float4* g1 = (float4*)(go + p1 * Cout + cg * 16);
#pragma unroll
                for (int q = 0; q < 4; q++) {
                    float4 v;
                    v.x = fmaxf(acc1[q * 4 + 0] + bsm[cg * 16 + q * 4 + 0], 0.f);
                    v.y = fmaxf(acc1[q * 4 + 1] + bsm[cg * 16 + q * 4 + 1], 0.f);
                    v.z = fmaxf(acc1[q * 4 + 2] + bsm[cg * 16 + q * 4 + 2], 0.f);
                    v.w = fmaxf(acc1[q * 4 + 3] + bsm[cg * 16 + q * 4 + 3], 0.f);
                    g1[q] = v;
                }
            }
        } else {
#pragma unroll
            for (int j = 0; j < 16; j++) {
                float bj = bsm[cg * 16 + j];
                so[(cg * 16 + j) * Npix + p0] = fmaxf(acc0[j] + bj, 0.f);
            }
            if (has1) {
#pragma unroll
                for (int j = 0; j < 16; j++) {
                    float bj = bsm[cg * 16 + j];
                    so[(cg * 16 + j) * Npix + p1] = fmaxf(acc1[j] + bj, 0.f);
                }
            }
        }
    }
}

// smem (floats): bufA 15488 | bufB 8464 | wb1 1536 | wb2 2048 | sb 112 = 27648
// wb3 (8192 floats) overlays bufB after conv2 no longer needs it.
// 110.6 KB -> 2 CTAs/SM (16 warps) instead of 1 (8 warps).
#define CONV_SMEM_FLOATS 27648

__global__ void __launch_bounds__(256, 2) conv_kernel(
    const int* __restrict__ positions, const void* __restrict__ umask,
    const int* __restrict__ tile_type, const int* __restrict__ rpos,
    const void* __restrict__ rmask, const float* __restrict__ reward,
    const float* __restrict__ emb_tile, const float* __restrict__ emb_unit,
    const float* __restrict__ w1, const float* __restrict__ b1,
    const float* __restrict__ w2, const float* __restrict__ b2,
    const float* __restrict__ w3, const float* __restrict__ b3) {
    extern __shared__ float sm[];
    float* bufA = sm;          // 15488
    float* bufB = sm + 15488;  // 8464 (reused for wb3 in stage 3)
    float* wb1 = sm + 23952;   // 1536
    float* wb2 = sm + 25488;   // 2048
    float* sb  = sm + 27536;   // 112 biases
    float* wb3 = bufB;         // overlay
    int tid = threadIdx.x, bs = blockIdx.x;

    for (int i = tid; i < 1536; i += 256) wb1[i] = w1[i];
    for (int i = tid; i < 2048; i += 256) wb2[i] = w2[i];
    if (tid < 16) sb[tid] = b1[tid];
    else if (tid < 48) sb[tid] = b2[tid - 16];
    else if (tid < 112) sb[tid] = b3[tid - 48];

    for (int i = tid; i < 19 * 576; i += 256) bufA[4 * 576 + i] = 0.f;
    float rw = reward[bs];
    for (int p = tid; p < 576; p += 256) {
        int tt = tile_type[bs * 576 + p] * 4;
        bufA[p] = emb_tile[tt];
        bufA[576 + p] = emb_tile[tt + 1];
        bufA[1152 + p] = emb_tile[tt + 2];
        bufA[1728 + p] = emb_tile[tt + 3];
        bufA[23 * 576 + p] = rw;
    }
    __syncthreads();
    if (tid < 32) {
        int mode = detect_bool_mode((const unsigned char*)umask);
        if (get_mask(umask, bs * 32 + tid, mode)) {
            int t = tid >> 4, u = tid & 15;
            int pb = (bs * 32 + tid) * 2;
            int y = positions[pb], x = positions[pb + 1];
            int cell = y * 24 + x;
            atomicAdd(&bufA[(4 + t) * 576 + cell], 0.0625f);
#pragma unroll
            for (int e = 0; e < 8; e++)
                atomicAdd(&bufA[(6 + t * 8 + e) * 576 + cell], emb_unit[u * 8 + e]);
        }
    } else if (tid < 38) {
        int r = tid - 32;
        int mode = detect_bool_mode((const unsigned char*)rmask);
        if (get_mask(rmask, bs * 6 + r, mode)) {
            int pb = (bs * 6 + r) * 2;
            int y = rpos[pb], x = rpos[pb + 1];
            atomicAdd(&bufA[22 * 576 + y * 24 + x], 1.0f);
        }
    }
    __syncthreads();
    conv2x2<24, 16, 24, false>(bufA, bufB, nullptr, wb1, sb);
    __syncthreads();
    conv2x2<16, 32, 23, false>(bufB, bufA, nullptr, wb2, sb + 16);
    __syncthreads();                 // conv2 done reading bufB
    for (int i = tid; i < 8192; i += 256) wb3[i] = w3[i];   // overlay wb3 into bufB
    __syncthreads();
    conv2x2<32, 64, 22, true>(bufA, nullptr, g_feat + (size_t)bs * FEAT_D_, wb3, sb + 48);
}

// ---------------- 3xTF32 tensor-core GEMM ----------------
__device__ __forceinline__ unsigned cvt_tf32(float v) {
    unsigned o;
    asm("cvt.rna.tf32.f32 %0, %1;" : "=r"(o) : "f"(v));
    return o;
}
__device__ __forceinline__ void split_tf32(float x, unsigned& hi, unsigned& lo) {
    hi = cvt_tf32(x);
    float r = x - __uint_as_float(hi);
    lo = cvt_tf32(r);
}
__device__ __forceinline__ void mma_tf32(float* acc, const unsigned* a, const unsigned* b) {
    asm volatile(
        "mma.sync.aligned.m16n8k8.row.col.f32.tf32.tf32.f32 "
        "{%0,%1,%2,%3}, {%4,%5,%6,%7}, {%8,%9}, {%0,%1,%2,%3};"
        : "+f"(acc[0]), "+f"(acc[1]), "+f"(acc[2]), "+f"(acc[3])
        : "r"(a[0]), "r"(a[1]), "r"(a[2]), "r"(a[3]), "r"(b[0]), "r"(b[1]));
}

#define SPAD 72

__global__ void __launch_bounds__(256) gemm_tf32_kernel(const float* __restrict__ Bmat) {
    __shared__ unsigned Ah[16][SPAD];
    __shared__ unsigned Al[16][SPAD];
    __shared__ unsigned Bh[16][SPAD];
    __shared__ unsigned Bl[16][SPAD];
    const int K = FEAT_D_;
    int tid = threadIdx.x;
    int m0 = blockIdx.x * 64, n0 = blockIdx.y * 64;
    int kz = blockIdx.z;
    int kbeg = kz * KSPLIT_LEN;

    int warp = tid >> 5, lane = tid & 31;
    int wm = (warp & 1) * 32;
    int wn = (warp >> 1) * 16;
    int grp = lane >> 2, tig = lane & 3;

    int lr = tid >> 2;
    int lk = (tid & 3) * 4;

    const float* A = g_feat;
    const float* Bp = Bmat;

    float4 pa = *(const float4*)&A[(size_t)(m0 + lr) * K + kbeg + lk];
    float4 pb = *(const float4*)&Bp[(size_t)(n0 + lr) * K + kbeg + lk];

    float acc[2][2][4];
#pragma unroll
    for (int i = 0; i < 2; i++)
#pragma unroll
        for (int j = 0; j < 2; j++)
#pragma unroll
            for (int q = 0; q < 4; q++) acc[i][j][q] = 0.f;

    const int NIT = KSPLIT_LEN / 16;  // 441
    for (int it = 0; it < NIT; it++) {
        {
            unsigned h, l;
            split_tf32(pa.x, h, l); Ah[lk + 0][lr] = h; Al[lk + 0][lr] = l;
            split_tf32(pa.y, h, l); Ah[lk + 1][lr] = h; Al[lk + 1][lr] = l;
            split_tf32(pa.z, h, l); Ah[lk + 2][lr] = h; Al[lk + 2][lr] = l;
            split_tf32(pa.w, h, l); Ah[lk + 3][lr] = h; Al[lk + 3][lr] = l;
            split_tf32(pb.x, h, l); Bh[lk + 0][lr] = h; Bl[lk + 0][lr] = l;
            split_tf32(pb.y, h, l); Bh[lk + 1][lr] = h; Bl[lk + 1][lr] = l;
            split_tf32(pb.z, h, l); Bh[lk + 2][lr] = h; Bl[lk + 2][lr] = l;
            split_tf32(pb.w, h, l); Bh[lk + 3][lr] = h; Bl[lk + 3][lr] = l;
        }
        __syncthreads();
        if (it + 1 < NIT) {
            int kn = kbeg + (it + 1) * 16;
            pa = *(const float4*)&A[(size_t)(m0 + lr) * K + kn + lk];
            pb = *(const float4*)&Bp[(size_t)(n0 + lr) * K + kn + lk];
        }
#pragma unroll
        for (int k8 = 0; k8 < 2; k8++) {
            int kr = k8 * 8;
            unsigned afh[2][4], afl[2][4], bfh[2][2], bfl[2][2];
#pragma unroll
            for (int mi = 0; mi < 2; mi++) {
                int mb = wm + mi * 16 + grp;
                afh[mi][0] = Ah[kr + tig][mb];
                afh[mi][1] = Ah[kr + tig][mb + 8];
                afh[mi][2] = Ah[kr + tig + 4][mb];
                afh[mi][3] = Ah[kr + tig + 4][mb + 8];
                afl[mi][0] = Al[kr + tig][mb];
                afl[mi][1] = Al[kr + tig][mb + 8];
                afl[mi][2] = Al[kr + tig + 4][mb];
                afl[mi][3] = Al[kr + tig + 4][mb + 8];
            }
#pragma unroll
            for (int ni = 0; ni < 2; ni++) {
                int nb = wn + ni * 8 + grp;
                bfh[ni][0] = Bh[kr + tig][nb];
                bfh[ni][1] = Bh[kr + tig + 4][nb];
                bfl[ni][0] = Bl[kr + tig][nb];
                bfl[ni][1] = Bl[kr + tig + 4][nb];
            }
#pragma unroll
            for (int mi = 0; mi < 2; mi++)
#pragma unroll
                for (int ni = 0; ni < 2; ni++) {
                    mma_tf32(acc[mi][ni], afl[mi], bfh[ni]);
                    mma_tf32(acc[mi][ni], afh[mi], bfl[ni]);
                    mma_tf32(acc[mi][ni], afh[mi], bfh[ni]);
                }
        }
        __syncthreads();
    }

    float* out = g_part + (size_t)kz * (BS_ * 192);
#pragma unroll
    for (int mi = 0; mi < 2; mi++) {
#pragma unroll
        for (int ni = 0; ni < 2; ni++) {
            int col = n0 + wn + ni * 8 + 2 * tig;
            int row0 = m0 + wm + mi * 16 + grp;
            float2 v0 = make_float2(acc[mi][ni][0], acc[mi][ni][1]);
            float2 v1 = make_float2(acc[mi][ni][2], acc[mi][ni][3]);
            *(float2*)&out[(size_t)row0 * 192 + col] = v0;
            *(float2*)&out[(size_t)(row0 + 8) * 192 + col] = v1;
        }
    }
}

__global__ void __launch_bounds__(256) reduce_kernel(const float* __restrict__ bi) {
    int idx = blockIdx.x * 256 + threadIdx.x;
    if (idx >= BS_ * 192) return;
    int n = idx % 192;
    float s = bi[n];
#pragma unroll
    for (int z = 0; z < SPLITK; z++) s += g_part[(size_t)z * (BS_ * 192) + idx];
    g_ig[idx] = s;
}

// ---------------- GRU scan (latency-hidden; 86us measured) ----------------
__global__ void __launch_bounds__(192) gru_kernel(const float* __restrict__ h0,
                                                  const float* __restrict__ Wh,
                                                  const float* __restrict__ bn,
                                                  float* __restrict__ hfinal) {
    int b = blockIdx.x, g = threadIdx.x;
    __shared__ float h[64];
    __shared__ float hg[192];
    __shared__ float sig[192];
    float w[64];
#pragma unroll
    for (int k = 0; k < 64; k++) w[k] = Wh[g * 64 + k];
    float bnv = (g < 64) ? bn[g] : 0.f;
    if (g < 64) h[g] = h0[b * 64 + g];
    float igv = g_ig[(b * 128 + 0) * 192 + g];
    __syncthreads();
    for (int t = 0; t < 128; t++) {
        float a0 = 0.f, a1 = 0.f, a2 = 0.f, a3 = 0.f;
#pragma unroll
        for (int k = 0; k < 64; k += 4) {
            a0 += w[k] * h[k];
            a1 += w[k + 1] * h[k + 1];
            a2 += w[k + 2] * h[k + 2];
            a3 += w[k + 3] * h[k + 3];
        }
        hg[g] = (a0 + a1) + (a2 + a3);
        sig[g] = igv;
        __syncthreads();
        int tn = (t < 127) ? t + 1 : 127;
        igv = g_ig[(b * 128 + tn) * 192 + g];
        if (g < 64) {
            float rr = 1.f / (1.f + __expf(-(sig[g] + hg[g])));
            float zz = 1.f / (1.f + __expf(-(sig[64 + g] + hg[64 + g])));
            float nn = tanhf(sig[128 + g] + rr * (hg[128 + g] + bnv));
            float hn = (1.f - zz) * nn + zz * h[g];
            h[g] = hn;
            g_allh[(b * 128 + t) * 64 + g] = hn;
        }
        __syncthreads();
    }
    if (g < 64) hfinal[b * 64 + g] = h[g];
}

// ---------------- heads ----------------
#define HEADS_SMEM_BYTES (14816 * 4)
__global__ void __launch_bounds__(128) heads_kernel(
    const float* __restrict__ Wa1, const float* __restrict__ ba1,
    const float* __restrict__ Wa2, const float* __restrict__ ba2,
    const float* __restrict__ Wc1, const float* __restrict__ bc1,
    const float* __restrict__ Wc2, const float* __restrict__ bc2,
    float* __restrict__ logits, float* __restrict__ values) {
    extern __shared__ float s[];
    float* sWa1 = s;
    float* sWc1 = s + 4096;
    float* sWa2 = s + 8192;
    float* sWc2 = s + 14336;
    float* sba1 = s + 14400;
    float* sbc1 = s + 14464;
    float* sba2 = s + 14528;
    float* sh   = s + 14624;
    float* sa   = s + 14688;
    float* sc   = s + 14752;
    int tid = threadIdx.x;
    for (int i = tid; i < 4096; i += 128) { sWa1[i] = Wa1[i]; sWc1[i] = Wc1[i]; }
    for (int i = tid; i < 6144; i += 128) sWa2[i] = Wa2[i];
    if (tid < 64) { sWc2[tid] = Wc2[tid]; sba1[tid] = ba1[tid]; sbc1[tid] = bc1[tid]; }
    if (tid < 96) sba2[tid] = ba2[tid];
    float bc2v = bc2[0];
    __syncthreads();
    for (int r = blockIdx.x * 32; r < blockIdx.x * 32 + 32; r++) {
        if (tid < 64) sh[tid] = g_allh[r * 64 + tid];
        __syncthreads();
        {
            int j = tid & 63;
            const float* W = (tid < 64) ? sWa1 : sWc1;
            float acc = 0.f;
#pragma unroll
            for (int i = 0; i < 64; i++) acc += sh[i] * W[i * 64 + j];
            float v = tanhf(acc + ((tid < 64) ? sba1[j] : sbc1[j]));
            if (tid < 64) sa[j] = v; else sc[j] = v;
        }
        __syncthreads();
        if (tid < 96) {
            float acc = sba2[tid];
#pragma unroll
            for (int j = 0; j < 64; j++) acc += sa[j] * sWa2[j * 96 + tid];
            logits[r * 96 + tid] = acc;
        } else if (tid == 96) {
            float acc = bc2v;
#pragma unroll
            for (int j = 0; j < 64; j++) acc += sc[j] * sWc2[j];
            values[r] = acc;
        }
        __syncthreads();
    }
}

// ---------------- launch ----------------
extern "C" void kernel_launch(void* const* d_in, const int* in_sizes, int n_in,
                              void* d_out, int out_size) {
    const int*   positions = (const int*)d_in[0];
    const void*  umask     = d_in[1];
    const int*   tile      = (const int*)d_in[2];
    const int*   rpos      = (const int*)d_in[3];
    const void*  rmask     = d_in[4];
    const float* reward    = (const float*)d_in[5];
    const float* hidden    = (const float*)d_in[6];
    const float* emb_tile  = (const float*)d_in[7];
    const float* emb_unit  = (const float*)d_in[8];
    const float* w1 = (const float*)d_in[9];
    const float* b1 = (const float*)d_in[10];
    const float* w2 = (const float*)d_in[11];
    const float* b2 = (const float*)d_in[12];
    const float* w3 = (const float*)d_in[13];
    const float* b3 = (const float*)d_in[14];
    const float* Wi = (const float*)d_in[15];
    const float* Wh = (const float*)d_in[16];
    const float* bi = (const float*)d_in[17];
    const float* bn = (const float*)d_in[18];
    const float* Wa1 = (const float*)d_in[19];
    const float* ba1 = (const float*)d_in[20];
    const float* Wa2 = (const float*)d_in[21];
    const float* ba2 = (const float*)d_in[22];
    const float* Wc1 = (const float*)d_in[23];
    const float* bc1 = (const float*)d_in[24];
    const float* Wc2 = (const float*)d_in[25];
    const float* bc2 = (const float*)d_in[26];
    float* out = (float*)d_out;

    float* out_logits = out;
    float* out_values = out + 393216;
    float* out_hidden = out + 397312;

    const int conv_smem = CONV_SMEM_FLOATS * (int)sizeof(float);
    cudaFuncSetAttribute(conv_kernel, cudaFuncAttributeMaxDynamicSharedMemorySize, conv_smem);
    cudaFuncSetAttribute(heads_kernel, cudaFuncAttributeMaxDynamicSharedMemorySize, HEADS_SMEM_BYTES);

    conv_kernel<<<BS_, 256, conv_smem>>>(positions, umask, tile, rpos, rmask, reward,
                                         emb_tile, emb_unit, w1, b1, w2, b2, w3, b3);
    gemm_tf32_kernel<<<dim3(64, 3, SPLITK), 256>>>(Wi);
    reduce_kernel<<<(BS_ * 192 + 255) / 256, 256>>>(bi);
    gru_kernel<<<32, 192>>>(hidden, Wh, bn, out_hidden);
    heads_kernel<<<128, 128, HEADS_SMEM_BYTES>>>(Wa1, ba1, Wa2, ba2, Wc1, bc1, Wc2, bc2,
                                                 out_logits, out_values);
}

// round 7
// speedup vs baseline: 1.2783x; 1.1628x over previous
#include <cuda_runtime.h>
#include <math.h>

#define B_ 32
#define S_ 128
#define BS_ 4096
#define FEAT_D_ 28224
#define SPLITK 4
#define KSPLIT_LEN (FEAT_D_ / SPLITK)   // 7056

// ---------------- scratch ----------------
__device__ float g_feat[(size_t)BS_ * FEAT_D_];
__device__ float g_ig[BS_ * 192];
__device__ float g_part[(size_t)SPLITK * BS_ * 192];
__device__ float g_allh[BS_ * 64];

// ---------------- bool-mask dtype detection ----------------
__device__ __forceinline__ int detect_bool_mode(const unsigned char* p) {
    bool any80 = false, nz = false;
    for (int i = 0; i < 256; i++) {
        unsigned char v = p[i];
        int m = i & 3;
        if (m == 2 && v == 0x80) any80 = true;
        if (m != 0 && v != 0) nz = true;
    }
    if (!nz) return 1;
    if (any80) return 2;
    return 0;
}
__device__ __forceinline__ bool get_mask(const void* p, int i, int mode) {
    if (mode == 1) return ((const int*)p)[i] != 0;
    if (mode == 2) return ((const float*)p)[i] != 0.0f;
    return ((const unsigned char*)p)[i] != 0;
}

// ---------------- conv building block: 4 pixels/thread ----------------
template<int Cin, int Cout, int Win, bool GLOBAL>
__device__ __forceinline__ void conv2x2q(const float* __restrict__ si,
                                         float* __restrict__ so,
                                         float* __restrict__ go,
                                         const float* __restrict__ wsm,
                                         const float* __restrict__ bsm) {
    constexpr int Wout = Win - 1;
    constexpr int Npix = Wout * Wout;
    constexpr int HWin = Win * Win;
    constexpr int NQUAD = (Npix + 3) / 4;
    constexpr int NG = Cout / 16;
    constexpr int ITEMS = NQUAD * NG;
    constexpr int WSTEP = Cout / 4;

    for (int it = threadIdx.x; it < ITEMS; it += 256) {
        int pr = it % NQUAD, cg = it / NQUAD;
        int p[4], base[4];
        bool val[4];
#pragma unroll
        for (int j = 0; j < 4; j++) {
            p[j] = pr + j * NQUAD;
            val[j] = (p[j] < Npix);
            int pc = val[j] ? p[j] : 0;
            int y = pc / Wout, x = pc - y * Wout;
            base[j] = y * Win + x;
        }
        float acc[4][16];
#pragma unroll
        for (int j = 0; j < 4; j++)
#pragma unroll
            for (int q = 0; q < 16; q++) acc[j][q] = 0.f;
#pragma unroll
        for (int d = 0; d < 4; d++) {
            int dy = d >> 1, dx = d & 1;
            int off = dy * Win + dx;
            const float4* wq = (const float4*)(wsm + (d * Cin) * Cout) + cg * 4;
#pragma unroll 8
            for (int ci = 0; ci < Cin; ci++) {
                float v0 = si[base[0] + off + ci * HWin];
                float v1 = si[base[1] + off + ci * HWin];
                float v2 = si[base[2] + off + ci * HWin];
                float v3 = si[base[3] + off + ci * HWin];
                float4 wv[4];
                wv[0] = wq[ci * WSTEP + 0];
                wv[1] = wq[ci * WSTEP + 1];
                wv[2] = wq[ci * WSTEP + 2];
                wv[3] = wq[ci * WSTEP + 3];
#pragma unroll
                for (int q = 0; q < 4; q++) {
                    acc[0][q * 4 + 0] += v0 * wv[q].x;
                    acc[0][q * 4 + 1] += v0 * wv[q].y;
                    acc[0][q * 4 + 2] += v0 * wv[q].z;
                    acc[0][q * 4 + 3] += v0 * wv[q].w;
                    acc[1][q * 4 + 0] += v1 * wv[q].x;
                    acc[1][q * 4 + 1] += v1 * wv[q].y;
                    acc[1][q * 4 + 2] += v1 * wv[q].z;
                    acc[1][q * 4 + 3] += v1 * wv[q].w;
                    acc[2][q * 4 + 0] += v2 * wv[q].x;
                    acc[2][q * 4 + 1] += v2 * wv[q].y;
                    acc[2][q * 4 + 2] += v2 * wv[q].z;
                    acc[2][q * 4 + 3] += v2 * wv[q].w;
                    acc[3][q * 4 + 0] += v3 * wv[q].x;
                    acc[3][q * 4 + 1] += v3 * wv[q].y;
                    acc[3][q * 4 + 2] += v3 * wv[q].z;
                    acc[3][q * 4 + 3] += v3 * wv[q].w;
                }
            }
        }
        if constexpr (GLOBAL) {
#pragma unroll
            for (int j = 0; j < 4; j++) {
                if (!val[j]) continue;
                float4* gq = (float4*)(go + p[j] * Cout + cg * 16);
#pragma unroll
                for (int q = 0; q < 4; q++) {
                    float4 v;
                    v.x = fmaxf(acc[j][q * 4 + 0] + bsm[cg * 16 + q * 4 + 0], 0.f);
                    v.y = fmaxf(acc[j][q * 4 + 1] + bsm[cg * 16 + q * 4 + 1], 0.f);
                    v.z = fmaxf(acc[j][q * 4 + 2] + bsm[cg * 16 + q * 4 + 2], 0.f);
                    v.w = fmaxf(acc[j][q * 4 + 3] + bsm[cg * 16 + q * 4 + 3], 0.f);
                    gq[q] = v;
                }
            }
        } else {
#pragma unroll
            for (int j = 0; j < 4; j++) {
                if (!val[j]) continue;
#pragma unroll
                for (int q = 0; q < 16; q++) {
                    float bj = bsm[cg * 16 + q];
                    so[(cg * 16 + q) * Npix + p[j]] = fmaxf(acc[j][q] + bj, 0.f);
                }
            }
        }
    }
}

// smem (floats): bufA 15488 | bufB 8464 | wb1 1536 | wb2 2048 | sb 112 = 27648
// wb3 overlays bufB after conv2. 110.6 KB -> 2 CTAs/SM.
#define CONV_SMEM_FLOATS 27648

__global__ void __launch_bounds__(256, 2) conv_kernel(
    const int* __restrict__ positions, const void* __restrict__ umask,
    const int* __restrict__ tile_type, const int* __restrict__ rpos,
    const void* __restrict__ rmask, const float* __restrict__ reward,
    const float* __restrict__ emb_tile, const float* __restrict__ emb_unit,
    const float* __restrict__ w1, const float* __restrict__ b1,
    const float* __restrict__ w2, const float* __restrict__ b2,
    const float* __restrict__ w3, const float* __restrict__ b3) {
    extern __shared__ float sm[];
    float* bufA = sm;          // 15488
    float* bufB = sm + 15488;  // 8464 (reused for wb3 in stage 3)
    float* wb1 = sm + 23952;   // 1536
    float* wb2 = sm + 25488;   // 2048
    float* sb  = sm + 27536;   // 112 biases
    float* wb3 = bufB;         // overlay
    int tid = threadIdx.x, bs = blockIdx.x;

    for (int i = tid; i < 1536; i += 256) wb1[i] = w1[i];
    for (int i = tid; i < 2048; i += 256) wb2[i] = w2[i];
    if (tid < 16) sb[tid] = b1[tid];
    else if (tid < 48) sb[tid] = b2[tid - 16];
    else if (tid < 112) sb[tid] = b3[tid - 48];

    for (int i = tid; i < 19 * 576; i += 256) bufA[4 * 576 + i] = 0.f;
    float rw = reward[bs];
    for (int p = tid; p < 576; p += 256) {
        int tt = tile_type[bs * 576 + p] * 4;
        bufA[p] = emb_tile[tt];
        bufA[576 + p] = emb_tile[tt + 1];
        bufA[1152 + p] = emb_tile[tt + 2];
        bufA[1728 + p] = emb_tile[tt + 3];
        bufA[23 * 576 + p] = rw;
    }
    __syncthreads();
    if (tid < 32) {
        int mode = detect_bool_mode((const unsigned char*)umask);
        if (get_mask(umask, bs * 32 + tid, mode)) {
            int t = tid >> 4, u = tid & 15;
            int pb = (bs * 32 + tid) * 2;
            int y = positions[pb], x = positions[pb + 1];
            int cell = y * 24 + x;
            atomicAdd(&bufA[(4 + t) * 576 + cell], 0.0625f);
#pragma unroll
            for (int e = 0; e < 8; e++)
                atomicAdd(&bufA[(6 + t * 8 + e) * 576 + cell], emb_unit[u * 8 + e]);
        }
    } else if (tid < 38) {
        int r = tid - 32;
        int mode = detect_bool_mode((const unsigned char*)rmask);
        if (get_mask(rmask, bs * 6 + r, mode)) {
            int pb = (bs * 6 + r) * 2;
            int y = rpos[pb], x = rpos[pb + 1];
            atomicAdd(&bufA[22 * 576 + y * 24 + x], 1.0f);
        }
    }
    __syncthreads();
    conv2x2q<24, 16, 24, false>(bufA, bufB, nullptr, wb1, sb);
    __syncthreads();
    conv2x2q<16, 32, 23, false>(bufB, bufA, nullptr, wb2, sb + 16);
    __syncthreads();                 // conv2 done reading bufB
    for (int i = tid; i < 8192; i += 256) wb3[i] = w3[i];   // overlay wb3
    __syncthreads();
    conv2x2q<32, 64, 22, true>(bufA, nullptr, g_feat + (size_t)bs * FEAT_D_, wb3, sb + 48);
}

// ---------------- 3-term split-bf16 tensor-core GEMM (m16n8k16) ----------------
__device__ __forceinline__ unsigned pack_bf16x2(float e, float o) {
    unsigned r;
    asm("cvt.rn.bf16x2.f32 %0, %1, %2;" : "=r"(r) : "f"(o), "f"(e));  // hi=o, lo=e
    return r;
}
__device__ __forceinline__ void split_bf(float e, float o, unsigned& h, unsigned& l) {
    h = pack_bf16x2(e, o);
    float he = __uint_as_float(h << 16);
    float ho = __uint_as_float(h & 0xffff0000u);
    l = pack_bf16x2(e - he, o - ho);
}
__device__ __forceinline__ void mma_bf16(float* acc, const unsigned* a, const unsigned* b) {
    asm volatile(
        "mma.sync.aligned.m16n8k16.row.col.f32.bf16.bf16.f32 "
        "{%0,%1,%2,%3}, {%4,%5,%6,%7}, {%8,%9}, {%0,%1,%2,%3};"
        : "+f"(acc[0]), "+f"(acc[1]), "+f"(acc[2]), "+f"(acc[3])
        : "r"(a[0]), "r"(a[1]), "r"(a[2]), "r"(a[3]), "r"(b[0]), "r"(b[1]));
}

#define SPAD 76   // 32-bank-clean for both stores (k2*76 mod 32 ∈ {0,24,16,8}) and frag loads

__global__ void __launch_bounds__(256) gemm_bf16_kernel(const float* __restrict__ Bmat) {
    __shared__ unsigned Ah[8][SPAD];
    __shared__ unsigned Al[8][SPAD];
    __shared__ unsigned Bh[8][SPAD];
    __shared__ unsigned Bl[8][SPAD];
    const int K = FEAT_D_;
    int tid = threadIdx.x;
    int m0 = blockIdx.x * 64, n0 = blockIdx.y * 64;
    int kz = blockIdx.z;
    int kbeg = kz * KSPLIT_LEN;

    int warp = tid >> 5, lane = tid & 31;
    int wm = (warp & 1) * 32;
    int wn = (warp >> 1) * 16;
    int grp = lane >> 2, tig = lane & 3;

    int lr = tid >> 2;            // 0..63 row
    int lkq = (tid & 3) * 4;      // k offset 0,4,8,12
    int k2 = lkq >> 1;            // packed-k index 0,2,4,6

    const float* A = g_feat;
    const float* Bp = Bmat;

    float4 pa = *(const float4*)&A[(size_t)(m0 + lr) * K + kbeg + lkq];
    float4 pb = *(const float4*)&Bp[(size_t)(n0 + lr) * K + kbeg + lkq];

    float acc[2][2][4];
#pragma unroll
    for (int i = 0; i < 2; i++)
#pragma unroll
        for (int j = 0; j < 2; j++)
#pragma unroll
            for (int q = 0; q < 4; q++) acc[i][j][q] = 0.f;

    const int NIT = KSPLIT_LEN / 16;  // 441
    for (int it = 0; it < NIT; it++) {
        {
            unsigned h, l;
            split_bf(pa.x, pa.y, h, l); Ah[k2 + 0][lr] = h; Al[k2 + 0][lr] = l;
            split_bf(pa.z, pa.w, h, l); Ah[k2 + 1][lr] = h; Al[k2 + 1][lr] = l;
            split_bf(pb.x, pb.y, h, l); Bh[k2 + 0][lr] = h; Bl[k2 + 0][lr] = l;
            split_bf(pb.z, pb.w, h, l); Bh[k2 + 1][lr] = h; Bl[k2 + 1][lr] = l;
        }
        __syncthreads();
        if (it + 1 < NIT) {
            int kn = kbeg + (it + 1) * 16;
            pa = *(const float4*)&A[(size_t)(m0 + lr) * K + kn + lkq];
            pb = *(const float4*)&Bp[(size_t)(n0 + lr) * K + kn + lkq];
        }
        {
            unsigned afh[2][4], afl[2][4], bfh[2][2], bfl[2][2];
#pragma unroll
            for (int mi = 0; mi < 2; mi++) {
                int mb = wm + mi * 16 + grp;
                afh[mi][0] = Ah[tig][mb];
                afh[mi][1] = Ah[tig][mb + 8];
                afh[mi][2] = Ah[tig + 4][mb];
                afh[mi][3] = Ah[tig + 4][mb + 8];
                afl[mi][0] = Al[tig][mb];
                afl[mi][1] = Al[tig][mb + 8];
                afl[mi][2] = Al[tig + 4][mb];
                afl[mi][3] = Al[tig + 4][mb + 8];
            }
#pragma unroll
            for (int ni = 0; ni < 2; ni++) {
                int nb = wn + ni * 8 + grp;
                bfh[ni][0] = Bh[tig][nb];
                bfh[ni][1] = Bh[tig + 4][nb];
                bfl[ni][0] = Bl[tig][nb];
                bfl[ni][1] = Bl[tig + 4][nb];
            }
#pragma unroll
            for (int mi = 0; mi < 2; mi++)
#pragma unroll
                for (int ni = 0; ni < 2; ni++) {
                    mma_bf16(acc[mi][ni], afl[mi], bfh[ni]);
                    mma_bf16(acc[mi][ni], afh[mi], bfl[ni]);
                    mma_bf16(acc[mi][ni], afh[mi], bfh[ni]);
                }
        }
        __syncthreads();
    }

    float* out = g_part + (size_t)kz * (BS_ * 192);
#pragma unroll
    for (int mi = 0; mi < 2; mi++) {
#pragma unroll
        for (int ni = 0; ni < 2; ni++) {
            int col = n0 + wn + ni * 8 + 2 * tig;
            int row0 = m0 + wm + mi * 16 + grp;
            float2 v0 = make_float2(acc[mi][ni][0], acc[mi][ni][1]);
            float2 v1 = make_float2(acc[mi][ni][2], acc[mi][ni][3]);
            *(float2*)&out[(size_t)row0 * 192 + col] = v0;
            *(float2*)&out[(size_t)(row0 + 8) * 192 + col] = v1;
        }
    }
}

__global__ void __launch_bounds__(256) reduce_kernel(const float* __restrict__ bi) {
    int idx = blockIdx.x * 256 + threadIdx.x;
    if (idx >= BS_ * 192) return;
    int n = idx % 192;
    float s = bi[n];
#pragma unroll
    for (int z = 0; z < SPLITK; z++) s += g_part[(size_t)z * (BS_ * 192) + idx];
    g_ig[idx] = s;
}

// ---------------- GRU scan (latency-hidden; 85us measured) ----------------
__global__ void __launch_bounds__(192) gru_kernel(const float* __restrict__ h0,
                                                  const float* __restrict__ Wh,
                                                  const float* __restrict__ bn,
                                                  float* __restrict__ hfinal) {
    int b = blockIdx.x, g = threadIdx.x;
    __shared__ float h[64];
    __shared__ float hg[192];
    __shared__ float sig[192];
    float w[64];
#pragma unroll
    for (int k = 0; k < 64; k++) w[k] = Wh[g * 64 + k];
    float bnv = (g < 64) ? bn[g] : 0.f;
    if (g < 64) h[g] = h0[b * 64 + g];
    float igv = g_ig[(b * 128 + 0) * 192 + g];
    __syncthreads();
    for (int t = 0; t < 128; t++) {
        float a0 = 0.f, a1 = 0.f, a2 = 0.f, a3 = 0.f;
#pragma unroll
        for (int k = 0; k < 64; k += 4) {
            a0 += w[k] * h[k];
            a1 += w[k + 1] * h[k + 1];
            a2 += w[k + 2] * h[k + 2];
            a3 += w[k + 3] * h[k + 3];
        }
        hg[g] = (a0 + a1) + (a2 + a3);
        sig[g] = igv;
        __syncthreads();
        int tn = (t < 127) ? t + 1 : 127;
        igv = g_ig[(b * 128 + tn) * 192 + g];
        if (g < 64) {
            float rr = 1.f / (1.f + __expf(-(sig[g] + hg[g])));
            float zz = 1.f / (1.f + __expf(-(sig[64 + g] + hg[64 + g])));
            float nn = tanhf(sig[128 + g] + rr * (hg[128 + g] + bnv));
            float hn = (1.f - zz) * nn + zz * h[g];
            h[g] = hn;
            g_allh[(b * 128 + t) * 64 + g] = hn;
        }
        __syncthreads();
    }
    if (g < 64) hfinal[b * 64 + g] = h[g];
}

// ---------------- heads ----------------
#define HEADS_SMEM_BYTES (14816 * 4)
__global__ void __launch_bounds__(128) heads_kernel(
    const float* __restrict__ Wa1, const float* __restrict__ ba1,
    const float* __restrict__ Wa2, const float* __restrict__ ba2,
    const float* __restrict__ Wc1, const float* __restrict__ bc1,
    const float* __restrict__ Wc2, const float* __restrict__ bc2,
    float* __restrict__ logits, float* __restrict__ values) {
    extern __shared__ float s[];
    float* sWa1 = s;
    float* sWc1 = s + 4096;
    float* sWa2 = s + 8192;
    float* sWc2 = s + 14336;
    float* sba1 = s + 14400;
    float* sbc1 = s + 14464;
    float* sba2 = s + 14528;
    float* sh   = s + 14624;
    float* sa   = s + 14688;
    float* sc   = s + 14752;
    int tid = threadIdx.x;
    for (int i = tid; i < 4096; i += 128) { sWa1[i] = Wa1[i]; sWc1[i] = Wc1[i]; }
    for (int i = tid; i < 6144; i += 128) sWa2[i] = Wa2[i];
    if (tid < 64) { sWc2[tid] = Wc2[tid]; sba1[tid] = ba1[tid]; sbc1[tid] = bc1[tid]; }
    if (tid < 96) sba2[tid] = ba2[tid];
    float bc2v = bc2[0];
    __syncthreads();
    for (int r = blockIdx.x * 32; r < blockIdx.x * 32 + 32; r++) {
        if (tid < 64) sh[tid] = g_allh[r * 64 + tid];
        __syncthreads();
        {
            int j = tid & 63;
            const float* W = (tid < 64) ? sWa1 : sWc1;
            float acc = 0.f;
#pragma unroll
            for (int i = 0; i < 64; i++) acc += sh[i] * W[i * 64 + j];
            float v = tanhf(acc + ((tid < 64) ? sba1[j] : sbc1[j]));
            if (tid < 64) sa[j] = v; else sc[j] = v;
        }
        __syncthreads();
        if (tid < 96) {
            float acc = sba2[tid];
#pragma unroll
            for (int j = 0; j < 64; j++) acc += sa[j] * sWa2[j * 96 + tid];
            logits[r * 96 + tid] = acc;
        } else if (tid == 96) {
            float acc = bc2v;
#pragma unroll
            for (int j = 0; j < 64; j++) acc += sc[j] * sWc2[j];
            values[r] = acc;
        }
        __syncthreads();
    }
}

// ---------------- launch ----------------
extern "C" void kernel_launch(void* const* d_in, const int* in_sizes, int n_in,
                              void* d_out, int out_size) {
    const int*   positions = (const int*)d_in[0];
    const void*  umask     = d_in[1];
    const int*   tile      = (const int*)d_in[2];
    const int*   rpos      = (const int*)d_in[3];
    const void*  rmask     = d_in[4];
    const float* reward    = (const float*)d_in[5];
    const float* hidden    = (const float*)d_in[6];
    const float* emb_tile  = (const float*)d_in[7];
    const float* emb_unit  = (const float*)d_in[8];
    const float* w1 = (const float*)d_in[9];
    const float* b1 = (const float*)d_in[10];
    const float* w2 = (const float*)d_in[11];
    const float* b2 = (const float*)d_in[12];
    const float* w3 = (const float*)d_in[13];
    const float* b3 = (const float*)d_in[14];
    const float* Wi = (const float*)d_in[15];
    const float* Wh = (const float*)d_in[16];
    const float* bi = (const float*)d_in[17];
    const float* bn = (const float*)d_in[18];
    const float* Wa1 = (const float*)d_in[19];
    const float* ba1 = (const float*)d_in[20];
    const float* Wa2 = (const float*)d_in[21];
    const float* ba2 = (const float*)d_in[22];
    const float* Wc1 = (const float*)d_in[23];
    const float* bc1 = (const float*)d_in[24];
    const float* Wc2 = (const float*)d_in[25];
    const float* bc2 = (const float*)d_in[26];
    float* out = (float*)d_out;

    float* out_logits = out;
    float* out_values = out + 393216;
    float* out_hidden = out + 397312;

    const int conv_smem = CONV_SMEM_FLOATS * (int)sizeof(float);
    cudaFuncSetAttribute(conv_kernel, cudaFuncAttributeMaxDynamicSharedMemorySize, conv_smem);
    cudaFuncSetAttribute(heads_kernel, cudaFuncAttributeMaxDynamicSharedMemorySize, HEADS_SMEM_BYTES);

    conv_kernel<<<BS_, 256, conv_smem>>>(positions, umask, tile, rpos, rmask, reward,
                                         emb_tile, emb_unit, w1, b1, w2, b2, w3, b3);
    gemm_bf16_kernel<<<dim3(64, 3, SPLITK), 256>>>(Wi);
    reduce_kernel<<<(BS_ * 192 + 255) / 256, 256>>>(bi);
    gru_kernel<<<32, 192>>>(hidden, Wh, bn, out_hidden);
    heads_kernel<<<128, 128, HEADS_SMEM_BYTES>>>(Wa1, ba1, Wa2, ba2, Wc1, bc1, Wc2, bc2,
                                                 out_logits, out_values);
}

// round 8
// speedup vs baseline: 1.8622x; 1.4568x over previous
#include <cuda_runtime.h>
#include <math.h>

#define B_ 32
#define S_ 128
#define BS_ 4096
#define FEAT_D_ 28224
#define SPLITK 4
#define KSPLIT_LEN (FEAT_D_ / SPLITK)   // 7056

// ---------------- scratch ----------------
__device__ float g_feat[(size_t)BS_ * FEAT_D_];
__device__ float g_ig[BS_ * 192];
__device__ float g_part[(size_t)SPLITK * BS_ * 192];
__device__ float g_allh[BS_ * 64];

// ---------------- bool-mask dtype detection ----------------
__device__ __forceinline__ int detect_bool_mode(const unsigned char* p) {
    bool any80 = false, nz = false;
    for (int i = 0; i < 256; i++) {
        unsigned char v = p[i];
        int m = i & 3;
        if (m == 2 && v == 0x80) any80 = true;
        if (m != 0 && v != 0) nz = true;
    }
    if (!nz) return 1;
    if (any80) return 2;
    return 0;
}
__device__ __forceinline__ bool get_mask(const void* p, int i, int mode) {
    if (mode == 1) return ((const int*)p)[i] != 0;
    if (mode == 2) return ((const float*)p)[i] != 0.0f;
    return ((const unsigned char*)p)[i] != 0;
}

// ---------------- bf16 split helpers ----------------
__device__ __forceinline__ unsigned pack_bf16x2(float e, float o) {
    unsigned r;
    asm("cvt.rn.bf16x2.f32 %0, %1, %2;" : "=r"(r) : "f"(o), "f"(e));  // lo=e, hi=o
    return r;
}
__device__ __forceinline__ void split_bf(float e, float o, unsigned& h, unsigned& l) {
    h = pack_bf16x2(e, o);
    float he = __uint_as_float(h << 16);
    float ho = __uint_as_float(h & 0xffff0000u);
    l = pack_bf16x2(e - he, o - ho);
}
__device__ __forceinline__ void mma_bf16(float* acc, const unsigned* a, const unsigned* b) {
    asm volatile(
        "mma.sync.aligned.m16n8k16.row.col.f32.bf16.bf16.f32 "
        "{%0,%1,%2,%3}, {%4,%5,%6,%7}, {%8,%9}, {%0,%1,%2,%3};"
        : "+f"(acc[0]), "+f"(acc[1]), "+f"(acc[2]), "+f"(acc[3])
        : "r"(a[0]), "r"(a[1]), "r"(a[2]), "r"(a[3]), "r"(b[0]), "r"(b[1]));
}

// ---------------- conv kernel smem layout (floats) ----------------
// U1: grid 24x576=13824 | wb1 1536 | spare  ==> overlaid by sA3h/l (2*16*488=15616)
// U2: sA2h/l 2*8*536=8576 | wB2h/l 2*32*40=2560   ==> overlaid by wB3h/l (2*64*72=9216)
// bias: 128
#define OFF_GRID 0
#define OFF_WB1  13824
#define OFF_A3H  0
#define OFF_A3L  7808
#define OFF_A2H  15616
#define OFF_A2L  19904
#define OFF_WB2H 24192
#define OFF_WB2L 25472
#define OFF_WB3H 15616
#define OFF_WB3L 20224
#define OFF_BIAS 26752
#define CONV_SMEM_FLOATS 26880   // 107520 B -> 2 CTAs/SM

__global__ void __launch_bounds__(256, 2) conv_kernel(
    const int* __restrict__ positions, const void* __restrict__ umask,
    const int* __restrict__ tile_type, const int* __restrict__ rpos,
    const void* __restrict__ rmask, const float* __restrict__ reward,
    const float* __restrict__ emb_tile, const float* __restrict__ emb_unit,
    const float* __restrict__ w1, const float* __restrict__ b1,
    const float* __restrict__ w2, const float* __restrict__ b2,
    const float* __restrict__ w3, const float* __restrict__ b3) {
    extern __shared__ float sm[];
    int tid = threadIdx.x, bs = blockIdx.x;
    float* grid = sm + OFF_GRID;
    float* wb1  = sm + OFF_WB1;
    float* sb   = sm + OFF_BIAS;   // b1[0:16) b2[16:48) b3[48:112)

    // ---- phase 0: weights/biases + grid build ----
    for (int i = tid; i < 1536; i += 256) wb1[i] = w1[i];
    {   // wB2 packed pairs over cin
        unsigned* wB2h = (unsigned*)(sm + OFF_WB2H);
        unsigned* wB2l = (unsigned*)(sm + OFF_WB2L);
        for (int i = tid; i < 32 * 32; i += 256) {
            int r = i >> 5, n = i & 31;
            int d = r >> 3, ci2 = r & 7;
            float e = w2[(d * 16 + 2 * ci2) * 32 + n];
            float o = w2[(d * 16 + 2 * ci2 + 1) * 32 + n];
            unsigned h, l; split_bf(e, o, h, l);
            wB2h[r * 40 + n] = h; wB2l[r * 40 + n] = l;
        }
    }
    if (tid < 16) sb[tid] = b1[tid];
    else if (tid < 48) sb[tid] = b2[tid - 16];
    else if (tid < 112) sb[tid] = b3[tid - 48];

    for (int i = tid; i < 19 * 576; i += 256) grid[4 * 576 + i] = 0.f;
    float rw = reward[bs];
    for (int p = tid; p < 576; p += 256) {
        int tt = tile_type[bs * 576 + p] * 4;
        grid[p] = emb_tile[tt];
        grid[576 + p] = emb_tile[tt + 1];
        grid[1152 + p] = emb_tile[tt + 2];
        grid[1728 + p] = emb_tile[tt + 3];
        grid[23 * 576 + p] = rw;
    }
    __syncthreads();
    if (tid < 32) {
        int mode = detect_bool_mode((const unsigned char*)umask);
        if (get_mask(umask, bs * 32 + tid, mode)) {
            int t = tid >> 4, u = tid & 15;
            int pb = (bs * 32 + tid) * 2;
            int y = positions[pb], x = positions[pb + 1];
            int cell = y * 24 + x;
            atomicAdd(&grid[(4 + t) * 576 + cell], 0.0625f);
#pragma unroll
            for (int e = 0; e < 8; e++)
                atomicAdd(&grid[(6 + t * 8 + e) * 576 + cell], emb_unit[u * 8 + e]);
        }
    } else if (tid < 38) {
        int r = tid - 32;
        int mode = detect_bool_mode((const unsigned char*)rmask);
        if (get_mask(rmask, bs * 6 + r, mode)) {
            int pb = (bs * 6 + r) * 2;
            int y = rpos[pb], x = rpos[pb + 1];
            atomicAdd(&grid[22 * 576 + y * 24 + x], 1.0f);
        }
    }
    __syncthreads();

    // ---- conv1: FFMA 24->16ch, 24x24 -> 23x23 (529). 4 pixels/thread, packed epilogue ----
    {
        unsigned* sA2h = (unsigned*)(sm + OFF_A2H);
        unsigned* sA2l = (unsigned*)(sm + OFF_A2L);
        if (tid < 133) {
            int p[4], base[4]; bool val[4];
#pragma unroll
            for (int j = 0; j < 4; j++) {
                p[j] = tid + j * 133;
                val[j] = (p[j] < 529);
                int pc = val[j] ? p[j] : 0;
                int y = pc / 23;
                base[j] = y * 24 + (pc - y * 23);
            }
            float acc[4][16];
#pragma unroll
            for (int j = 0; j < 4; j++)
#pragma unroll
                for (int q = 0; q < 16; q++) acc[j][q] = 0.f;
#pragma unroll
            for (int d = 0; d < 4; d++) {
                int off = (d >> 1) * 24 + (d & 1);
#pragma unroll 8
                for (int ci = 0; ci < 24; ci++) {
                    float v0 = grid[ci * 576 + base[0] + off];
                    float v1 = grid[ci * 576 + base[1] + off];
                    float v2 = grid[ci * 576 + base[2] + off];
                    float v3 = grid[ci * 576 + base[3] + off];
                    const float4* wq = (const float4*)(wb1 + (d * 24 + ci) * 16);
                    float4 wv[4] = {wq[0], wq[1], wq[2], wq[3]};
#pragma unroll
                    for (int q = 0; q < 4; q++) {
                        acc[0][q * 4 + 0] += v0 * wv[q].x; acc[0][q * 4 + 1] += v0 * wv[q].y;
                        acc[0][q * 4 + 2] += v0 * wv[q].z; acc[0][q * 4 + 3] += v0 * wv[q].w;
                        acc[1][q * 4 + 0] += v1 * wv[q].x; acc[1][q * 4 + 1] += v1 * wv[q].y;
                        acc[1][q * 4 + 2] += v1 * wv[q].z; acc[1][q * 4 + 3] += v1 * wv[q].w;
                        acc[2][q * 4 + 0] += v2 * wv[q].x; acc[2][q * 4 + 1] += v2 * wv[q].y;
                        acc[2][q * 4 + 2] += v2 * wv[q].z; acc[2][q * 4 + 3] += v2 * wv[q].w;
                        acc[3][q * 4 + 0] += v3 * wv[q].x; acc[3][q * 4 + 1] += v3 * wv[q].y;
                        acc[3][q * 4 + 2] += v3 * wv[q].z; acc[3][q * 4 + 3] += v3 * wv[q].w;
                    }
                }
            }
#pragma unroll
            for (int j = 0; j < 4; j++) {
                if (!val[j]) continue;
#pragma unroll
                for (int q2 = 0; q2 < 8; q2++) {
                    float e = fmaxf(acc[j][2 * q2] + sb[2 * q2], 0.f);
                    float o = fmaxf(acc[j][2 * q2 + 1] + sb[2 * q2 + 1], 0.f);
                    unsigned h, l; split_bf(e, o, h, l);
                    sA2h[q2 * 536 + p[j]] = h;
                    sA2l[q2 * 536 + p[j]] = l;
                }
            }
        }
    }
    __syncthreads();

    int wid = tid >> 5, lane = tid & 31;
    int grp = lane >> 2, tig = lane & 3;
    int wm = wid & 3, wn = wid >> 2;

    // ---- conv2: MMA 16->32ch, 23x23 -> 22x22 (484). M-tiles 31, N=32, K=64 ----
    {
        const unsigned* sA2h = (const unsigned*)(sm + OFF_A2H);
        const unsigned* sA2l = (const unsigned*)(sm + OFF_A2L);
        const unsigned* wB2h = (const unsigned*)(sm + OFF_WB2H);
        const unsigned* wB2l = (const unsigned*)(sm + OFF_WB2L);
        float acc2[8][2][4];
#pragma unroll
        for (int mt = 0; mt < 8; mt++)
#pragma unroll
            for (int ni = 0; ni < 2; ni++)
#pragma unroll
                for (int q = 0; q < 4; q++) acc2[mt][ni][q] = 0.f;
        int i0[8], i1[8];
#pragma unroll
        for (int mt = 0; mt < 8; mt++) {
            int tile = wm + mt * 4;
            int p0 = tile * 16 + grp, p1 = p0 + 8;
            int q0 = (p0 < 484) ? p0 : 0; i0[mt] = q0 + q0 / 22;
            int q1 = (p1 < 484) ? p1 : 0; i1[mt] = q1 + q1 / 22;
        }
#pragma unroll 1
        for (int d = 0; d < 4; d++) {
            int off = (d >> 1) * 23 + (d & 1);
            unsigned bh[2][2], bl[2][2];
#pragma unroll
            for (int ni = 0; ni < 2; ni++) {
                int nb = wn * 16 + ni * 8 + grp;
                bh[ni][0] = wB2h[(d * 8 + tig) * 40 + nb];
                bh[ni][1] = wB2h[(d * 8 + tig + 4) * 40 + nb];
                bl[ni][0] = wB2l[(d * 8 + tig) * 40 + nb];
                bl[ni][1] = wB2l[(d * 8 + tig + 4) * 40 + nb];
            }
#pragma unroll
            for (int mt = 0; mt < 8; mt++) {
                if (wm + mt * 4 < 31) {
                    int a0 = tig * 536 + i0[mt] + off;
                    int a1 = tig * 536 + i1[mt] + off;
                    unsigned ah[4], al[4];
                    ah[0] = sA2h[a0]; ah[1] = sA2h[a1];
                    ah[2] = sA2h[a0 + 4 * 536]; ah[3] = sA2h[a1 + 4 * 536];
                    al[0] = sA2l[a0]; al[1] = sA2l[a1];
                    al[2] = sA2l[a0 + 4 * 536]; al[3] = sA2l[a1 + 4 * 536];
#pragma unroll
                    for (int ni = 0; ni < 2; ni++) {
                        mma_bf16(acc2[mt][ni], al, bh[ni]);
                        mma_bf16(acc2[mt][ni], ah, bl[ni]);
                        mma_bf16(acc2[mt][ni], ah, bh[ni]);
                    }
                }
            }
        }
        // epilogue: relu+bias, pack pairs -> sA3 (overlays grid/wb1; both dead)
        unsigned* sA3h = (unsigned*)(sm + OFF_A3H);
        unsigned* sA3l = (unsigned*)(sm + OFF_A3L);
        const float* b2s = sb + 16;
#pragma unroll
        for (int mt = 0; mt < 8; mt++) {
            int tile = wm + mt * 4;
            if (tile < 31) {
                int p0 = tile * 16 + grp, p1 = p0 + 8;
#pragma unroll
                for (int ni = 0; ni < 2; ni++) {
                    int c0 = wn * 16 + ni * 8 + 2 * tig;
                    float be = b2s[c0], bo = b2s[c0 + 1];
                    int c2 = c0 >> 1;
                    if (p0 < 484) {
                        unsigned h, l;
                        split_bf(fmaxf(acc2[mt][ni][0] + be, 0.f),
                                 fmaxf(acc2[mt][ni][1] + bo, 0.f), h, l);
                        sA3h[c2 * 488 + p0] = h; sA3l[c2 * 488 + p0] = l;
                    }
                    if (p1 < 484) {
                        unsigned h, l;
                        split_bf(fmaxf(acc2[mt][ni][2] + be, 0.f),
                                 fmaxf(acc2[mt][ni][3] + bo, 0.f), h, l);
                        sA3h[c2 * 488 + p1] = h; sA3l[c2 * 488 + p1] = l;
                    }
                }
            }
        }
    }
    __syncthreads();

    // ---- load wB3 (overlays sA2/wB2 — dead) ----
    {
        unsigned* wB3h = (unsigned*)(sm + OFF_WB3H);
        unsigned* wB3l = (unsigned*)(sm + OFF_WB3L);
        for (int i = tid; i < 64 * 64; i += 256) {
            int r = i >> 6, n = i & 63;
            int d = r >> 4, ci2 = r & 15;
            float e = w3[(d * 32 + 2 * ci2) * 64 + n];
            float o = w3[(d * 32 + 2 * ci2 + 1) * 64 + n];
            unsigned h, l; split_bf(e, o, h, l);
            wB3h[r * 72 + n] = h; wB3l[r * 72 + n] = l;
        }
    }
    __syncthreads();

    // ---- conv3: MMA 32->64ch, 22x22 -> 21x21 (441). M-tiles 28, N=64, K=128, 2 n-passes ----
    {
        const unsigned* sA3h = (const unsigned*)(sm + OFF_A3H);
        const unsigned* sA3l = (const unsigned*)(sm + OFF_A3L);
        const unsigned* wB3h = (const unsigned*)(sm + OFF_WB3H);
        const unsigned* wB3l = (const unsigned*)(sm + OFF_WB3L);
        const float* b3s = sb + 48;
        float* go = g_feat + (size_t)bs * FEAT_D_;
        int i0[7], i1[7];
#pragma unroll
        for (int mt = 0; mt < 7; mt++) {
            int p0 = (wm + mt * 4) * 16 + grp, p1 = p0 + 8;
            int q0 = (p0 < 441) ? p0 : 0; i0[mt] = q0 + q0 / 21;
            int q1 = (p1 < 441) ? p1 : 0; i1[mt] = q1 + q1 / 21;
        }
#pragma unroll 1
        for (int pass = 0; pass < 2; pass++) {
            int n0 = wn * 32 + pass * 16;
            float acc3[7][2][4];
#pragma unroll
            for (int mt = 0; mt < 7; mt++)
#pragma unroll
                for (int ni = 0; ni < 2; ni++)
#pragma unroll
                    for (int q = 0; q < 4; q++) acc3[mt][ni][q] = 0.f;
#pragma unroll 1
            for (int dk = 0; dk < 8; dk++) {
                int d = dk >> 1, h8 = dk & 1;
                int off = (d >> 1) * 22 + (d & 1);
                int kb = h8 * 8;
                unsigned bh[2][2], bl[2][2];
#pragma unroll
                for (int ni = 0; ni < 2; ni++) {
                    int nb = n0 + ni * 8 + grp;
                    bh[ni][0] = wB3h[(d * 16 + kb + tig) * 72 + nb];
                    bh[ni][1] = wB3h[(d * 16 + kb + tig + 4) * 72 + nb];
                    bl[ni][0] = wB3l[(d * 16 + kb + tig) * 72 + nb];
                    bl[ni][1] = wB3l[(d * 16 + kb + tig + 4) * 72 + nb];
                }
#pragma unroll
                for (int mt = 0; mt < 7; mt++) {
                    int a0 = (kb + tig) * 488 + i0[mt] + off;
                    int a1 = (kb + tig) * 488 + i1[mt] + off;
                    unsigned ah[4], al[4];
                    ah[0] = sA3h[a0]; ah[1] = sA3h[a1];
                    ah[2] = sA3h[a0 + 4 * 488]; ah[3] = sA3h[a1 + 4 * 488];
                    al[0] = sA3l[a0]; al[1] = sA3l[a1];
                    al[2] = sA3l[a0 + 4 * 488]; al[3] = sA3l[a1 + 4 * 488];
#pragma unroll
                    for (int ni = 0; ni < 2; ni++) {
                        mma_bf16(acc3[mt][ni], al, bh[ni]);
                        mma_bf16(acc3[mt][ni], ah, bl[ni]);
                        mma_bf16(acc3[mt][ni], ah, bh[ni]);
                    }
                }
            }
            // epilogue: relu+bias -> g_feat NHWC fp32
#pragma unroll
            for (int mt = 0; mt < 7; mt++) {
                int p0 = (wm + mt * 4) * 16 + grp, p1 = p0 + 8;
#pragma unroll
                for (int ni = 0; ni < 2; ni++) {
                    int c0 = n0 + ni * 8 + 2 * tig;
                    float be = b3s[c0], bo = b3s[c0 + 1];
                    if (p0 < 441) {
                        float2 v = make_float2(fmaxf(acc3[mt][ni][0] + be, 0.f),
                                               fmaxf(acc3[mt][ni][1] + bo, 0.f));
                        *(float2*)&go[p0 * 64 + c0] = v;
                    }
                    if (p1 < 441) {
                        float2 v = make_float2(fmaxf(acc3[mt][ni][2] + be, 0.f),
                                               fmaxf(acc3[mt][ni][3] + bo, 0.f));
                        *(float2*)&go[p1 * 64 + c0] = v;
                    }
                }
            }
        }
    }
}

// ---------------- 3-term split-bf16 tensor-core GEMM (m16n8k16) ----------------
#define SPAD 76

__global__ void __launch_bounds__(256) gemm_bf16_kernel(const float* __restrict__ Bmat) {
    __shared__ unsigned Ah[8][SPAD];
    __shared__ unsigned Al[8][SPAD];
    __shared__ unsigned Bh[8][SPAD];
    __shared__ unsigned Bl[8][SPAD];
    const int K = FEAT_D_;
    int tid = threadIdx.x;
    int m0 = blockIdx.x * 64, n0 = blockIdx.y * 64;
    int kz = blockIdx.z;
    int kbeg = kz * KSPLIT_LEN;

    int warp = tid >> 5, lane = tid & 31;
    int wm = (warp & 1) * 32;
    int wn = (warp >> 1) * 16;
    int grp = lane >> 2, tig = lane & 3;

    int lr = tid >> 2;
    int lkq = (tid & 3) * 4;
    int k2 = lkq >> 1;

    const float* A = g_feat;
    const float* Bp = Bmat;

    float4 pa = *(const float4*)&A[(size_t)(m0 + lr) * K + kbeg + lkq];
    float4 pb = *(const float4*)&Bp[(size_t)(n0 + lr) * K + kbeg + lkq];

    float acc[2][2][4];
#pragma unroll
    for (int i = 0; i < 2; i++)
#pragma unroll
        for (int j = 0; j < 2; j++)
#pragma unroll
            for (int q = 0; q < 4; q++) acc[i][j][q] = 0.f;

    const int NIT = KSPLIT_LEN / 16;
    for (int it = 0; it < NIT; it++) {
        {
            unsigned h, l;
            split_bf(pa.x, pa.y, h, l); Ah[k2 + 0][lr] = h; Al[k2 + 0][lr] = l;
            split_bf(pa.z, pa.w, h, l); Ah[k2 + 1][lr] = h; Al[k2 + 1][lr] = l;
            split_bf(pb.x, pb.y, h, l); Bh[k2 + 0][lr] = h; Bl[k2 + 0][lr] = l;
            split_bf(pb.z, pb.w, h, l); Bh[k2 + 1][lr] = h; Bl[k2 + 1][lr] = l;
        }
        __syncthreads();
        if (it + 1 < NIT) {
            int kn = kbeg + (it + 1) * 16;
            pa = *(const float4*)&A[(size_t)(m0 + lr) * K + kn + lkq];
            pb = *(const float4*)&Bp[(size_t)(n0 + lr) * K + kn + lkq];
        }
        {
            unsigned afh[2][4], afl[2][4], bfh[2][2], bfl[2][2];
#pragma unroll
            for (int mi = 0; mi < 2; mi++) {
                int mb = wm + mi * 16 + grp;
                afh[mi][0] = Ah[tig][mb];
                afh[mi][1] = Ah[tig][mb + 8];
                afh[mi][2] = Ah[tig + 4][mb];
                afh[mi][3] = Ah[tig + 4][mb + 8];
                afl[mi][0] = Al[tig][mb];
                afl[mi][1] = Al[tig][mb + 8];
                afl[mi][2] = Al[tig + 4][mb];
                afl[mi][3] = Al[tig + 4][mb + 8];
            }
#pragma unroll
            for (int ni = 0; ni < 2; ni++) {
                int nb = wn + ni * 8 + grp;
                bfh[ni][0] = Bh[tig][nb];
                bfh[ni][1] = Bh[tig + 4][nb];
                bfl[ni][0] = Bl[tig][nb];
                bfl[ni][1] = Bl[tig + 4][nb];
            }
#pragma unroll
            for (int mi = 0; mi < 2; mi++)
#pragma unroll
                for (int ni = 0; ni < 2; ni++) {
                    mma_bf16(acc[mi][ni], afl[mi], bfh[ni]);
                    mma_bf16(acc[mi][ni], afh[mi], bfl[ni]);
                    mma_bf16(acc[mi][ni], afh[mi], bfh[ni]);
                }
        }
        __syncthreads();
    }

    float* out = g_part + (size_t)kz * (BS_ * 192);
#pragma unroll
    for (int mi = 0; mi < 2; mi++) {
#pragma unroll
        for (int ni = 0; ni < 2; ni++) {
            int col = n0 + wn + ni * 8 + 2 * tig;
            int row0 = m0 + wm + mi * 16 + grp;
            float2 v0 = make_float2(acc[mi][ni][0], acc[mi][ni][1]);
            float2 v1 = make_float2(acc[mi][ni][2], acc[mi][ni][3]);
            *(float2*)&out[(size_t)row0 * 192 + col] = v0;
            *(float2*)&out[(size_t)(row0 + 8) * 192 + col] = v1;
        }
    }
}

__global__ void __launch_bounds__(256) reduce_kernel(const float* __restrict__ bi) {
    int idx = blockIdx.x * 256 + threadIdx.x;
    if (idx >= BS_ * 192) return;
    int n = idx % 192;
    float s = bi[n];
#pragma unroll
    for (int z = 0; z < SPLITK; z++) s += g_part[(size_t)z * (BS_ * 192) + idx];
    g_ig[idx] = s;
}

// ---------------- GRU scan ----------------
__global__ void __launch_bounds__(192) gru_kernel(const float* __restrict__ h0,
                                                  const float* __restrict__ Wh,
                                                  const float* __restrict__ bn,
                                                  float* __restrict__ hfinal) {
    int b = blockIdx.x, g = threadIdx.x;
    __shared__ float h[64];
    __shared__ float hg[192];
    __shared__ float sig[192];
    float w[64];
#pragma unroll
    for (int k = 0; k < 64; k++) w[k] = Wh[g * 64 + k];
    float bnv = (g < 64) ? bn[g] : 0.f;
    if (g < 64) h[g] = h0[b * 64 + g];
    float igv = g_ig[(b * 128 + 0) * 192 + g];
    __syncthreads();
    for (int t = 0; t < 128; t++) {
        float a0 = 0.f, a1 = 0.f, a2 = 0.f, a3 = 0.f;
#pragma unroll
        for (int k = 0; k < 64; k += 4) {
            a0 += w[k] * h[k];
            a1 += w[k + 1] * h[k + 1];
            a2 += w[k + 2] * h[k + 2];
            a3 += w[k + 3] * h[k + 3];
        }
        hg[g] = (a0 + a1) + (a2 + a3);
        sig[g] = igv;
        __syncthreads();
        int tn = (t < 127) ? t + 1 : 127;
        igv = g_ig[(b * 128 + tn) * 192 + g];
        if (g < 64) {
            float rr = 1.f / (1.f + __expf(-(sig[g] + hg[g])));
            float zz = 1.f / (1.f + __expf(-(sig[64 + g] + hg[64 + g])));
            float nn = tanhf(sig[128 + g] + rr * (hg[128 + g] + bnv));
            float hn = (1.f - zz) * nn + zz * h[g];
            h[g] = hn;
            g_allh[(b * 128 + t) * 64 + g] = hn;
        }
        __syncthreads();
    }
    if (g < 64) hfinal[b * 64 + g] = h[g];
}

// ---------------- heads ----------------
#define HEADS_SMEM_BYTES (14816 * 4)
__global__ void __launch_bounds__(128) heads_kernel(
    const float* __restrict__ Wa1, const float* __restrict__ ba1,
    const float* __restrict__ Wa2, const float* __restrict__ ba2,
    const float* __restrict__ Wc1, const float* __restrict__ bc1,
    const float* __restrict__ Wc2, const float* __restrict__ bc2,
    float* __restrict__ logits, float* __restrict__ values) {
    extern __shared__ float s[];
    float* sWa1 = s;
    float* sWc1 = s + 4096;
    float* sWa2 = s + 8192;
    float* sWc2 = s + 14336;
    float* sba1 = s + 14400;
    float* sbc1 = s + 14464;
    float* sba2 = s + 14528;
    float* sh   = s + 14624;
    float* sa   = s + 14688;
    float* sc   = s + 14752;
    int tid = threadIdx.x;
    for (int i = tid; i < 4096; i += 128) { sWa1[i] = Wa1[i]; sWc1[i] = Wc1[i]; }
    for (int i = tid; i < 6144; i += 128) sWa2[i] = Wa2[i];
    if (tid < 64) { sWc2[tid] = Wc2[tid]; sba1[tid] = ba1[tid]; sbc1[tid] = bc1[tid]; }
    if (tid < 96) sba2[tid] = ba2[tid];
    float bc2v = bc2[0];
    __syncthreads();
    for (int r = blockIdx.x * 32; r < blockIdx.x * 32 + 32; r++) {
        if (tid < 64) sh[tid] = g_allh[r * 64 + tid];
        __syncthreads();
        {
            int j = tid & 63;
            const float* W = (tid < 64) ? sWa1 : sWc1;
            float acc = 0.f;
#pragma unroll
            for (int i = 0; i < 64; i++) acc += sh[i] * W[i * 64 + j];
            float v = tanhf(acc + ((tid < 64) ? sba1[j] : sbc1[j]));
            if (tid < 64) sa[j] = v; else sc[j] = v;
        }
        __syncthreads();
        if (tid < 96) {
            float acc = sba2[tid];
#pragma unroll
            for (int j = 0; j < 64; j++) acc += sa[j] * sWa2[j * 96 + tid];
            logits[r * 96 + tid] = acc;
        } else if (tid == 96) {
            float acc = bc2v;
#pragma unroll
            for (int j = 0; j < 64; j++) acc += sc[j] * sWc2[j];
            values[r] = acc;
        }
        __syncthreads();
    }
}

// ---------------- launch ----------------
extern "C" void kernel_launch(void* const* d_in, const int* in_sizes, int n_in,
                              void* d_out, int out_size) {
    const int*   positions = (const int*)d_in[0];
    const void*  umask     = d_in[1];
    const int*   tile      = (const int*)d_in[2];
    const int*   rpos      = (const int*)d_in[3];
    const void*  rmask     = d_in[4];
    const float* reward    = (const float*)d_in[5];
    const float* hidden    = (const float*)d_in[6];
    const float* emb_tile  = (const float*)d_in[7];
    const float* emb_unit  = (const float*)d_in[8];
    const float* w1 = (const float*)d_in[9];
    const float* b1 = (const float*)d_in[10];
    const float* w2 = (const float*)d_in[11];
    const float* b2 = (const float*)d_in[12];
    const float* w3 = (const float*)d_in[13];
    const float* b3 = (const float*)d_in[14];
    const float* Wi = (const float*)d_in[15];
    const float* Wh = (const float*)d_in[16];
    const float* bi = (const float*)d_in[17];
    const float* bn = (const float*)d_in[18];
    const float* Wa1 = (const float*)d_in[19];
    const float* ba1 = (const float*)d_in[20];
    const float* Wa2 = (const float*)d_in[21];
    const float* ba2 = (const float*)d_in[22];
    const float* Wc1 = (const float*)d_in[23];
    const float* bc1 = (const float*)d_in[24];
    const float* Wc2 = (const float*)d_in[25];
    const float* bc2 = (const float*)d_in[26];
    float* out = (float*)d_out;

    float* out_logits = out;
    float* out_values = out + 393216;
    float* out_hidden = out + 397312;

    const int conv_smem = CONV_SMEM_FLOATS * (int)sizeof(float);
    cudaFuncSetAttribute(conv_kernel, cudaFuncAttributeMaxDynamicSharedMemorySize, conv_smem);
    cudaFuncSetAttribute(heads_kernel, cudaFuncAttributeMaxDynamicSharedMemorySize, HEADS_SMEM_BYTES);

    conv_kernel<<<BS_, 256, conv_smem>>>(positions, umask, tile, rpos, rmask, reward,
                                         emb_tile, emb_unit, w1, b1, w2, b2, w3, b3);
    gemm_bf16_kernel<<<dim3(64, 3, SPLITK), 256>>>(Wi);
    reduce_kernel<<<(BS_ * 192 + 255) / 256, 256>>>(bi);
    gru_kernel<<<32, 192>>>(hidden, Wh, bn, out_hidden);
    heads_kernel<<<128, 128, HEADS_SMEM_BYTES>>>(Wa1, ba1, Wa2, ba2, Wc1, bc1, Wc2, bc2,
                                                 out_logits, out_values);
}

// round 9
// speedup vs baseline: 1.9181x; 1.0300x over previous
#include <cuda_runtime.h>
#include <math.h>

#define B_ 32
#define S_ 128
#define BS_ 4096
#define FEAT_D_ 28224
#define SPLITK 4
#define KSPLIT_LEN (FEAT_D_ / SPLITK)   // 7056
#define PART_STRIDE (BS_ * 192)         // 786432

// ---------------- scratch ----------------
__device__ float g_feat[(size_t)BS_ * FEAT_D_];
__device__ float g_part[(size_t)SPLITK * BS_ * 192];
__device__ float g_allh[BS_ * 64];

// ---------------- bool-mask dtype detection ----------------
__device__ __forceinline__ int detect_bool_mode(const unsigned char* p) {
    bool any80 = false, nz = false;
    for (int i = 0; i < 256; i++) {
        unsigned char v = p[i];
        int m = i & 3;
        if (m == 2 && v == 0x80) any80 = true;
        if (m != 0 && v != 0) nz = true;
    }
    if (!nz) return 1;
    if (any80) return 2;
    return 0;
}
__device__ __forceinline__ bool get_mask(const void* p, int i, int mode) {
    if (mode == 1) return ((const int*)p)[i] != 0;
    if (mode == 2) return ((const float*)p)[i] != 0.0f;
    return ((const unsigned char*)p)[i] != 0;
}

// ---------------- bf16 split helpers ----------------
__device__ __forceinline__ unsigned pack_bf16x2(float e, float o) {
    unsigned r;
    asm("cvt.rn.bf16x2.f32 %0, %1, %2;" : "=r"(r) : "f"(o), "f"(e));  // lo=e, hi=o
    return r;
}
__device__ __forceinline__ void split_bf(float e, float o, unsigned& h, unsigned& l) {
    h = pack_bf16x2(e, o);
    float he = __uint_as_float(h << 16);
    float ho = __uint_as_float(h & 0xffff0000u);
    l = pack_bf16x2(e - he, o - ho);
}
__device__ __forceinline__ void mma_bf16(float* acc, const unsigned* a, const unsigned* b) {
    asm volatile(
        "mma.sync.aligned.m16n8k16.row.col.f32.bf16.bf16.f32 "
        "{%0,%1,%2,%3}, {%4,%5,%6,%7}, {%8,%9}, {%0,%1,%2,%3};"
        : "+f"(acc[0]), "+f"(acc[1]), "+f"(acc[2]), "+f"(acc[3])
        : "r"(a[0]), "r"(a[1]), "r"(a[2]), "r"(a[3]), "r"(b[0]), "r"(b[1]));
}

// ---------------- conv kernel smem layout (floats) ----------------
// Region1 [0..15488): grid 13824 + wb1 1536  ==> overlaid by sA3 (uint2 16x484 = 15488 fl)
// Region2 [15488..26304): sA2 (uint2 8x532 = 8512 fl) + wB2 (uint2 32x36 = 2304 fl)
//                         ==> overlaid by wB3 (uint2 64x68 = 8704 fl)
// bias [26304..26432)
// All uint2 strides ≡ 4 (mod 16) in 8B units -> LDS.64 phase-conflict-free.
#define OFF_GRID 0
#define OFF_WB1  13824
#define OFF_A3   0
#define OFF_A2   15488
#define OFF_WB2  24000
#define OFF_WB3  15488
#define OFF_BIAS 26304
#define CONV_SMEM_FLOATS 26432   // 105728 B -> 2 CTAs/SM

__global__ void __launch_bounds__(256, 2) conv_kernel(
    const int* __restrict__ positions, const void* __restrict__ umask,
    const int* __restrict__ tile_type, const int* __restrict__ rpos,
    const void* __restrict__ rmask, const float* __restrict__ reward,
    const float* __restrict__ emb_tile, const float* __restrict__ emb_unit,
    const float* __restrict__ w1, const float* __restrict__ b1,
    const float* __restrict__ w2, const float* __restrict__ b2,
    const float* __restrict__ w3, const float* __restrict__ b3) {
    extern __shared__ float sm[];
    int tid = threadIdx.x, bs = blockIdx.x;
    float* grid = sm + OFF_GRID;
    float* wb1  = sm + OFF_WB1;
    float* sb   = sm + OFF_BIAS;   // b1[0:16) b2[16:48) b3[48:112)

    // ---- phase 0: weights/biases + grid build ----
    for (int i = tid; i < 1536; i += 256) wb1[i] = w1[i];
    {   // wB2 packed pairs over cin, interleaved {h,l}
        uint2* wB2 = (uint2*)(sm + OFF_WB2);
        for (int i = tid; i < 32 * 32; i += 256) {
            int r = i >> 5, n = i & 31;
            int d = r >> 3, ci2 = r & 7;
            float e = w2[(d * 16 + 2 * ci2) * 32 + n];
            float o = w2[(d * 16 + 2 * ci2 + 1) * 32 + n];
            unsigned h, l; split_bf(e, o, h, l);
            wB2[r * 36 + n] = make_uint2(h, l);
        }
    }
    if (tid < 16) sb[tid] = b1[tid];
    else if (tid < 48) sb[tid] = b2[tid - 16];
    else if (tid < 112) sb[tid] = b3[tid - 48];

    for (int i = tid; i < 19 * 576; i += 256) grid[4 * 576 + i] = 0.f;
    float rw = reward[bs];
    for (int p = tid; p < 576; p += 256) {
        int tt = tile_type[bs * 576 + p] * 4;
        grid[p] = emb_tile[tt];
        grid[576 + p] = emb_tile[tt + 1];
        grid[1152 + p] = emb_tile[tt + 2];
        grid[1728 + p] = emb_tile[tt + 3];
        grid[23 * 576 + p] = rw;
    }
    __syncthreads();
    if (tid < 32) {
        int mode = detect_bool_mode((const unsigned char*)umask);
        if (get_mask(umask, bs * 32 + tid, mode)) {
            int t = tid >> 4, u = tid & 15;
            int pb = (bs * 32 + tid) * 2;
            int y = positions[pb], x = positions[pb + 1];
            int cell = y * 24 + x;
            atomicAdd(&grid[(4 + t) * 576 + cell], 0.0625f);
#pragma unroll
            for (int e = 0; e < 8; e++)
                atomicAdd(&grid[(6 + t * 8 + e) * 576 + cell], emb_unit[u * 8 + e]);
        }
    } else if (tid < 38) {
        int r = tid - 32;
        int mode = detect_bool_mode((const unsigned char*)rmask);
        if (get_mask(rmask, bs * 6 + r, mode)) {
            int pb = (bs * 6 + r) * 2;
            int y = rpos[pb], x = rpos[pb + 1];
            atomicAdd(&grid[22 * 576 + y * 24 + x], 1.0f);
        }
    }
    __syncthreads();

    // ---- conv1: FFMA 24->16ch, 24x24 -> 23x23 (529). 4 pixels/thread ----
    {
        uint2* sA2 = (uint2*)(sm + OFF_A2);
        if (tid < 133) {
            int p[4], base[4]; bool val[4];
#pragma unroll
            for (int j = 0; j < 4; j++) {
                p[j] = tid + j * 133;
                val[j] = (p[j] < 529);
                int pc = val[j] ? p[j] : 0;
                int y = pc / 23;
                base[j] = y * 24 + (pc - y * 23);
            }
            float acc[4][16];
#pragma unroll
            for (int j = 0; j < 4; j++)
#pragma unroll
                for (int q = 0; q < 16; q++) acc[j][q] = 0.f;
#pragma unroll
            for (int d = 0; d < 4; d++) {
                int off = (d >> 1) * 24 + (d & 1);
#pragma unroll 8
                for (int ci = 0; ci < 24; ci++) {
                    float v0 = grid[ci * 576 + base[0] + off];
                    float v1 = grid[ci * 576 + base[1] + off];
                    float v2 = grid[ci * 576 + base[2] + off];
                    float v3 = grid[ci * 576 + base[3] + off];
                    const float4* wq = (const float4*)(wb1 + (d * 24 + ci) * 16);
                    float4 wv[4] = {wq[0], wq[1], wq[2], wq[3]};
#pragma unroll
                    for (int q = 0; q < 4; q++) {
                        acc[0][q * 4 + 0] += v0 * wv[q].x; acc[0][q * 4 + 1] += v0 * wv[q].y;
                        acc[0][q * 4 + 2] += v0 * wv[q].z; acc[0][q * 4 + 3] += v0 * wv[q].w;
                        acc[1][q * 4 + 0] += v1 * wv[q].x; acc[1][q * 4 + 1] += v1 * wv[q].y;
                        acc[1][q * 4 + 2] += v1 * wv[q].z; acc[1][q * 4 + 3] += v1 * wv[q].w;
                        acc[2][q * 4 + 0] += v2 * wv[q].x; acc[2][q * 4 + 1] += v2 * wv[q].y;
                        acc[2][q * 4 + 2] += v2 * wv[q].z; acc[2][q * 4 + 3] += v2 * wv[q].w;
                        acc[3][q * 4 + 0] += v3 * wv[q].x; acc[3][q * 4 + 1] += v3 * wv[q].y;
                        acc[3][q * 4 + 2] += v3 * wv[q].z; acc[3][q * 4 + 3] += v3 * wv[q].w;
                    }
                }
            }
#pragma unroll
            for (int j = 0; j < 4; j++) {
                if (!val[j]) continue;
#pragma unroll
                for (int q2 = 0; q2 < 8; q2++) {
                    float e = fmaxf(acc[j][2 * q2] + sb[2 * q2], 0.f);
                    float o = fmaxf(acc[j][2 * q2 + 1] + sb[2 * q2 + 1], 0.f);
                    unsigned h, l; split_bf(e, o, h, l);
                    sA2[q2 * 532 + p[j]] = make_uint2(h, l);
                }
            }
        }
    }
    __syncthreads();

    int wid = tid >> 5, lane = tid & 31;
    int grp = lane >> 2, tig = lane & 3;
    int wm = wid & 3, wn = wid >> 2;

    // ---- conv2: MMA 16->32ch, 23x23 -> 22x22 (484) ----
    {
        const uint2* sA2 = (const uint2*)(sm + OFF_A2);
        const uint2* wB2 = (const uint2*)(sm + OFF_WB2);
        float acc2[8][2][4];
#pragma unroll
        for (int mt = 0; mt < 8; mt++)
#pragma unroll
            for (int ni = 0; ni < 2; ni++)
#pragma unroll
                for (int q = 0; q < 4; q++) acc2[mt][ni][q] = 0.f;
        int i0[8], i1[8];
#pragma unroll
        for (int mt = 0; mt < 8; mt++) {
            int tile = wm + mt * 4;
            int p0 = tile * 16 + grp, p1 = p0 + 8;
            int q0 = (p0 < 484) ? p0 : 0; i0[mt] = q0 + q0 / 22;
            int q1 = (p1 < 484) ? p1 : 0; i1[mt] = q1 + q1 / 22;
        }
#pragma unroll 1
        for (int d = 0; d < 4; d++) {
            int off = (d >> 1) * 23 + (d & 1);
            unsigned bh[2][2], bl[2][2];
#pragma unroll
            for (int ni = 0; ni < 2; ni++) {
                int nb = wn * 16 + ni * 8 + grp;
                uint2 bv0 = wB2[(d * 8 + tig) * 36 + nb];
                uint2 bv1 = wB2[(d * 8 + tig + 4) * 36 + nb];
                bh[ni][0] = bv0.x; bh[ni][1] = bv1.x;
                bl[ni][0] = bv0.y; bl[ni][1] = bv1.y;
            }
#pragma unroll
            for (int mt = 0; mt < 8; mt++) {
                if (wm + mt * 4 < 31) {
                    uint2 v00 = sA2[tig * 532 + i0[mt] + off];
                    uint2 v01 = sA2[tig * 532 + i1[mt] + off];
                    uint2 v10 = sA2[(tig + 4) * 532 + i0[mt] + off];
                    uint2 v11 = sA2[(tig + 4) * 532 + i1[mt] + off];
                    unsigned ah[4] = {v00.x, v01.x, v10.x, v11.x};
                    unsigned al[4] = {v00.y, v01.y, v10.y, v11.y};
#pragma unroll
                    for (int ni = 0; ni < 2; ni++) {
                        mma_bf16(acc2[mt][ni], al, bh[ni]);
                        mma_bf16(acc2[mt][ni], ah, bl[ni]);
                        mma_bf16(acc2[mt][ni], ah, bh[ni]);
                    }
                }
            }
        }
        // epilogue: relu+bias, pack pairs -> sA3 (overlays grid/wb1)
        uint2* sA3 = (uint2*)(sm + OFF_A3);
        const float* b2s = sb + 16;
#pragma unroll
        for (int mt = 0; mt < 8; mt++) {
            int tile = wm + mt * 4;
            if (tile < 31) {
                int p0 = tile * 16 + grp, p1 = p0 + 8;
#pragma unroll
                for (int ni = 0; ni < 2; ni++) {
                    int c0 = wn * 16 + ni * 8 + 2 * tig;
                    float be = b2s[c0], bo = b2s[c0 + 1];
                    int c2 = c0 >> 1;
                    if (p0 < 484) {
                        unsigned h, l;
                        split_bf(fmaxf(acc2[mt][ni][0] + be, 0.f),
                                 fmaxf(acc2[mt][ni][1] + bo, 0.f), h, l);
                        sA3[c2 * 484 + p0] = make_uint2(h, l);
                    }
                    if (p1 < 484) {
                        unsigned h, l;
                        split_bf(fmaxf(acc2[mt][ni][2] + be, 0.f),
                                 fmaxf(acc2[mt][ni][3] + bo, 0.f), h, l);
                        sA3[c2 * 484 + p1] = make_uint2(h, l);
                    }
                }
            }
        }
    }
    __syncthreads();

    // ---- load wB3 (overlays sA2/wB2 — dead) ----
    {
        uint2* wB3 = (uint2*)(sm + OFF_WB3);
        for (int i = tid; i < 64 * 64; i += 256) {
            int r = i >> 6, n = i & 63;
            int d = r >> 4, ci2 = r & 15;
            float e = w3[(d * 32 + 2 * ci2) * 64 + n];
            float o = w3[(d * 32 + 2 * ci2 + 1) * 64 + n];
            unsigned h, l; split_bf(e, o, h, l);
            wB3[r * 68 + n] = make_uint2(h, l);
        }
    }
    __syncthreads();

    // ---- conv3: MMA 32->64ch, 22x22 -> 21x21 (441), 2 n-passes ----
    {
        const uint2* sA3 = (const uint2*)(sm + OFF_A3);
        const uint2* wB3 = (const uint2*)(sm + OFF_WB3);
        const float* b3s = sb + 48;
        float* go = g_feat + (size_t)bs * FEAT_D_;
        int i0[7], i1[7];
#pragma unroll
        for (int mt = 0; mt < 7; mt++) {
            int p0 = (wm + mt * 4) * 16 + grp, p1 = p0 + 8;
            int q0 = (p0 < 441) ? p0 : 0; i0[mt] = q0 + q0 / 21;
            int q1 = (p1 < 441) ? p1 : 0; i1[mt] = q1 + q1 / 21;
        }
#pragma unroll 1
        for (int pass = 0; pass < 2; pass++) {
            int n0 = wn * 32 + pass * 16;
            float acc3[7][2][4];
#pragma unroll
            for (int mt = 0; mt < 7; mt++)
#pragma unroll
                for (int ni = 0; ni < 2; ni++)
#pragma unroll
                    for (int q = 0; q < 4; q++) acc3[mt][ni][q] = 0.f;
#pragma unroll 1
            for (int dk = 0; dk < 8; dk++) {
                int d = dk >> 1, h8 = dk & 1;
                int off = (d >> 1) * 22 + (d & 1);
                int kb = h8 * 8;
                unsigned bh[2][2], bl[2][2];
#pragma unroll
                for (int ni = 0; ni < 2; ni++) {
                    int nb = n0 + ni * 8 + grp;
                    uint2 bv0 = wB3[(d * 16 + kb + tig) * 68 + nb];
                    uint2 bv1 = wB3[(d * 16 + kb + tig + 4) * 68 + nb];
                    bh[ni][0] = bv0.x; bh[ni][1] = bv1.x;
                    bl[ni][0] = bv0.y; bl[ni][1] = bv1.y;
                }
#pragma unroll
                for (int mt = 0; mt < 7; mt++) {
                    int a0 = (kb + tig) * 484 + i0[mt] + off;
                    int a1 = (kb + tig) * 484 + i1[mt] + off;
                    uint2 v00 = sA3[a0];
                    uint2 v01 = sA3[a1];
                    uint2 v10 = sA3[a0 + 4 * 484];
                    uint2 v11 = sA3[a1 + 4 * 484];
                    unsigned ah[4] = {v00.x, v01.x, v10.x, v11.x};
                    unsigned al[4] = {v00.y, v01.y, v10.y, v11.y};
#pragma unroll
                    for (int ni = 0; ni < 2; ni++) {
                        mma_bf16(acc3[mt][ni], al, bh[ni]);
                        mma_bf16(acc3[mt][ni], ah, bl[ni]);
                        mma_bf16(acc3[mt][ni], ah, bh[ni]);
                    }
                }
            }
            // epilogue: relu+bias -> g_feat NHWC fp32
#pragma unroll
            for (int mt = 0; mt < 7; mt++) {
                int p0 = (wm + mt * 4) * 16 + grp, p1 = p0 + 8;
#pragma unroll
                for (int ni = 0; ni < 2; ni++) {
                    int c0 = n0 + ni * 8 + 2 * tig;
                    float be = b3s[c0], bo = b3s[c0 + 1];
                    if (p0 < 441) {
                        float2 v = make_float2(fmaxf(acc3[mt][ni][0] + be, 0.f),
                                               fmaxf(acc3[mt][ni][1] + bo, 0.f));
                        *(float2*)&go[p0 * 64 + c0] = v;
                    }
                    if (p1 < 441) {
                        float2 v = make_float2(fmaxf(acc3[mt][ni][2] + be, 0.f),
                                               fmaxf(acc3[mt][ni][3] + bo, 0.f));
                        *(float2*)&go[p1 * 64 + c0] = v;
                    }
                }
            }
        }
    }
}

// ---------------- 3-term split-bf16 tensor-core GEMM (m16n8k16), interleaved smem ----------------
#define SPAD2 68   // uint2 stride: 68 ≡ 4 (mod 16) -> LDS.64 conflict-free frag loads

__global__ void __launch_bounds__(256) gemm_bf16_kernel(const float* __restrict__ Bmat) {
    __shared__ uint2 A2s[8][SPAD2];
    __shared__ uint2 B2s[8][SPAD2];
    const int K = FEAT_D_;
    int tid = threadIdx.x;
    int m0 = blockIdx.x * 64, n0 = blockIdx.y * 64;
    int kz = blockIdx.z;
    int kbeg = kz * KSPLIT_LEN;

    int warp = tid >> 5, lane = tid & 31;
    int wm = (warp & 1) * 32;
    int wn = (warp >> 1) * 16;
    int grp = lane >> 2, tig = lane & 3;

    int lr = tid >> 2;
    int lkq = (tid & 3) * 4;
    int k2 = lkq >> 1;

    const float* A = g_feat;
    const float* Bp = Bmat;

    float4 pa = *(const float4*)&A[(size_t)(m0 + lr) * K + kbeg + lkq];
    float4 pb = *(const float4*)&Bp[(size_t)(n0 + lr) * K + kbeg + lkq];

    float acc[2][2][4];
#pragma unroll
    for (int i = 0; i < 2; i++)
#pragma unroll
        for (int j = 0; j < 2; j++)
#pragma unroll
            for (int q = 0; q < 4; q++) acc[i][j][q] = 0.f;

    const int NIT = KSPLIT_LEN / 16;
    for (int it = 0; it < NIT; it++) {
        {
            unsigned h, l;
            split_bf(pa.x, pa.y, h, l); A2s[k2 + 0][lr] = make_uint2(h, l);
            split_bf(pa.z, pa.w, h, l); A2s[k2 + 1][lr] = make_uint2(h, l);
            split_bf(pb.x, pb.y, h, l); B2s[k2 + 0][lr] = make_uint2(h, l);
            split_bf(pb.z, pb.w, h, l); B2s[k2 + 1][lr] = make_uint2(h, l);
        }
        __syncthreads();
        if (it + 1 < NIT) {
            int kn = kbeg + (it + 1) * 16;
            pa = *(const float4*)&A[(size_t)(m0 + lr) * K + kn + lkq];
            pb = *(const float4*)&Bp[(size_t)(n0 + lr) * K + kn + lkq];
        }
        {
            unsigned afh[2][4], afl[2][4], bfh[2][2], bfl[2][2];
#pragma unroll
            for (int mi = 0; mi < 2; mi++) {
                int mb = wm + mi * 16 + grp;
                uint2 a00 = A2s[tig][mb];
                uint2 a01 = A2s[tig][mb + 8];
                uint2 a10 = A2s[tig + 4][mb];
                uint2 a11 = A2s[tig + 4][mb + 8];
                afh[mi][0] = a00.x; afh[mi][1] = a01.x; afh[mi][2] = a10.x; afh[mi][3] = a11.x;
                afl[mi][0] = a00.y; afl[mi][1] = a01.y; afl[mi][2] = a10.y; afl[mi][3] = a11.y;
            }
#pragma unroll
            for (int ni = 0; ni < 2; ni++) {
                int nb = wn + ni * 8 + grp;
                uint2 b0 = B2s[tig][nb];
                uint2 b1 = B2s[tig + 4][nb];
                bfh[ni][0] = b0.x; bfh[ni][1] = b1.x;
                bfl[ni][0] = b0.y; bfl[ni][1] = b1.y;
            }
#pragma unroll
            for (int mi = 0; mi < 2; mi++)
#pragma unroll
                for (int ni = 0; ni < 2; ni++) {
                    mma_bf16(acc[mi][ni], afl[mi], bfh[ni]);
                    mma_bf16(acc[mi][ni], afh[mi], bfl[ni]);
                    mma_bf16(acc[mi][ni], afh[mi], bfh[ni]);
                }
        }
        __syncthreads();
    }

    float* out = g_part + (size_t)kz * PART_STRIDE;
#pragma unroll
    for (int mi = 0; mi < 2; mi++) {
#pragma unroll
        for (int ni = 0; ni < 2; ni++) {
            int col = n0 + wn + ni * 8 + 2 * tig;
            int row0 = m0 + wm + mi * 16 + grp;
            float2 v0 = make_float2(acc[mi][ni][0], acc[mi][ni][1]);
            float2 v1 = make_float2(acc[mi][ni][2], acc[mi][ni][3]);
            *(float2*)&out[(size_t)row0 * 192 + col] = v0;
            *(float2*)&out[(size_t)(row0 + 8) * 192 + col] = v1;
        }
    }
}

// ---------------- GRU scan (fused split-K reduce + bias) ----------------
__global__ void __launch_bounds__(192) gru_kernel(const float* __restrict__ h0,
                                                  const float* __restrict__ Wh,
                                                  const float* __restrict__ bn,
                                                  const float* __restrict__ bi,
                                                  float* __restrict__ hfinal) {
    int b = blockIdx.x, g = threadIdx.x;
    __shared__ float h[64];
    __shared__ float hg[192];
    __shared__ float sig[192];
    float w[64];
#pragma unroll
    for (int k = 0; k < 64; k++) w[k] = Wh[g * 64 + k];
    float bnv = (g < 64) ? bn[g] : 0.f;
    float biv = bi[g];
    if (g < 64) h[g] = h0[b * 64 + g];
    const float* P = g_part;
    int idx = (b * 128 + 0) * 192 + g;
    float q0 = P[idx], q1 = P[PART_STRIDE + idx];
    float q2 = P[2 * PART_STRIDE + idx], q3 = P[3 * PART_STRIDE + idx];
    __syncthreads();
    for (int t = 0; t < 128; t++) {
        float a0 = 0.f, a1 = 0.f, a2 = 0.f, a3 = 0.f;
#pragma unroll
        for (int k = 0; k < 64; k += 4) {
            a0 += w[k] * h[k];
            a1 += w[k + 1] * h[k + 1];
            a2 += w[k + 2] * h[k + 2];
            a3 += w[k + 3] * h[k + 3];
        }
        hg[g] = (a0 + a1) + (a2 + a3);
        sig[g] = biv + q0 + q1 + q2 + q3;
        __syncthreads();
        int tn = (t < 127) ? t + 1 : 127;
        int idxn = (b * 128 + tn) * 192 + g;
        q0 = P[idxn]; q1 = P[PART_STRIDE + idxn];
        q2 = P[2 * PART_STRIDE + idxn]; q3 = P[3 * PART_STRIDE + idxn];
        if (g < 64) {
            float rr = 1.f / (1.f + __expf(-(sig[g] + hg[g])));
            float zz = 1.f / (1.f + __expf(-(sig[64 + g] + hg[64 + g])));
            float nn = tanhf(sig[128 + g] + rr * (hg[128 + g] + bnv));
            float hn = (1.f - zz) * nn + zz * h[g];
            h[g] = hn;
            g_allh[(b * 128 + t) * 64 + g] = hn;
        }
        __syncthreads();
    }
    if (g < 64) hfinal[b * 64 + g] = h[g];
}

// ---------------- heads ----------------
#define HEADS_SMEM_BYTES (14816 * 4)
__global__ void __launch_bounds__(128) heads_kernel(
    const float* __restrict__ Wa1, const float* __restrict__ ba1,
    const float* __restrict__ Wa2, const float* __restrict__ ba2,
    const float* __restrict__ Wc1, const float* __restrict__ bc1,
    const float* __restrict__ Wc2, const float* __restrict__ bc2,
    float* __restrict__ logits, float* __restrict__ values) {
    extern __shared__ float s[];
    float* sWa1 = s;
    float* sWc1 = s + 4096;
    float* sWa2 = s + 8192;
    float* sWc2 = s + 14336;
    float* sba1 = s + 14400;
    float* sbc1 = s + 14464;
    float* sba2 = s + 14528;
    float* sh   = s + 14624;
    float* sa   = s + 14688;
    float* sc   = s + 14752;
    int tid = threadIdx.x;
    for (int i = tid; i < 4096; i += 128) { sWa1[i] = Wa1[i]; sWc1[i] = Wc1[i]; }
    for (int i = tid; i < 6144; i += 128) sWa2[i] = Wa2[i];
    if (tid < 64) { sWc2[tid] = Wc2[tid]; sba1[tid] = ba1[tid]; sbc1[tid] = bc1[tid]; }
    if (tid < 96) sba2[tid] = ba2[tid];
    float bc2v = bc2[0];
    __syncthreads();
    for (int r = blockIdx.x * 32; r < blockIdx.x * 32 + 32; r++) {
        if (tid < 64) sh[tid] = g_allh[r * 64 + tid];
        __syncthreads();
        {
            int j = tid & 63;
            const float* W = (tid < 64) ? sWa1 : sWc1;
            float acc = 0.f;
#pragma unroll
            for (int i = 0; i < 64; i++) acc += sh[i] * W[i * 64 + j];
            float v = tanhf(acc + ((tid < 64) ? sba1[j] : sbc1[j]));
            if (tid < 64) sa[j] = v; else sc[j] = v;
        }
        __syncthreads();
        if (tid < 96) {
            float acc = sba2[tid];
#pragma unroll
            for (int j = 0; j < 64; j++) acc += sa[j] * sWa2[j * 96 + tid];
            logits[r * 96 + tid] = acc;
        } else if (tid == 96) {
            float acc = bc2v;
#pragma unroll
            for (int j = 0; j < 64; j++) acc += sc[j] * sWc2[j];
            values[r] = acc;
        }
        __syncthreads();
    }
}

// ---------------- launch ----------------
extern "C" void kernel_launch(void* const* d_in, const int* in_sizes, int n_in,
                              void* d_out, int out_size) {
    const int*   positions = (const int*)d_in[0];
    const void*  umask     = d_in[1];
    const int*   tile      = (const int*)d_in[2];
    const int*   rpos      = (const int*)d_in[3];
    const void*  rmask     = d_in[4];
    const float* reward    = (const float*)d_in[5];
    const float* hidden    = (const float*)d_in[6];
    const float* emb_tile  = (const float*)d_in[7];
    const float* emb_unit  = (const float*)d_in[8];
    const float* w1 = (const float*)d_in[9];
    const float* b1 = (const float*)d_in[10];
    const float* w2 = (const float*)d_in[11];
    const float* b2 = (const float*)d_in[12];
    const float* w3 = (const float*)d_in[13];
    const float* b3 = (const float*)d_in[14];
    const float* Wi = (const float*)d_in[15];
    const float* Wh = (const float*)d_in[16];
    const float* bi = (const float*)d_in[17];
    const float* bn = (const float*)d_in[18];
    const float* Wa1 = (const float*)d_in[19];
    const float* ba1 = (const float*)d_in[20];
    const float* Wa2 = (const float*)d_in[21];
    const float* ba2 = (const float*)d_in[22];
    const float* Wc1 = (const float*)d_in[23];
    const float* bc1 = (const float*)d_in[24];
    const float* Wc2 = (const float*)d_in[25];
    const float* bc2 = (const float*)d_in[26];
    float* out = (float*)d_out;

    float* out_logits = out;
    float* out_values = out + 393216;
    float* out_hidden = out + 397312;

    const int conv_smem = CONV_SMEM_FLOATS * (int)sizeof(float);
    cudaFuncSetAttribute(conv_kernel, cudaFuncAttributeMaxDynamicSharedMemorySize, conv_smem);
    cudaFuncSetAttribute(heads_kernel, cudaFuncAttributeMaxDynamicSharedMemorySize, HEADS_SMEM_BYTES);

    conv_kernel<<<BS_, 256, conv_smem>>>(positions, umask, tile, rpos, rmask, reward,
                                         emb_tile, emb_unit, w1, b1, w2, b2, w3, b3);
    gemm_bf16_kernel<<<dim3(64, 3, SPLITK), 256>>>(Wi);
    gru_kernel<<<32, 192>>>(hidden, Wh, bn, bi, out_hidden);
    heads_kernel<<<128, 128, HEADS_SMEM_BYTES>>>(Wa1, ba1, Wa2, ba2, Wc1, bc1, Wc2, bc2,
                                                 out_logits, out_values);
}

// round 10
// speedup vs baseline: 2.0691x; 1.0787x over previous
#include <cuda_runtime.h>
#include <math.h>

#define B_ 32
#define S_ 128
#define BS_ 4096
#define FEAT_D_ 28224
#define SPLITK 4
#define KSPLIT_LEN (FEAT_D_ / SPLITK)   // 7056
#define PART_STRIDE (BS_ * 192)         // 786432

// ---------------- scratch ----------------
__device__ float g_feat[(size_t)BS_ * FEAT_D_];
__device__ float g_part[(size_t)SPLITK * BS_ * 192];
__device__ float g_allh[BS_ * 64];

// ---------------- bool-mask dtype detection ----------------
__device__ __forceinline__ int detect_bool_mode(const unsigned char* p) {
    bool any80 = false, nz = false;
    for (int i = 0; i < 256; i++) {
        unsigned char v = p[i];
        int m = i & 3;
        if (m == 2 && v == 0x80) any80 = true;
        if (m != 0 && v != 0) nz = true;
    }
    if (!nz) return 1;
    if (any80) return 2;
    return 0;
}
__device__ __forceinline__ bool get_mask(const void* p, int i, int mode) {
    if (mode == 1) return ((const int*)p)[i] != 0;
    if (mode == 2) return ((const float*)p)[i] != 0.0f;
    return ((const unsigned char*)p)[i] != 0;
}

// ---------------- bf16 split helpers ----------------
__device__ __forceinline__ unsigned pack_bf16x2(float e, float o) {
    unsigned r;
    asm("cvt.rn.bf16x2.f32 %0, %1, %2;" : "=r"(r) : "f"(o), "f"(e));  // lo=e, hi=o
    return r;
}
__device__ __forceinline__ void split_bf(float e, float o, unsigned& h, unsigned& l) {
    h = pack_bf16x2(e, o);
    float he = __uint_as_float(h << 16);
    float ho = __uint_as_float(h & 0xffff0000u);
    l = pack_bf16x2(e - he, o - ho);
}
__device__ __forceinline__ void mma_bf16(float* acc, const unsigned* a, const unsigned* b) {
    asm volatile(
        "mma.sync.aligned.m16n8k16.row.col.f32.bf16.bf16.f32 "
        "{%0,%1,%2,%3}, {%4,%5,%6,%7}, {%8,%9}, {%0,%1,%2,%3};"
        : "+f"(acc[0]), "+f"(acc[1]), "+f"(acc[2]), "+f"(acc[3])
        : "r"(a[0]), "r"(a[1]), "r"(a[2]), "r"(a[3]), "r"(b[0]), "r"(b[1]));
}

// ---------------- conv kernel smem layout (floats) ----------------
#define OFF_GRID 0
#define OFF_WB1  13824
#define OFF_A3   0
#define OFF_A2   15488
#define OFF_WB2  24000
#define OFF_WB3  15488
#define OFF_BIAS 26304
#define CONV_SMEM_FLOATS 26432   // 105728 B -> 2 CTAs/SM

__global__ void __launch_bounds__(256, 2) conv_kernel(
    const int* __restrict__ positions, const void* __restrict__ umask,
    const int* __restrict__ tile_type, const int* __restrict__ rpos,
    const void* __restrict__ rmask, const float* __restrict__ reward,
    const float* __restrict__ emb_tile, const float* __restrict__ emb_unit,
    const float* __restrict__ w1, const float* __restrict__ b1,
    const float* __restrict__ w2, const float* __restrict__ b2,
    const float* __restrict__ w3, const float* __restrict__ b3) {
    extern __shared__ float sm[];
    int tid = threadIdx.x, bs = blockIdx.x;
    float* grid = sm + OFF_GRID;
    float* wb1  = sm + OFF_WB1;
    float* sb   = sm + OFF_BIAS;   // b1[0:16) b2[16:48) b3[48:112)

    for (int i = tid; i < 1536; i += 256) wb1[i] = w1[i];
    {
        uint2* wB2 = (uint2*)(sm + OFF_WB2);
        for (int i = tid; i < 32 * 32; i += 256) {
            int r = i >> 5, n = i & 31;
            int d = r >> 3, ci2 = r & 7;
            float e = w2[(d * 16 + 2 * ci2) * 32 + n];
            float o = w2[(d * 16 + 2 * ci2 + 1) * 32 + n];
            unsigned h, l; split_bf(e, o, h, l);
            wB2[r * 36 + n] = make_uint2(h, l);
        }
    }
    if (tid < 16) sb[tid] = b1[tid];
    else if (tid < 48) sb[tid] = b2[tid - 16];
    else if (tid < 112) sb[tid] = b3[tid - 48];

    for (int i = tid; i < 19 * 576; i += 256) grid[4 * 576 + i] = 0.f;
    float rw = reward[bs];
    for (int p = tid; p < 576; p += 256) {
        int tt = tile_type[bs * 576 + p] * 4;
        grid[p] = emb_tile[tt];
        grid[576 + p] = emb_tile[tt + 1];
        grid[1152 + p] = emb_tile[tt + 2];
        grid[1728 + p] = emb_tile[tt + 3];
        grid[23 * 576 + p] = rw;
    }
    __syncthreads();
    if (tid < 32) {
        int mode = detect_bool_mode((const unsigned char*)umask);
        if (get_mask(umask, bs * 32 + tid, mode)) {
            int t = tid >> 4, u = tid & 15;
            int pb = (bs * 32 + tid) * 2;
            int y = positions[pb], x = positions[pb + 1];
            int cell = y * 24 + x;
            atomicAdd(&grid[(4 + t) * 576 + cell], 0.0625f);
#pragma unroll
            for (int e = 0; e < 8; e++)
                atomicAdd(&grid[(6 + t * 8 + e) * 576 + cell], emb_unit[u * 8 + e]);
        }
    } else if (tid < 38) {
        int r = tid - 32;
        int mode = detect_bool_mode((const unsigned char*)rmask);
        if (get_mask(rmask, bs * 6 + r, mode)) {
            int pb = (bs * 6 + r) * 2;
            int y = rpos[pb], x = rpos[pb + 1];
            atomicAdd(&grid[22 * 576 + y * 24 + x], 1.0f);
        }
    }
    __syncthreads();

    // ---- conv1: FFMA 24->16ch, 24x24 -> 23x23 (529) ----
    {
        uint2* sA2 = (uint2*)(sm + OFF_A2);
        if (tid < 133) {
            int p[4], base[4]; bool val[4];
#pragma unroll
            for (int j = 0; j < 4; j++) {
                p[j] = tid + j * 133;
                val[j] = (p[j] < 529);
                int pc = val[j] ? p[j] : 0;
                int y = pc / 23;
                base[j] = y * 24 + (pc - y * 23);
            }
            float acc[4][16];
#pragma unroll
            for (int j = 0; j < 4; j++)
#pragma unroll
                for (int q = 0; q < 16; q++) acc[j][q] = 0.f;
#pragma unroll
            for (int d = 0; d < 4; d++) {
                int off = (d >> 1) * 24 + (d & 1);
#pragma unroll 8
                for (int ci = 0; ci < 24; ci++) {
                    float v0 = grid[ci * 576 + base[0] + off];
                    float v1 = grid[ci * 576 + base[1] + off];
                    float v2 = grid[ci * 576 + base[2] + off];
                    float v3 = grid[ci * 576 + base[3] + off];
                    const float4* wq = (const float4*)(wb1 + (d * 24 + ci) * 16);
                    float4 wv[4] = {wq[0], wq[1], wq[2], wq[3]};
#pragma unroll
                    for (int q = 0; q < 4; q++) {
                        acc[0][q * 4 + 0] += v0 * wv[q].x; acc[0][q * 4 + 1] += v0 * wv[q].y;
                        acc[0][q * 4 + 2] += v0 * wv[q].z; acc[0][q * 4 + 3] += v0 * wv[q].w;
                        acc[1][q * 4 + 0] += v1 * wv[q].x; acc[1][q * 4 + 1] += v1 * wv[q].y;
                        acc[1][q * 4 + 2] += v1 * wv[q].z; acc[1][q * 4 + 3] += v1 * wv[q].w;
                        acc[2][q * 4 + 0] += v2 * wv[q].x; acc[2][q * 4 + 1] += v2 * wv[q].y;
                        acc[2][q * 4 + 2] += v2 * wv[q].z; acc[2][q * 4 + 3] += v2 * wv[q].w;
                        acc[3][q * 4 + 0] += v3 * wv[q].x; acc[3][q * 4 + 1] += v3 * wv[q].y;
                        acc[3][q * 4 + 2] += v3 * wv[q].z; acc[3][q * 4 + 3] += v3 * wv[q].w;
                    }
                }
            }
#pragma unroll
            for (int j = 0; j < 4; j++) {
                if (!val[j]) continue;
#pragma unroll
                for (int q2 = 0; q2 < 8; q2++) {
                    float e = fmaxf(acc[j][2 * q2] + sb[2 * q2], 0.f);
                    float o = fmaxf(acc[j][2 * q2 + 1] + sb[2 * q2 + 1], 0.f);
                    unsigned h, l; split_bf(e, o, h, l);
                    sA2[q2 * 532 + p[j]] = make_uint2(h, l);
                }
            }
        }
    }
    __syncthreads();

    int wid = tid >> 5, lane = tid & 31;
    int grp = lane >> 2, tig = lane & 3;
    int wm = wid & 3, wn = wid >> 2;

    // ---- conv2: MMA 16->32ch, 23x23 -> 22x22 (484) ----
    {
        const uint2* sA2 = (const uint2*)(sm + OFF_A2);
        const uint2* wB2 = (const uint2*)(sm + OFF_WB2);
        float acc2[8][2][4];
#pragma unroll
        for (int mt = 0; mt < 8; mt++)
#pragma unroll
            for (int ni = 0; ni < 2; ni++)
#pragma unroll
                for (int q = 0; q < 4; q++) acc2[mt][ni][q] = 0.f;
        int i0[8], i1[8];
#pragma unroll
        for (int mt = 0; mt < 8; mt++) {
            int tile = wm + mt * 4;
            int p0 = tile * 16 + grp, p1 = p0 + 8;
            int q0 = (p0 < 484) ? p0 : 0; i0[mt] = q0 + q0 / 22;
            int q1 = (p1 < 484) ? p1 : 0; i1[mt] = q1 + q1 / 22;
        }
#pragma unroll 1
        for (int d = 0; d < 4; d++) {
            int off = (d >> 1) * 23 + (d & 1);
            unsigned bh[2][2], bl[2][2];
#pragma unroll
            for (int ni = 0; ni < 2; ni++) {
                int nb = wn * 16 + ni * 8 + grp;
                uint2 bv0 = wB2[(d * 8 + tig) * 36 + nb];
                uint2 bv1 = wB2[(d * 8 + tig + 4) * 36 + nb];
                bh[ni][0] = bv0.x; bh[ni][1] = bv1.x;
                bl[ni][0] = bv0.y; bl[ni][1] = bv1.y;
            }
#pragma unroll
            for (int mt = 0; mt < 8; mt++) {
                if (wm + mt * 4 < 31) {
                    uint2 v00 = sA2[tig * 532 + i0[mt] + off];
                    uint2 v01 = sA2[tig * 532 + i1[mt] + off];
                    uint2 v10 = sA2[(tig + 4) * 532 + i0[mt] + off];
                    uint2 v11 = sA2[(tig + 4) * 532 + i1[mt] + off];
                    unsigned ah[4] = {v00.x, v01.x, v10.x, v11.x};
                    unsigned al[4] = {v00.y, v01.y, v10.y, v11.y};
#pragma unroll
                    for (int ni = 0; ni < 2; ni++) {
                        mma_bf16(acc2[mt][ni], al, bh[ni]);
                        mma_bf16(acc2[mt][ni], ah, bl[ni]);
                        mma_bf16(acc2[mt][ni], ah, bh[ni]);
                    }
                }
            }
        }
        uint2* sA3 = (uint2*)(sm + OFF_A3);
        const float* b2s = sb + 16;
#pragma unroll
        for (int mt = 0; mt < 8; mt++) {
            int tile = wm + mt * 4;
            if (tile < 31) {
                int p0 = tile * 16 + grp, p1 = p0 + 8;
#pragma unroll
                for (int ni = 0; ni < 2; ni++) {
                    int c0 = wn * 16 + ni * 8 + 2 * tig;
                    float be = b2s[c0], bo = b2s[c0 + 1];
                    int c2 = c0 >> 1;
                    if (p0 < 484) {
                        unsigned h, l;
                        split_bf(fmaxf(acc2[mt][ni][0] + be, 0.f),
                                 fmaxf(acc2[mt][ni][1] + bo, 0.f), h, l);
                        sA3[c2 * 484 + p0] = make_uint2(h, l);
                    }
                    if (p1 < 484) {
                        unsigned h, l;
                        split_bf(fmaxf(acc2[mt][ni][2] + be, 0.f),
                                 fmaxf(acc2[mt][ni][3] + bo, 0.f), h, l);
                        sA3[c2 * 484 + p1] = make_uint2(h, l);
                    }
                }
            }
        }
    }
    __syncthreads();

    {
        uint2* wB3 = (uint2*)(sm + OFF_WB3);
        for (int i = tid; i < 64 * 64; i += 256) {
            int r = i >> 6, n = i & 63;
            int d = r >> 4, ci2 = r & 15;
            float e = w3[(d * 32 + 2 * ci2) * 64 + n];
            float o = w3[(d * 32 + 2 * ci2 + 1) * 64 + n];
            unsigned h, l; split_bf(e, o, h, l);
            wB3[r * 68 + n] = make_uint2(h, l);
        }
    }
    __syncthreads();

    // ---- conv3: MMA 32->64ch, 22x22 -> 21x21 (441), 2 n-passes ----
    {
        const uint2* sA3 = (const uint2*)(sm + OFF_A3);
        const uint2* wB3 = (const uint2*)(sm + OFF_WB3);
        const float* b3s = sb + 48;
        float* go = g_feat + (size_t)bs * FEAT_D_;
        int i0[7], i1[7];
#pragma unroll
        for (int mt = 0; mt < 7; mt++) {
            int p0 = (wm + mt * 4) * 16 + grp, p1 = p0 + 8;
            int q0 = (p0 < 441) ? p0 : 0; i0[mt] = q0 + q0 / 21;
            int q1 = (p1 < 441) ? p1 : 0; i1[mt] = q1 + q1 / 21;
        }
#pragma unroll 1
        for (int pass = 0; pass < 2; pass++) {
            int n0 = wn * 32 + pass * 16;
            float acc3[7][2][4];
#pragma unroll
            for (int mt = 0; mt < 7; mt++)
#pragma unroll
                for (int ni = 0; ni < 2; ni++)
#pragma unroll
                    for (int q = 0; q < 4; q++) acc3[mt][ni][q] = 0.f;
#pragma unroll 1
            for (int dk = 0; dk < 8; dk++) {
                int d = dk >> 1, h8 = dk & 1;
                int off = (d >> 1) * 22 + (d & 1);
                int kb = h8 * 8;
                unsigned bh[2][2], bl[2][2];
#pragma unroll
                for (int ni = 0; ni < 2; ni++) {
                    int nb = n0 + ni * 8 + grp;
                    uint2 bv0 = wB3[(d * 16 + kb + tig) * 68 + nb];
                    uint2 bv1 = wB3[(d * 16 + kb + tig + 4) * 68 + nb];
                    bh[ni][0] = bv0.x; bh[ni][1] = bv1.x;
                    bl[ni][0] = bv0.y; bl[ni][1] = bv1.y;
                }
#pragma unroll
                for (int mt = 0; mt < 7; mt++) {
                    int a0 = (kb + tig) * 484 + i0[mt] + off;
                    int a1 = (kb + tig) * 484 + i1[mt] + off;
                    uint2 v00 = sA3[a0];
                    uint2 v01 = sA3[a1];
                    uint2 v10 = sA3[a0 + 4 * 484];
                    uint2 v11 = sA3[a1 + 4 * 484];
                    unsigned ah[4] = {v00.x, v01.x, v10.x, v11.x};
                    unsigned al[4] = {v00.y, v01.y, v10.y, v11.y};
#pragma unroll
                    for (int ni = 0; ni < 2; ni++) {
                        mma_bf16(acc3[mt][ni], al, bh[ni]);
                        mma_bf16(acc3[mt][ni], ah, bl[ni]);
                        mma_bf16(acc3[mt][ni], ah, bh[ni]);
                    }
                }
            }
#pragma unroll
            for (int mt = 0; mt < 7; mt++) {
                int p0 = (wm + mt * 4) * 16 + grp, p1 = p0 + 8;
#pragma unroll
                for (int ni = 0; ni < 2; ni++) {
                    int c0 = n0 + ni * 8 + 2 * tig;
                    float be = b3s[c0], bo = b3s[c0 + 1];
                    if (p0 < 441) {
                        float2 v = make_float2(fmaxf(acc3[mt][ni][0] + be, 0.f),
                                               fmaxf(acc3[mt][ni][1] + bo, 0.f));
                        *(float2*)&go[p0 * 64 + c0] = v;
                    }
                    if (p1 < 441) {
                        float2 v = make_float2(fmaxf(acc3[mt][ni][2] + be, 0.f),
                                               fmaxf(acc3[mt][ni][3] + bo, 0.f));
                        *(float2*)&go[p1 * 64 + c0] = v;
                    }
                }
            }
        }
    }
}

// ---------------- 3-term split-bf16 GEMM, BN=192 (A read from DRAM exactly once) ----------------
// grid (64, 1, SPLITK). 8 warps: 2m x 4n; warp tile 32 x 48 (2mi x 6ni).
#define APAD 68    // uint2 stride ≡ 4 (mod 16)
#define BPAD 196   // uint2 stride ≡ 4 (mod 16)

__global__ void __launch_bounds__(256) gemm_bf16_kernel(const float* __restrict__ Bmat) {
    __shared__ uint2 A2s[8][APAD];
    __shared__ uint2 B2s[8][BPAD];
    const int K = FEAT_D_;
    int tid = threadIdx.x;
    int m0 = blockIdx.x * 64;
    int kz = blockIdx.z;
    int kbeg = kz * KSPLIT_LEN;

    int warp = tid >> 5, lane = tid & 31;
    int wm = (warp & 1) * 32;
    int wn = (warp >> 1) * 48;
    int grp = lane >> 2, tig = lane & 3;

    int lr = tid >> 2;            // 0..63
    int lkq = (tid & 3) * 4;      // 0,4,8,12
    int k2 = lkq >> 1;            // 0,2,4,6

    const float* A = g_feat;
    const float* Bp = Bmat;

    float4 pa = *(const float4*)&A[(size_t)(m0 + lr) * K + kbeg + lkq];
    float4 pb0 = *(const float4*)&Bp[(size_t)(lr) * K + kbeg + lkq];
    float4 pb1 = *(const float4*)&Bp[(size_t)(lr + 64) * K + kbeg + lkq];
    float4 pb2 = *(const float4*)&Bp[(size_t)(lr + 128) * K + kbeg + lkq];

    float acc[2][6][4];
#pragma unroll
    for (int i = 0; i < 2; i++)
#pragma unroll
        for (int j = 0; j < 6; j++)
#pragma unroll
            for (int q = 0; q < 4; q++) acc[i][j][q] = 0.f;

    const int NIT = KSPLIT_LEN / 16;  // 441
    for (int it = 0; it < NIT; it++) {
        {
            unsigned h, l;
            split_bf(pa.x, pa.y, h, l);  A2s[k2 + 0][lr] = make_uint2(h, l);
            split_bf(pa.z, pa.w, h, l);  A2s[k2 + 1][lr] = make_uint2(h, l);
            split_bf(pb0.x, pb0.y, h, l); B2s[k2 + 0][lr] = make_uint2(h, l);
            split_bf(pb0.z, pb0.w, h, l); B2s[k2 + 1][lr] = make_uint2(h, l);
            split_bf(pb1.x, pb1.y, h, l); B2s[k2 + 0][lr + 64] = make_uint2(h, l);
            split_bf(pb1.z, pb1.w, h, l); B2s[k2 + 1][lr + 64] = make_uint2(h, l);
            split_bf(pb2.x, pb2.y, h, l); B2s[k2 + 0][lr + 128] = make_uint2(h, l);
            split_bf(pb2.z, pb2.w, h, l); B2s[k2 + 1][lr + 128] = make_uint2(h, l);
        }
        __syncthreads();
        if (it + 1 < NIT) {
            int kn = kbeg + (it + 1) * 16;
            pa  = *(const float4*)&A[(size_t)(m0 + lr) * K + kn + lkq];
            pb0 = *(const float4*)&Bp[(size_t)(lr) * K + kn + lkq];
            pb1 = *(const float4*)&Bp[(size_t)(lr + 64) * K + kn + lkq];
            pb2 = *(const float4*)&Bp[(size_t)(lr + 128) * K + kn + lkq];
        }
        {
            unsigned afh[2][4], afl[2][4];
#pragma unroll
            for (int mi = 0; mi < 2; mi++) {
                int mb = wm + mi * 16 + grp;
                uint2 a00 = A2s[tig][mb];
                uint2 a01 = A2s[tig][mb + 8];
                uint2 a10 = A2s[tig + 4][mb];
                uint2 a11 = A2s[tig + 4][mb + 8];
                afh[mi][0] = a00.x; afh[mi][1] = a01.x; afh[mi][2] = a10.x; afh[mi][3] = a11.x;
                afl[mi][0] = a00.y; afl[mi][1] = a01.y; afl[mi][2] = a10.y; afl[mi][3] = a11.y;
            }
#pragma unroll
            for (int ni = 0; ni < 6; ni++) {
                int nb = wn + ni * 8 + grp;
                uint2 b0 = B2s[tig][nb];
                uint2 b1 = B2s[tig + 4][nb];
                unsigned bfh[2] = {b0.x, b1.x};
                unsigned bfl[2] = {b0.y, b1.y};
#pragma unroll
                for (int mi = 0; mi < 2; mi++) {
                    mma_bf16(acc[mi][ni], afl[mi], bfh);
                    mma_bf16(acc[mi][ni], afh[mi], bfl);
                    mma_bf16(acc[mi][ni], afh[mi], bfh);
                }
            }
        }
        __syncthreads();
    }

    float* out = g_part + (size_t)kz * PART_STRIDE;
#pragma unroll
    for (int mi = 0; mi < 2; mi++) {
#pragma unroll
        for (int ni = 0; ni < 6; ni++) {
            int col = wn + ni * 8 + 2 * tig;
            int row0 = m0 + wm + mi * 16 + grp;
            float2 v0 = make_float2(acc[mi][ni][0], acc[mi][ni][1]);
            float2 v1 = make_float2(acc[mi][ni][2], acc[mi][ni][3]);
            *(float2*)&out[(size_t)row0 * 192 + col] = v0;
            *(float2*)&out[(size_t)(row0 + 8) * 192 + col] = v1;
        }
    }
}

// ---------------- GRU scan (fused split-K reduce + bias) ----------------
__global__ void __launch_bounds__(192) gru_kernel(const float* __restrict__ h0,
                                                  const float* __restrict__ Wh,
                                                  const float* __restrict__ bn,
                                                  const float* __restrict__ bi,
                                                  float* __restrict__ hfinal) {
    int b = blockIdx.x, g = threadIdx.x;
    __shared__ float h[64];
    __shared__ float hg[192];
    __shared__ float sig[192];
    float w[64];
#pragma unroll
    for (int k = 0; k < 64; k++) w[k] = Wh[g * 64 + k];
    float bnv = (g < 64) ? bn[g] : 0.f;
    float biv = bi[g];
    if (g < 64) h[g] = h0[b * 64 + g];
    const float* P = g_part;
    int idx = (b * 128 + 0) * 192 + g;
    float q0 = P[idx], q1 = P[PART_STRIDE + idx];
    float q2 = P[2 * PART_STRIDE + idx], q3 = P[3 * PART_STRIDE + idx];
    __syncthreads();
    for (int t = 0; t < 128; t++) {
        float a0 = 0.f, a1 = 0.f, a2 = 0.f, a3 = 0.f;
#pragma unroll
        for (int k = 0; k < 64; k += 4) {
            a0 += w[k] * h[k];
            a1 += w[k + 1] * h[k + 1];
            a2 += w[k + 2] * h[k + 2];
            a3 += w[k + 3] * h[k + 3];
        }
        hg[g] = (a0 + a1) + (a2 + a3);
        sig[g] = biv + q0 + q1 + q2 + q3;
        __syncthreads();
        int tn = (t < 127) ? t + 1 : 127;
        int idxn = (b * 128 + tn) * 192 + g;
        q0 = P[idxn]; q1 = P[PART_STRIDE + idxn];
        q2 = P[2 * PART_STRIDE + idxn]; q3 = P[3 * PART_STRIDE + idxn];
        if (g < 64) {
            float rr = 1.f / (1.f + __expf(-(sig[g] + hg[g])));
            float zz = 1.f / (1.f + __expf(-(sig[64 + g] + hg[64 + g])));
            float nn = tanhf(sig[128 + g] + rr * (hg[128 + g] + bnv));
            float hn = (1.f - zz) * nn + zz * h[g];
            h[g] = hn;
            g_allh[(b * 128 + t) * 64 + g] = hn;
        }
        __syncthreads();
    }
    if (g < 64) hfinal[b * 64 + g] = h[g];
}

// ---------------- heads (256 CTAs x 16 rows) ----------------
#define HEADS_SMEM_BYTES (14816 * 4)
__global__ void __launch_bounds__(128) heads_kernel(
    const float* __restrict__ Wa1, const float* __restrict__ ba1,
    const float* __restrict__ Wa2, const float* __restrict__ ba2,
    const float* __restrict__ Wc1, const float* __restrict__ bc1,
    const float* __restrict__ Wc2, const float* __restrict__ bc2,
    float* __restrict__ logits, float* __restrict__ values) {
    extern __shared__ float s[];
    float* sWa1 = s;
    float* sWc1 = s + 4096;
    float* sWa2 = s + 8192;
    float* sWc2 = s + 14336;
    float* sba1 = s + 14400;
    float* sbc1 = s + 14464;
    float* sba2 = s + 14528;
    float* sh   = s + 14624;
    float* sa   = s + 14688;
    float* sc   = s + 14752;
    int tid = threadIdx.x;
    for (int i = tid; i < 4096; i += 128) { sWa1[i] = Wa1[i]; sWc1[i] = Wc1[i]; }
    for (int i = tid; i < 6144; i += 128) sWa2[i] = Wa2[i];
    if (tid < 64) { sWc2[tid] = Wc2[tid]; sba1[tid] = ba1[tid]; sbc1[tid] = bc1[tid]; }
    if (tid < 96) sba2[tid] = ba2[tid];
    float bc2v = bc2[0];
    __syncthreads();
    for (int r = blockIdx.x * 16; r < blockIdx.x * 16 + 16; r++) {
        if (tid < 64) sh[tid] = g_allh[r * 64 + tid];
        __syncthreads();
        {
            int j = tid & 63;
            const float* W = (tid < 64) ? sWa1 : sWc1;
            float acc = 0.f;
#pragma unroll
            for (int i = 0; i < 64; i++) acc += sh[i] * W[i * 64 + j];
            float v = tanhf(acc + ((tid < 64) ? sba1[j] : sbc1[j]));
            if (tid < 64) sa[j] = v; else sc[j] = v;
        }
        __syncthreads();
        if (tid < 96) {
            float acc = sba2[tid];
#pragma unroll
            for (int j = 0; j < 64; j++) acc += sa[j] * sWa2[j * 96 + tid];
            logits[r * 96 + tid] = acc;
        } else if (tid == 96) {
            float acc = bc2v;
#pragma unroll
            for (int j = 0; j < 64; j++) acc += sc[j] * sWc2[j];
            values[r] = acc;
        }
        __syncthreads();
    }
}

// ---------------- launch ----------------
extern "C" void kernel_launch(void* const* d_in, const int* in_sizes, int n_in,
                              void* d_out, int out_size) {
    const int*   positions = (const int*)d_in[0];
    const void*  umask     = d_in[1];
    const int*   tile      = (const int*)d_in[2];
    const int*   rpos      = (const int*)d_in[3];
    const void*  rmask     = d_in[4];
    const float* reward    = (const float*)d_in[5];
    const float* hidden    = (const float*)d_in[6];
    const float* emb_tile  = (const float*)d_in[7];
    const float* emb_unit  = (const float*)d_in[8];
    const float* w1 = (const float*)d_in[9];
    const float* b1 = (const float*)d_in[10];
    const float* w2 = (const float*)d_in[11];
    const float* b2 = (const float*)d_in[12];
    const float* w3 = (const float*)d_in[13];
    const float* b3 = (const float*)d_in[14];
    const float* Wi = (const float*)d_in[15];
    const float* Wh = (const float*)d_in[16];
    const float* bi = (const float*)d_in[17];
    const float* bn = (const float*)d_in[18];
    const float* Wa1 = (const float*)d_in[19];
    const float* ba1 = (const float*)d_in[20];
    const float* Wa2 = (const float*)d_in[21];
    const float* ba2 = (const float*)d_in[22];
    const float* Wc1 = (const float*)d_in[23];
    const float* bc1 = (const float*)d_in[24];
    const float* Wc2 = (const float*)d_in[25];
    const float* bc2 = (const float*)d_in[26];
    float* out = (float*)d_out;

    float* out_logits = out;
    float* out_values = out + 393216;
    float* out_hidden = out + 397312;

    const int conv_smem = CONV_SMEM_FLOATS * (int)sizeof(float);
    cudaFuncSetAttribute(conv_kernel, cudaFuncAttributeMaxDynamicSharedMemorySize, conv_smem);
    cudaFuncSetAttribute(heads_kernel, cudaFuncAttributeMaxDynamicSharedMemorySize, HEADS_SMEM_BYTES);

    conv_kernel<<<BS_, 256, conv_smem>>>(positions, umask, tile, rpos, rmask, reward,
                                         emb_tile, emb_unit, w1, b1, w2, b2, w3, b3);
    gemm_bf16_kernel<<<dim3(64, 1, SPLITK), 256>>>(Wi);
    gru_kernel<<<32, 192>>>(hidden, Wh, bn, bi, out_hidden);
    heads_kernel<<<256, 128, HEADS_SMEM_BYTES>>>(Wa1, ba1, Wa2, ba2, Wc1, bc1, Wc2, bc2,
                                                 out_logits, out_values);
}

// round 13
// speedup vs baseline: 2.3274x; 1.1248x over previous
#include <cuda_runtime.h>
#include <cuda_fp16.h>
#include <stdint.h>
#include <math.h>

#define B_ 32
#define S_ 128
#define BS_ 4096
#define FEAT_D_ 28224
#define SPLITK 4
#define KSPLIT_LEN (FEAT_D_ / SPLITK)   // 7056
#define PART_STRIDE (BS_ * 192)

// ---------------- scratch ----------------
__device__ float g_feat[(size_t)BS_ * FEAT_D_];
__device__ float g_part[(size_t)SPLITK * BS_ * 192];
__device__ float g_allh[BS_ * 64];

// ---------------- bool-mask dtype detection ----------------
__device__ __forceinline__ int detect_bool_mode(const unsigned char* p) {
    bool any80 = false, nz = false;
    for (int i = 0; i < 256; i++) {
        unsigned char v = p[i];
        int m = i & 3;
        if (m == 2 && v == 0x80) any80 = true;
        if (m != 0 && v != 0) nz = true;
    }
    if (!nz) return 1;
    if (any80) return 2;
    return 0;
}
__device__ __forceinline__ bool get_mask(const void* p, int i, int mode) {
    if (mode == 1) return ((const int*)p)[i] != 0;
    if (mode == 2) return ((const float*)p)[i] != 0.0f;
    return ((const unsigned char*)p)[i] != 0;
}

// ---------------- bf16 split helpers (GEMM) ----------------
__device__ __forceinline__ unsigned pack_bf16x2(float e, float o) {
    unsigned r;
    asm("cvt.rn.bf16x2.f32 %0, %1, %2;" : "=r"(r) : "f"(o), "f"(e));  // lo=e, hi=o
    return r;
}
__device__ __forceinline__ void split_bf(float e, float o, unsigned& h, unsigned& l) {
    h = pack_bf16x2(e, o);
    float he = __uint_as_float(h << 16);
    float ho = __uint_as_float(h & 0xffff0000u);
    l = pack_bf16x2(e - he, o - ho);
}
__device__ __forceinline__ void mma_bf16(float* acc, const unsigned* a, const unsigned* b) {
    asm volatile(
        "mma.sync.aligned.m16n8k16.row.col.f32.bf16.bf16.f32 "
        "{%0,%1,%2,%3}, {%4,%5,%6,%7}, {%8,%9}, {%0,%1,%2,%3};"
        : "+f"(acc[0]), "+f"(acc[1]), "+f"(acc[2]), "+f"(acc[3])
        : "r"(a[0]), "r"(a[1]), "r"(a[2]), "r"(a[3]), "r"(b[0]), "r"(b[1]));
}

// ---------------- fp16 helpers (conv) ----------------
__device__ __forceinline__ unsigned pack_f16x2(float e, float o) {
    unsigned r;
    asm("cvt.rn.f16x2.f32 %0, %1, %2;" : "=r"(r) : "f"(o), "f"(e));  // lo=e, hi=o
    return r;
}
__device__ __forceinline__ void split_f16(float e, float o, unsigned& h, unsigned& l) {
    h = pack_f16x2(e, o);
    __half2 hh = *reinterpret_cast<__half2*>(&h);
    float he = __low2float(hh), ho = __high2float(hh);
    l = pack_f16x2(e - he, o - ho);
}
__device__ __forceinline__ void mma_f16(float* acc, const unsigned* a, const unsigned* b) {
    asm volatile(
        "mma.sync.aligned.m16n8k16.row.col.f32.f16.f16.f32 "
        "{%0,%1,%2,%3}, {%4,%5,%6,%7}, {%8,%9}, {%0,%1,%2,%3};"
        : "+f"(acc[0]), "+f"(acc[1]), "+f"(acc[2]), "+f"(acc[3])
        : "r"(a[0]), "r"(a[1]), "r"(a[2]), "r"(a[3]), "r"(b[0]), "r"(b[1]));
}

// ---------------- conv kernel smem layout (floats) ----------------
// Region1 [0..15488): grid 13824 + wb1 1536  ==> overlaid by sA3 (uint2 16x484)
// Region2 [15488..25280): sA2 (uint2 8x532 = 8512 fl) + wB2h (u32 32x40 = 1280 fl)
//                         ==> overlaid by wB3h (u32 64x72 = 4608 fl)
// bias [25280..25408)
#define OFF_GRID 0
#define OFF_WB1  13824
#define OFF_A3   0
#define OFF_A2   15488
#define OFF_WB2  24000
#define OFF_WB3  15488
#define OFF_BIAS 25280
#define CONV_SMEM_FLOATS 25408   // 101632 B -> 2 CTAs/SM

__global__ void __launch_bounds__(256, 2) conv_kernel(
    const int* __restrict__ positions, const void* __restrict__ umask,
    const int* __restrict__ tile_type, const int* __restrict__ rpos,
    const void* __restrict__ rmask, const float* __restrict__ reward,
    const float* __restrict__ emb_tile, const float* __restrict__ emb_unit,
    const float* __restrict__ w1, const float* __restrict__ b1,
    const float* __restrict__ w2, const float* __restrict__ b2,
    const float* __restrict__ w3, const float* __restrict__ b3) {
    extern __shared__ float sm[];
    int tid = threadIdx.x, bs = blockIdx.x;
    float* grid = sm + OFF_GRID;
    float* wb1  = sm + OFF_WB1;
    float* sb   = sm + OFF_BIAS;   // b1[0:16) b2[16:48) b3[48:112)

    for (int i = tid; i < 1536; i += 256) wb1[i] = w1[i];
    {   // wB2: single fp16x2 pairs over cin (pair = adjacent channels along K)
        unsigned* wB2h = (unsigned*)(sm + OFF_WB2);
        for (int i = tid; i < 32 * 32; i += 256) {
            int r = i >> 5, n = i & 31;
            int d = r >> 3, ci2 = r & 7;
            float e = w2[(d * 16 + 2 * ci2) * 32 + n];
            float o = w2[(d * 16 + 2 * ci2 + 1) * 32 + n];
            wB2h[r * 40 + n] = pack_f16x2(e, o);
        }
    }
    if (tid < 16) sb[tid] = b1[tid];
    else if (tid < 48) sb[tid] = b2[tid - 16];
    else if (tid < 112) sb[tid] = b3[tid - 48];

    for (int i = tid; i < 19 * 576; i += 256) grid[4 * 576 + i] = 0.f;
    float rw = reward[bs];
    for (int p = tid; p < 576; p += 256) {
        int tt = tile_type[bs * 576 + p] * 4;
        grid[p] = emb_tile[tt];
        grid[576 + p] = emb_tile[tt + 1];
        grid[1152 + p] = emb_tile[tt + 2];
        grid[1728 + p] = emb_tile[tt + 3];
        grid[23 * 576 + p] = rw;
    }
    __syncthreads();
    if (tid < 32) {
        int mode = detect_bool_mode((const unsigned char*)umask);
        if (get_mask(umask, bs * 32 + tid, mode)) {
            int t = tid >> 4, u = tid & 15;
            int pb = (bs * 32 + tid) * 2;
            int y = positions[pb], x = positions[pb + 1];
            int cell = y * 24 + x;
            atomicAdd(&grid[(4 + t) * 576 + cell], 0.0625f);
#pragma unroll
            for (int e = 0; e < 8; e++)
                atomicAdd(&grid[(6 + t * 8 + e) * 576 + cell], emb_unit[u * 8 + e]);
        }
    } else if (tid < 38) {
        int r = tid - 32;
        int mode = detect_bool_mode((const unsigned char*)rmask);
        if (get_mask(rmask, bs * 6 + r, mode)) {
            int pb = (bs * 6 + r) * 2;
            int y = rpos[pb], x = rpos[pb + 1];
            atomicAdd(&grid[22 * 576 + y * 24 + x], 1.0f);
        }
    }
    __syncthreads();

    // ---- conv1: FFMA 24->16ch, 24x24 -> 23x23 (529). 3 pixels x 177 threads ----
    {
        uint2* sA2 = (uint2*)(sm + OFF_A2);
        if (tid < 177) {
            int p[3], base[3]; bool val[3];
#pragma unroll
            for (int j = 0; j < 3; j++) {
                p[j] = tid + j * 177;
                val[j] = (p[j] < 529);
                int pc = val[j] ? p[j] : 0;
                int y = pc / 23;
                base[j] = y * 24 + (pc - y * 23);
            }
            float acc[3][16];
#pragma unroll
            for (int j = 0; j < 3; j++)
#pragma unroll
                for (int q = 0; q < 16; q++) acc[j][q] = 0.f;
#pragma unroll
            for (int d = 0; d < 4; d++) {
                int off = (d >> 1) * 24 + (d & 1);
#pragma unroll 8
                for (int ci = 0; ci < 24; ci++) {
                    float v0 = grid[ci * 576 + base[0] + off];
                    float v1 = grid[ci * 576 + base[1] + off];
                    float v2 = grid[ci * 576 + base[2] + off];
                    const float4* wq = (const float4*)(wb1 + (d * 24 + ci) * 16);
                    float4 wv[4] = {wq[0], wq[1], wq[2], wq[3]};
#pragma unroll
                    for (int q = 0; q < 4; q++) {
                        acc[0][q * 4 + 0] += v0 * wv[q].x; acc[0][q * 4 + 1] += v0 * wv[q].y;
                        acc[0][q * 4 + 2] += v0 * wv[q].z; acc[0][q * 4 + 3] += v0 * wv[q].w;
                        acc[1][q * 4 + 0] += v1 * wv[q].x; acc[1][q * 4 + 1] += v1 * wv[q].y;
                        acc[1][q * 4 + 2] += v1 * wv[q].z; acc[1][q * 4 + 3] += v1 * wv[q].w;
                        acc[2][q * 4 + 0] += v2 * wv[q].x; acc[2][q * 4 + 1] += v2 * wv[q].y;
                        acc[2][q * 4 + 2] += v2 * wv[q].z; acc[2][q * 4 + 3] += v2 * wv[q].w;
                    }
                }
            }
#pragma unroll
            for (int j = 0; j < 3; j++) {
                if (!val[j]) continue;
#pragma unroll
                for (int q2 = 0; q2 < 8; q2++) {
                    float e = fmaxf(acc[j][2 * q2] + sb[2 * q2], 0.f);
                    float o = fmaxf(acc[j][2 * q2 + 1] + sb[2 * q2 + 1], 0.f);
                    unsigned h, l; split_f16(e, o, h, l);
                    sA2[q2 * 532 + p[j]] = make_uint2(h, l);
                }
            }
        }
    }
    __syncthreads();

    int wid = tid >> 5, lane = tid & 31;
    int grp = lane >> 2, tig = lane & 3;
    int wm = wid & 3, wn = wid >> 2;

    // ---- conv2: fp16 MMA 16->32ch, 23x23 -> 22x22 (484). 2 MMAs per logical ----
    {
        const uint2* sA2 = (const uint2*)(sm + OFF_A2);
        const unsigned* wB2h = (const unsigned*)(sm + OFF_WB2);
        float acc2[8][2][4];
#pragma unroll
        for (int mt = 0; mt < 8; mt++)
#pragma unroll
            for (int ni = 0; ni < 2; ni++)
#pragma unroll
                for (int q = 0; q < 4; q++) acc2[mt][ni][q] = 0.f;
        int i0[8], i1[8];
#pragma unroll
        for (int mt = 0; mt < 8; mt++) {
            int tile = wm + mt * 4;
            int p0 = tile * 16 + grp, p1 = p0 + 8;
            int q0 = (p0 < 484) ? p0 : 0; i0[mt] = q0 + q0 / 22;
            int q1 = (p1 < 484) ? p1 : 0; i1[mt] = q1 + q1 / 22;
        }
#pragma unroll 1
        for (int d = 0; d < 4; d++) {
            int off = (d >> 1) * 23 + (d & 1);
            unsigned bh[2][2];
#pragma unroll
            for (int ni = 0; ni < 2; ni++) {
                int nb = wn * 16 + ni * 8 + grp;
                bh[ni][0] = wB2h[(d * 8 + tig) * 40 + nb];
                bh[ni][1] = wB2h[(d * 8 + tig + 4) * 40 + nb];
            }
#pragma unroll
            for (int mt = 0; mt < 8; mt++) {
                if (wm + mt * 4 < 31) {
                    uint2 v00 = sA2[tig * 532 + i0[mt] + off];
                    uint2 v01 = sA2[tig * 532 + i1[mt] + off];
                    uint2 v10 = sA2[(tig + 4) * 532 + i0[mt] + off];
                    uint2 v11 = sA2[(tig + 4) * 532 + i1[mt] + off];
                    unsigned ah[4] = {v00.x, v01.x, v10.x, v11.x};
                    unsigned al[4] = {v00.y, v01.y, v10.y, v11.y};
#pragma unroll
                    for (int ni = 0; ni < 2; ni++) {
                        mma_f16(acc2[mt][ni], al, bh[ni]);
                        mma_f16(acc2[mt][ni], ah, bh[ni]);
                    }
                }
            }
        }
        uint2* sA3 = (uint2*)(sm + OFF_A3);
        const float* b2s = sb + 16;
#pragma unroll
        for (int mt = 0; mt < 8; mt++) {
            int tile = wm + mt * 4;
            if (tile < 31) {
                int p0 = tile * 16 + grp, p1 = p0 + 8;
#pragma unroll
                for (int ni = 0; ni < 2; ni++) {
                    int c0 = wn * 16 + ni * 8 + 2 * tig;
                    float be = b2s[c0], bo = b2s[c0 + 1];
                    int c2 = c0 >> 1;
                    if (p0 < 484) {
                        unsigned h, l;
                        split_f16(fmaxf(acc2[mt][ni][0] + be, 0.f),
                                  fmaxf(acc2[mt][ni][1] + bo, 0.f), h, l);
                        sA3[c2 * 484 + p0] = make_uint2(h, l);
                    }
                    if (p1 < 484) {
                        unsigned h, l;
                        split_f16(fmaxf(acc2[mt][ni][2] + be, 0.f),
                                  fmaxf(acc2[mt][ni][3] + bo, 0.f), h, l);
                        sA3[c2 * 484 + p1] = make_uint2(h, l);
                    }
                }
            }
        }
    }
    __syncthreads();

    // ---- load wB3h (single fp16 pairs; overlays sA2/wB2 — dead) ----
    {
        unsigned* wB3h = (unsigned*)(sm + OFF_WB3);
        for (int i = tid; i < 64 * 64; i += 256) {
            int r = i >> 6, n = i & 63;
            int d = r >> 4, ci2 = r & 15;
            float e = w3[(d * 32 + 2 * ci2) * 64 + n];
            float o = w3[(d * 32 + 2 * ci2 + 1) * 64 + n];
            wB3h[r * 72 + n] = pack_f16x2(e, o);
        }
    }
    __syncthreads();

    // ---- conv3: fp16 MMA 32->64ch, 22x22 -> 21x21 (441), 2 n-passes ----
    {
        const uint2* sA3 = (const uint2*)(sm + OFF_A3);
        const unsigned* wB3h = (const unsigned*)(sm + OFF_WB3);
        const float* b3s = sb + 48;
        float* go = g_feat + (size_t)bs * FEAT_D_;
        int i0[7], i1[7];
#pragma unroll
        for (int mt = 0; mt < 7; mt++) {
            int p0 = (wm + mt * 4) * 16 + grp, p1 = p0 + 8;
            int q0 = (p0 < 441) ? p0 : 0; i0[mt] = q0 + q0 / 21;
            int q1 = (p1 < 441) ? p1 : 0; i1[mt] = q1 + q1 / 21;
        }
#pragma unroll 1
        for (int pass = 0; pass < 2; pass++) {
            int n0 = wn * 32 + pass * 16;
            float acc3[7][2][4];
#pragma unroll
            for (int mt = 0; mt < 7; mt++)
#pragma unroll
                for (int ni = 0; ni < 2; ni++)
#pragma unroll
                    for (int q = 0; q < 4; q++) acc3[mt][ni][q] = 0.f;
#pragma unroll 1
            for (int dk = 0; dk < 8; dk++) {
                int d = dk >> 1, h8 = dk & 1;
                int off = (d >> 1) * 22 + (d & 1);
                int kb = h8 * 8;
                unsigned bh[2][2];
#pragma unroll
                for (int ni = 0; ni < 2; ni++) {
                    int nb = n0 + ni * 8 + grp;
                    bh[ni][0] = wB3h[(d * 16 + kb + tig) * 72 + nb];
                    bh[ni][1] = wB3h[(d * 16 + kb + tig + 4) * 72 + nb];
                }
#pragma unroll
                for (int mt = 0; mt < 7; mt++) {
                    int a0 = (kb + tig) * 484 + i0[mt] + off;
                    int a1 = (kb + tig) * 484 + i1[mt] + off;
                    uint2 v00 = sA3[a0];
                    uint2 v01 = sA3[a1];
                    uint2 v10 = sA3[a0 + 4 * 484];
                    uint2 v11 = sA3[a1 + 4 * 484];
                    unsigned ah[4] = {v00.x, v01.x, v10.x, v11.x};
                    unsigned al[4] = {v00.y, v01.y, v10.y, v11.y};
#pragma unroll
                    for (int ni = 0; ni < 2; ni++) {
                        mma_f16(acc3[mt][ni], al, bh[ni]);
                        mma_f16(acc3[mt][ni], ah, bh[ni]);
                    }
                }
            }
#pragma unroll
            for (int mt = 0; mt < 7; mt++) {
                int p0 = (wm + mt * 4) * 16 + grp, p1 = p0 + 8;
#pragma unroll
                for (int ni = 0; ni < 2; ni++) {
                    int c0 = n0 + ni * 8 + 2 * tig;
                    float be = b3s[c0], bo = b3s[c0 + 1];
                    if (p0 < 441) {
                        float2 v = make_float2(fmaxf(acc3[mt][ni][0] + be, 0.f),
                                               fmaxf(acc3[mt][ni][1] + bo, 0.f));
                        *(float2*)&go[p0 * 64 + c0] = v;
                    }
                    if (p1 < 441) {
                        float2 v = make_float2(fmaxf(acc3[mt][ni][2] + be, 0.f),
                                               fmaxf(acc3[mt][ni][3] + bo, 0.f));
                        *(float2*)&go[p1 * 64 + c0] = v;
                    }
                }
            }
        }
    }
}

// ---------------- 3-term split-bf16 GEMM, BN=192 (R10, unchanged) ----------------
#define APAD 68
#define BPAD 196

__global__ void __launch_bounds__(256) gemm_bf16_kernel(const float* __restrict__ Bmat) {
    __shared__ uint2 A2s[8][APAD];
    __shared__ uint2 B2s[8][BPAD];
    const int K = FEAT_D_;
    int tid = threadIdx.x;
    int m0 = blockIdx.x * 64;
    int kz = blockIdx.z;
    int kbeg = kz * KSPLIT_LEN;

    int warp = tid >> 5, lane = tid & 31;
    int wm = (warp & 1) * 32;
    int wn = (warp >> 1) * 48;
    int grp = lane >> 2, tig = lane & 3;

    int lr = tid >> 2;
    int lkq = (tid & 3) * 4;
    int k2 = lkq >> 1;

    const float* A = g_feat;
    const float* Bp = Bmat;

    float4 pa = *(const float4*)&A[(size_t)(m0 + lr) * K + kbeg + lkq];
    float4 pb0 = *(const float4*)&Bp[(size_t)(lr) * K + kbeg + lkq];
    float4 pb1 = *(const float4*)&Bp[(size_t)(lr + 64) * K + kbeg + lkq];
    float4 pb2 = *(const float4*)&Bp[(size_t)(lr + 128) * K + kbeg + lkq];

    float acc[2][6][4];
#pragma unroll
    for (int i = 0; i < 2; i++)
#pragma unroll
        for (int j = 0; j < 6; j++)
#pragma unroll
            for (int q = 0; q < 4; q++) acc[i][j][q] = 0.f;

    const int NIT = KSPLIT_LEN / 16;
    for (int it = 0; it < NIT; it++) {
        {
            unsigned h, l;
            split_bf(pa.x, pa.y, h, l);  A2s[k2 + 0][lr] = make_uint2(h, l);
            split_bf(pa.z, pa.w, h, l);  A2s[k2 + 1][lr] = make_uint2(h, l);
            split_bf(pb0.x, pb0.y, h, l); B2s[k2 + 0][lr] = make_uint2(h, l);
            split_bf(pb0.z, pb0.w, h, l); B2s[k2 + 1][lr] = make_uint2(h, l);
            split_bf(pb1.x, pb1.y, h, l); B2s[k2 + 0][lr + 64] = make_uint2(h, l);
            split_bf(pb1.z, pb1.w, h, l); B2s[k2 + 1][lr + 64] = make_uint2(h, l);
            split_bf(pb2.x, pb2.y, h, l); B2s[k2 + 0][lr + 128] = make_uint2(h, l);
            split_bf(pb2.z, pb2.w, h, l); B2s[k2 + 1][lr + 128] = make_uint2(h, l);
        }
        __syncthreads();
        if (it + 1 < NIT) {
            int kn = kbeg + (it + 1) * 16;
            pa  = *(const float4*)&A[(size_t)(m0 + lr) * K + kn + lkq];
            pb0 = *(const float4*)&Bp[(size_t)(lr) * K + kn + lkq];
            pb1 = *(const float4*)&Bp[(size_t)(lr + 64) * K + kn + lkq];
            pb2 = *(const float4*)&Bp[(size_t)(lr + 128) * K + kn + lkq];
        }
        {
            unsigned afh[2][4], afl[2][4];
#pragma unroll
            for (int mi = 0; mi < 2; mi++) {
                int mb = wm + mi * 16 + grp;
                uint2 a00 = A2s[tig][mb];
                uint2 a01 = A2s[tig][mb + 8];
                uint2 a10 = A2s[tig + 4][mb];
                uint2 a11 = A2s[tig + 4][mb + 8];
                afh[mi][0] = a00.x; afh[mi][1] = a01.x; afh[mi][2] = a10.x; afh[mi][3] = a11.x;
                afl[mi][0] = a00.y; afl[mi][1] = a01.y; afl[mi][2] = a10.y; afl[mi][3] = a11.y;
            }
#pragma unroll
            for (int ni = 0; ni < 6; ni++) {
                int nb = wn + ni * 8 + grp;
                uint2 b0 = B2s[tig][nb];
                uint2 b1 = B2s[tig + 4][nb];
                unsigned bfh[2] = {b0.x, b1.x};
                unsigned bfl[2] = {b0.y, b1.y};
#pragma unroll
                for (int mi = 0; mi < 2; mi++) {
                    mma_bf16(acc[mi][ni], afl[mi], bfh);
                    mma_bf16(acc[mi][ni], afh[mi], bfl);
                    mma_bf16(acc[mi][ni], afh[mi], bfh);
                }
            }
        }
        __syncthreads();
    }

    float* out = g_part + (size_t)kz * PART_STRIDE;
#pragma unroll
    for (int mi = 0; mi < 2; mi++) {
#pragma unroll
        for (int ni = 0; ni < 6; ni++) {
            int col = wn + ni * 8 + 2 * tig;
            int row0 = m0 + wm + mi * 16 + grp;
            float2 v0 = make_float2(acc[mi][ni][0], acc[mi][ni][1]);
            float2 v1 = make_float2(acc[mi][ni][2], acc[mi][ni][3]);
            *(float2*)&out[(size_t)row0 * 192 + col] = v0;
            *(float2*)&out[(size_t)(row0 + 8) * 192 + col] = v1;
        }
    }
}

// ---------------- GRU scan (fused split-K reduce + bias) ----------------
__global__ void __launch_bounds__(192) gru_kernel(const float* __restrict__ h0,
                                                  const float* __restrict__ Wh,
                                                  const float* __restrict__ bn,
                                                  const float* __restrict__ bi,
                                                  float* __restrict__ hfinal) {
    int b = blockIdx.x, g = threadIdx.x;
    __shared__ float h[64];
    __shared__ float hg[192];
    __shared__ float sig[192];
    float w[64];
#pragma unroll
    for (int k = 0; k < 64; k++) w[k] = Wh[g * 64 + k];
    float bnv = (g < 64) ? bn[g] : 0.f;
    float biv = bi[g];
    if (g < 64) h[g] = h0[b * 64 + g];
    const float* P = g_part;
    int idx = (b * 128 + 0) * 192 + g;
    float q0 = P[idx], q1 = P[PART_STRIDE + idx];
    float q2 = P[2 * PART_STRIDE + idx], q3 = P[3 * PART_STRIDE + idx];
    __syncthreads();
    for (int t = 0; t < 128; t++) {
        float a0 = 0.f, a1 = 0.f, a2 = 0.f, a3 = 0.f;
#pragma unroll
        for (int k = 0; k < 64; k += 4) {
            a0 += w[k] * h[k];
            a1 += w[k + 1] * h[k + 1];
            a2 += w[k + 2] * h[k + 2];
            a3 += w[k + 3] * h[k + 3];
        }
        hg[g] = (a0 + a1) + (a2 + a3);
        sig[g] = biv + q0 + q1 + q2 + q3;
        __syncthreads();
        int tn = (t < 127) ? t + 1 : 127;
        int idxn = (b * 128 + tn) * 192 + g;
        q0 = P[idxn]; q1 = P[PART_STRIDE + idxn];
        q2 = P[2 * PART_STRIDE + idxn]; q3 = P[3 * PART_STRIDE + idxn];
        if (g < 64) {
            float rr = 1.f / (1.f + __expf(-(sig[g] + hg[g])));
            float zz = 1.f / (1.f + __expf(-(sig[64 + g] + hg[64 + g])));
            float nn = tanhf(sig[128 + g] + rr * (hg[128 + g] + bnv));
            float hn = (1.f - zz) * nn + zz * h[g];
            h[g] = hn;
            g_allh[(b * 128 + t) * 64 + g] = hn;
        }
        __syncthreads();
    }
    if (g < 64) hfinal[b * 64 + g] = h[g];
}

// ---------------- heads (256 CTAs x 16 rows) ----------------
#define HEADS_SMEM_BYTES (14816 * 4)
__global__ void __launch_bounds__(128) heads_kernel(
    const float* __restrict__ Wa1, const float* __restrict__ ba1,
    const float* __restrict__ Wa2, const float* __restrict__ ba2,
    const float* __restrict__ Wc1, const float* __restrict__ bc1,
    const float* __restrict__ Wc2, const float* __restrict__ bc2,
    float* __restrict__ logits, float* __restrict__ values) {
    extern __shared__ float s[];
    float* sWa1 = s;
    float* sWc1 = s + 4096;
    float* sWa2 = s + 8192;
    float* sWc2 = s + 14336;
    float* sba1 = s + 14400;
    float* sbc1 = s + 14464;
    float* sba2 = s + 14528;
    float* sh   = s + 14624;
    float* sa   = s + 14688;
    float* sc   = s + 14752;
    int tid = threadIdx.x;
    for (int i = tid; i < 4096; i += 128) { sWa1[i] = Wa1[i]; sWc1[i] = Wc1[i]; }
    for (int i = tid; i < 6144; i += 128) sWa2[i] = Wa2[i];
    if (tid < 64) { sWc2[tid] = Wc2[tid]; sba1[tid] = ba1[tid]; sbc1[tid] = bc1[tid]; }
    if (tid < 96) sba2[tid] = ba2[tid];
    float bc2v = bc2[0];
    __syncthreads();
    for (int r = blockIdx.x * 16; r < blockIdx.x * 16 + 16; r++) {
        if (tid < 64) sh[tid] = g_allh[r * 64 + tid];
        __syncthreads();
        {
            int j = tid & 63;
            const float* W = (tid < 64) ? sWa1 : sWc1;
            float acc = 0.f;
#pragma unroll
            for (int i = 0; i < 64; i++) acc += sh[i] * W[i * 64 + j];
            float v = tanhf(acc + ((tid < 64) ? sba1[j] : sbc1[j]));
            if (tid < 64) sa[j] = v; else sc[j] = v;
        }
        __syncthreads();
        if (tid < 96) {
            float acc = sba2[tid];
#pragma unroll
            for (int j = 0; j < 64; j++) acc += sa[j] * sWa2[j * 96 + tid];
            logits[r * 96 + tid] = acc;
        } else if (tid == 96) {
            float acc = bc2v;
#pragma unroll
            for (int j = 0; j < 64; j++) acc += sc[j] * sWc2[j];
            values[r] = acc;
        }
        __syncthreads();
    }
}

// ---------------- launch ----------------
extern "C" void kernel_launch(void* const* d_in, const int* in_sizes, int n_in,
                              void* d_out, int out_size) {
    const int*   positions = (const int*)d_in[0];
    const void*  umask     = d_in[1];
    const int*   tile      = (const int*)d_in[2];
    const int*   rpos      = (const int*)d_in[3];
    const void*  rmask     = d_in[4];
    const float* reward    = (const float*)d_in[5];
    const float* hidden    = (const float*)d_in[6];
    const float* emb_tile  = (const float*)d_in[7];
    const float* emb_unit  = (const float*)d_in[8];
    const float* w1 = (const float*)d_in[9];
    const float* b1 = (const float*)d_in[10];
    const float* w2 = (const float*)d_in[11];
    const float* b2 = (const float*)d_in[12];
    const float* w3 = (const float*)d_in[13];
    const float* b3 = (const float*)d_in[14];
    const float* Wi = (const float*)d_in[15];
    const float* Wh = (const float*)d_in[16];
    const float* bi = (const float*)d_in[17];
    const float* bn = (const float*)d_in[18];
    const float* Wa1 = (const float*)d_in[19];
    const float* ba1 = (const float*)d_in[20];
    const float* Wa2 = (const float*)d_in[21];
    const float* ba2 = (const float*)d_in[22];
    const float* Wc1 = (const float*)d_in[23];
    const float* bc1 = (const float*)d_in[24];
    const float* Wc2 = (const float*)d_in[25];
    const float* bc2 = (const float*)d_in[26];
    float* out = (float*)d_out;

    float* out_logits = out;
    float* out_values = out + 393216;
    float* out_hidden = out + 397312;

    const int conv_smem = CONV_SMEM_FLOATS * (int)sizeof(float);
    cudaFuncSetAttribute(conv_kernel, cudaFuncAttributeMaxDynamicSharedMemorySize, conv_smem);
    cudaFuncSetAttribute(heads_kernel, cudaFuncAttributeMaxDynamicSharedMemorySize, HEADS_SMEM_BYTES);

    conv_kernel<<<BS_, 256, conv_smem>>>(positions, umask, tile, rpos, rmask, reward,
                                         emb_tile, emb_unit, w1, b1, w2, b2, w3, b3);
    gemm_bf16_kernel<<<dim3(64, 1, SPLITK), 256>>>(Wi);
    gru_kernel<<<32, 192>>>(hidden, Wh, bn, bi, out_hidden);
    heads_kernel<<<256, 128, HEADS_SMEM_BYTES>>>(Wa1, ba1, Wa2, ba2, Wc1, bc1, Wc2, bc2,
                                                 out_logits, out_values);
}

// round 14
// speedup vs baseline: 2.6738x; 1.1489x over previous
#include <cuda_runtime.h>
#include <cuda_fp16.h>
#include <stdint.h>
#include <math.h>

#define B_ 32
#define S_ 128
#define BS_ 4096
#define FEAT_D_ 28224
#define SPLITK 4
#define KSPLIT_LEN (FEAT_D_ / SPLITK)   // 7056
#define PART_STRIDE (BS_ * 192)

// ---------------- scratch ----------------
__device__ __half g_feat[(size_t)BS_ * FEAT_D_];   // fp16 conv output (231 MB)
__device__ float g_part[(size_t)SPLITK * BS_ * 192];
__device__ float g_allh[BS_ * 64];

// ---------------- bool-mask dtype detection ----------------
__device__ __forceinline__ int detect_bool_mode(const unsigned char* p) {
    bool any80 = false, nz = false;
    for (int i = 0; i < 256; i++) {
        unsigned char v = p[i];
        int m = i & 3;
        if (m == 2 && v == 0x80) any80 = true;
        if (m != 0 && v != 0) nz = true;
    }
    if (!nz) return 1;
    if (any80) return 2;
    return 0;
}
__device__ __forceinline__ bool get_mask(const void* p, int i, int mode) {
    if (mode == 1) return ((const int*)p)[i] != 0;
    if (mode == 2) return ((const float*)p)[i] != 0.0f;
    return ((const unsigned char*)p)[i] != 0;
}

// ---------------- fp16 helpers ----------------
__device__ __forceinline__ unsigned pack_f16x2(float e, float o) {
    unsigned r;
    asm("cvt.rn.f16x2.f32 %0, %1, %2;" : "=r"(r) : "f"(o), "f"(e));  // lo=e, hi=o
    return r;
}
__device__ __forceinline__ void split_f16(float e, float o, unsigned& h, unsigned& l) {
    h = pack_f16x2(e, o);
    __half2 hh = *reinterpret_cast<__half2*>(&h);
    float he = __low2float(hh), ho = __high2float(hh);
    l = pack_f16x2(e - he, o - ho);
}
__device__ __forceinline__ void mma_f16(float* acc, const unsigned* a, const unsigned* b) {
    asm volatile(
        "mma.sync.aligned.m16n8k16.row.col.f32.f16.f16.f32 "
        "{%0,%1,%2,%3}, {%4,%5,%6,%7}, {%8,%9}, {%0,%1,%2,%3};"
        : "+f"(acc[0]), "+f"(acc[1]), "+f"(acc[2]), "+f"(acc[3])
        : "r"(a[0]), "r"(a[1]), "r"(a[2]), "r"(a[3]), "r"(b[0]), "r"(b[1]));
}

// ---------------- conv kernel smem layout (floats) ----------------
#define OFF_GRID 0
#define OFF_WB1  13824
#define OFF_A3   0
#define OFF_A2   15488
#define OFF_WB2  24000
#define OFF_WB3  15488
#define OFF_BIAS 25280
#define CONV_SMEM_FLOATS 25408   // 101632 B -> 2 CTAs/SM

__global__ void __launch_bounds__(256, 2) conv_kernel(
    const int* __restrict__ positions, const void* __restrict__ umask,
    const int* __restrict__ tile_type, const int* __restrict__ rpos,
    const void* __restrict__ rmask, const float* __restrict__ reward,
    const float* __restrict__ emb_tile, const float* __restrict__ emb_unit,
    const float* __restrict__ w1, const float* __restrict__ b1,
    const float* __restrict__ w2, const float* __restrict__ b2,
    const float* __restrict__ w3, const float* __restrict__ b3) {
    extern __shared__ float sm[];
    int tid = threadIdx.x, bs = blockIdx.x;
    float* grid = sm + OFF_GRID;
    float* wb1  = sm + OFF_WB1;
    float* sb   = sm + OFF_BIAS;   // b1[0:16) b2[16:48) b3[48:112)

    for (int i = tid; i < 1536; i += 256) wb1[i] = w1[i];
    {   // wB2: single fp16x2 pairs over cin
        unsigned* wB2h = (unsigned*)(sm + OFF_WB2);
        for (int i = tid; i < 32 * 32; i += 256) {
            int r = i >> 5, n = i & 31;
            int d = r >> 3, ci2 = r & 7;
            float e = w2[(d * 16 + 2 * ci2) * 32 + n];
            float o = w2[(d * 16 + 2 * ci2 + 1) * 32 + n];
            wB2h[r * 40 + n] = pack_f16x2(e, o);
        }
    }
    if (tid < 16) sb[tid] = b1[tid];
    else if (tid < 48) sb[tid] = b2[tid - 16];
    else if (tid < 112) sb[tid] = b3[tid - 48];

    for (int i = tid; i < 19 * 576; i += 256) grid[4 * 576 + i] = 0.f;
    float rw = reward[bs];
    for (int p = tid; p < 576; p += 256) {
        int tt = tile_type[bs * 576 + p] * 4;
        grid[p] = emb_tile[tt];
        grid[576 + p] = emb_tile[tt + 1];
        grid[1152 + p] = emb_tile[tt + 2];
        grid[1728 + p] = emb_tile[tt + 3];
        grid[23 * 576 + p] = rw;
    }
    __syncthreads();
    if (tid < 32) {
        int mode = detect_bool_mode((const unsigned char*)umask);
        if (get_mask(umask, bs * 32 + tid, mode)) {
            int t = tid >> 4, u = tid & 15;
            int pb = (bs * 32 + tid) * 2;
            int y = positions[pb], x = positions[pb + 1];
            int cell = y * 24 + x;
            atomicAdd(&grid[(4 + t) * 576 + cell], 0.0625f);
#pragma unroll
            for (int e = 0; e < 8; e++)
                atomicAdd(&grid[(6 + t * 8 + e) * 576 + cell], emb_unit[u * 8 + e]);
        }
    } else if (tid < 38) {
        int r = tid - 32;
        int mode = detect_bool_mode((const unsigned char*)rmask);
        if (get_mask(rmask, bs * 6 + r, mode)) {
            int pb = (bs * 6 + r) * 2;
            int y = rpos[pb], x = rpos[pb + 1];
            atomicAdd(&grid[22 * 576 + y * 24 + x], 1.0f);
        }
    }
    __syncthreads();

    // ---- conv1: FFMA 24->16ch, 24x24 -> 23x23 (529). 3 pixels x 177 threads ----
    {
        uint2* sA2 = (uint2*)(sm + OFF_A2);
        if (tid < 177) {
            int p[3], base[3]; bool val[3];
#pragma unroll
            for (int j = 0; j < 3; j++) {
                p[j] = tid + j * 177;
                val[j] = (p[j] < 529);
                int pc = val[j] ? p[j] : 0;
                int y = pc / 23;
                base[j] = y * 24 + (pc - y * 23);
            }
            float acc[3][16];
#pragma unroll
            for (int j = 0; j < 3; j++)
#pragma unroll
                for (int q = 0; q < 16; q++) acc[j][q] = 0.f;
#pragma unroll
            for (int d = 0; d < 4; d++) {
                int off = (d >> 1) * 24 + (d & 1);
#pragma unroll 8
                for (int ci = 0; ci < 24; ci++) {
                    float v0 = grid[ci * 576 + base[0] + off];
                    float v1 = grid[ci * 576 + base[1] + off];
                    float v2 = grid[ci * 576 + base[2] + off];
                    const float4* wq = (const float4*)(wb1 + (d * 24 + ci) * 16);
                    float4 wv[4] = {wq[0], wq[1], wq[2], wq[3]};
#pragma unroll
                    for (int q = 0; q < 4; q++) {
                        acc[0][q * 4 + 0] += v0 * wv[q].x; acc[0][q * 4 + 1] += v0 * wv[q].y;
                        acc[0][q * 4 + 2] += v0 * wv[q].z; acc[0][q * 4 + 3] += v0 * wv[q].w;
                        acc[1][q * 4 + 0] += v1 * wv[q].x; acc[1][q * 4 + 1] += v1 * wv[q].y;
                        acc[1][q * 4 + 2] += v1 * wv[q].z; acc[1][q * 4 + 3] += v1 * wv[q].w;
                        acc[2][q * 4 + 0] += v2 * wv[q].x; acc[2][q * 4 + 1] += v2 * wv[q].y;
                        acc[2][q * 4 + 2] += v2 * wv[q].z; acc[2][q * 4 + 3] += v2 * wv[q].w;
                    }
                }
            }
#pragma unroll
            for (int j = 0; j < 3; j++) {
                if (!val[j]) continue;
#pragma unroll
                for (int q2 = 0; q2 < 8; q2++) {
                    float e = fmaxf(acc[j][2 * q2] + sb[2 * q2], 0.f);
                    float o = fmaxf(acc[j][2 * q2 + 1] + sb[2 * q2 + 1], 0.f);
                    unsigned h, l; split_f16(e, o, h, l);
                    sA2[q2 * 532 + p[j]] = make_uint2(h, l);
                }
            }
        }
    }
    __syncthreads();

    int wid = tid >> 5, lane = tid & 31;
    int grp = lane >> 2, tig = lane & 3;
    int wm = wid & 3, wn = wid >> 2;

    // ---- conv2: fp16 MMA 16->32ch, 23x23 -> 22x22 (484). 2 MMAs per logical ----
    {
        const uint2* sA2 = (const uint2*)(sm + OFF_A2);
        const unsigned* wB2h = (const unsigned*)(sm + OFF_WB2);
        float acc2[8][2][4];
#pragma unroll
        for (int mt = 0; mt < 8; mt++)
#pragma unroll
            for (int ni = 0; ni < 2; ni++)
#pragma unroll
                for (int q = 0; q < 4; q++) acc2[mt][ni][q] = 0.f;
        int i0[8], i1[8];
#pragma unroll
        for (int mt = 0; mt < 8; mt++) {
            int tile = wm + mt * 4;
            int p0 = tile * 16 + grp, p1 = p0 + 8;
            int q0 = (p0 < 484) ? p0 : 0; i0[mt] = q0 + q0 / 22;
            int q1 = (p1 < 484) ? p1 : 0; i1[mt] = q1 + q1 / 22;
        }
#pragma unroll 1
        for (int d = 0; d < 4; d++) {
            int off = (d >> 1) * 23 + (d & 1);
            unsigned bh[2][2];
#pragma unroll
            for (int ni = 0; ni < 2; ni++) {
                int nb = wn * 16 + ni * 8 + grp;
                bh[ni][0] = wB2h[(d * 8 + tig) * 40 + nb];
                bh[ni][1] = wB2h[(d * 8 + tig + 4) * 40 + nb];
            }
#pragma unroll
            for (int mt = 0; mt < 8; mt++) {
                if (wm + mt * 4 < 31) {
                    uint2 v00 = sA2[tig * 532 + i0[mt] + off];
                    uint2 v01 = sA2[tig * 532 + i1[mt] + off];
                    uint2 v10 = sA2[(tig + 4) * 532 + i0[mt] + off];
                    uint2 v11 = sA2[(tig + 4) * 532 + i1[mt] + off];
                    unsigned ah[4] = {v00.x, v01.x, v10.x, v11.x};
                    unsigned al[4] = {v00.y, v01.y, v10.y, v11.y};
#pragma unroll
                    for (int ni = 0; ni < 2; ni++) {
                        mma_f16(acc2[mt][ni], al, bh[ni]);
                        mma_f16(acc2[mt][ni], ah, bh[ni]);
                    }
                }
            }
        }
        uint2* sA3 = (uint2*)(sm + OFF_A3);
        const float* b2s = sb + 16;
#pragma unroll
        for (int mt = 0; mt < 8; mt++) {
            int tile = wm + mt * 4;
            if (tile < 31) {
                int p0 = tile * 16 + grp, p1 = p0 + 8;
#pragma unroll
                for (int ni = 0; ni < 2; ni++) {
                    int c0 = wn * 16 + ni * 8 + 2 * tig;
                    float be = b2s[c0], bo = b2s[c0 + 1];
                    int c2 = c0 >> 1;
                    if (p0 < 484) {
                        unsigned h, l;
                        split_f16(fmaxf(acc2[mt][ni][0] + be, 0.f),
                                  fmaxf(acc2[mt][ni][1] + bo, 0.f), h, l);
                        sA3[c2 * 484 + p0] = make_uint2(h, l);
                    }
                    if (p1 < 484) {
                        unsigned h, l;
                        split_f16(fmaxf(acc2[mt][ni][2] + be, 0.f),
                                  fmaxf(acc2[mt][ni][3] + bo, 0.f), h, l);
                        sA3[c2 * 484 + p1] = make_uint2(h, l);
                    }
                }
            }
        }
    }
    __syncthreads();

    // ---- load wB3h (single fp16 pairs; overlays sA2/wB2 — dead) ----
    {
        unsigned* wB3h = (unsigned*)(sm + OFF_WB3);
        for (int i = tid; i < 64 * 64; i += 256) {
            int r = i >> 6, n = i & 63;
            int d = r >> 4, ci2 = r & 15;
            float e = w3[(d * 32 + 2 * ci2) * 64 + n];
            float o = w3[(d * 32 + 2 * ci2 + 1) * 64 + n];
            wB3h[r * 72 + n] = pack_f16x2(e, o);
        }
    }
    __syncthreads();

    // ---- conv3: fp16 MMA 32->64ch, 22x22 -> 21x21 (441), 2 n-passes; fp16 epilogue ----
    {
        const uint2* sA3 = (const uint2*)(sm + OFF_A3);
        const unsigned* wB3h = (const unsigned*)(sm + OFF_WB3);
        const float* b3s = sb + 48;
        __half* go = g_feat + (size_t)bs * FEAT_D_;
        int i0[7], i1[7];
#pragma unroll
        for (int mt = 0; mt < 7; mt++) {
            int p0 = (wm + mt * 4) * 16 + grp, p1 = p0 + 8;
            int q0 = (p0 < 441) ? p0 : 0; i0[mt] = q0 + q0 / 21;
            int q1 = (p1 < 441) ? p1 : 0; i1[mt] = q1 + q1 / 21;
        }
#pragma unroll 1
        for (int pass = 0; pass < 2; pass++) {
            int n0 = wn * 32 + pass * 16;
            float acc3[7][2][4];
#pragma unroll
            for (int mt = 0; mt < 7; mt++)
#pragma unroll
                for (int ni = 0; ni < 2; ni++)
#pragma unroll
                    for (int q = 0; q < 4; q++) acc3[mt][ni][q] = 0.f;
#pragma unroll 1
            for (int dk = 0; dk < 8; dk++) {
                int d = dk >> 1, h8 = dk & 1;
                int off = (d >> 1) * 22 + (d & 1);
                int kb = h8 * 8;
                unsigned bh[2][2];
#pragma unroll
                for (int ni = 0; ni < 2; ni++) {
                    int nb = n0 + ni * 8 + grp;
                    bh[ni][0] = wB3h[(d * 16 + kb + tig) * 72 + nb];
                    bh[ni][1] = wB3h[(d * 16 + kb + tig + 4) * 72 + nb];
                }
#pragma unroll
                for (int mt = 0; mt < 7; mt++) {
                    int a0 = (kb + tig) * 484 + i0[mt] + off;
                    int a1 = (kb + tig) * 484 + i1[mt] + off;
                    uint2 v00 = sA3[a0];
                    uint2 v01 = sA3[a1];
                    uint2 v10 = sA3[a0 + 4 * 484];
                    uint2 v11 = sA3[a1 + 4 * 484];
                    unsigned ah[4] = {v00.x, v01.x, v10.x, v11.x};
                    unsigned al[4] = {v00.y, v01.y, v10.y, v11.y};
#pragma unroll
                    for (int ni = 0; ni < 2; ni++) {
                        mma_f16(acc3[mt][ni], al, bh[ni]);
                        mma_f16(acc3[mt][ni], ah, bh[ni]);
                    }
                }
            }
#pragma unroll
            for (int mt = 0; mt < 7; mt++) {
                int p0 = (wm + mt * 4) * 16 + grp, p1 = p0 + 8;
#pragma unroll
                for (int ni = 0; ni < 2; ni++) {
                    int c0 = n0 + ni * 8 + 2 * tig;
                    float be = b3s[c0], bo = b3s[c0 + 1];
                    if (p0 < 441) {
                        unsigned v = pack_f16x2(fmaxf(acc3[mt][ni][0] + be, 0.f),
                                                fmaxf(acc3[mt][ni][1] + bo, 0.f));
                        *(unsigned*)(go + p0 * 64 + c0) = v;
                    }
                    if (p1 < 441) {
                        unsigned v = pack_f16x2(fmaxf(acc3[mt][ni][2] + be, 0.f),
                                                fmaxf(acc3[mt][ni][3] + bo, 0.f));
                        *(unsigned*)(go + p1 * 64 + c0) = v;
                    }
                }
            }
        }
    }
}

// ---------------- fp16 GEMM, BN=192: A single fp16, B = Wi split fp16 hi+lo ----------------
// grid (64, 1, SPLITK). 8 warps: 2m x 4n; warp tile 32 x 48 (2mi x 6ni). 2 MMAs per logical.
#define APAD 76    // u32 stride: (76*tig+grp)%32 distinct for stores and frag loads
#define BPAD 196   // uint2 stride ≡ 4 (mod 16)

__global__ void __launch_bounds__(256) gemm_f16_kernel(const float* __restrict__ Bmat) {
    __shared__ unsigned A1s[8][APAD];
    __shared__ uint2 B2s[8][BPAD];
    const int K = FEAT_D_;
    int tid = threadIdx.x;
    int m0 = blockIdx.x * 64;
    int kz = blockIdx.z;
    int kbeg = kz * KSPLIT_LEN;

    int warp = tid >> 5, lane = tid & 31;
    int wm = (warp & 1) * 32;
    int wn = (warp >> 1) * 48;
    int grp = lane >> 2, tig = lane & 3;

    int lr = tid >> 2;            // 0..63
    int lkq = (tid & 3) * 4;      // 0,4,8,12
    int k2 = lkq >> 1;            // 0,2,4,6

    const __half* A = g_feat;
    const float* Bp = Bmat;

    uint2 pa = *(const uint2*)&A[(size_t)(m0 + lr) * K + kbeg + lkq];
    float4 pb0 = *(const float4*)&Bp[(size_t)(lr) * K + kbeg + lkq];
    float4 pb1 = *(const float4*)&Bp[(size_t)(lr + 64) * K + kbeg + lkq];
    float4 pb2 = *(const float4*)&Bp[(size_t)(lr + 128) * K + kbeg + lkq];

    float acc[2][6][4];
#pragma unroll
    for (int i = 0; i < 2; i++)
#pragma unroll
        for (int j = 0; j < 6; j++)
#pragma unroll
            for (int q = 0; q < 4; q++) acc[i][j][q] = 0.f;

    const int NIT = KSPLIT_LEN / 16;  // 441
    for (int it = 0; it < NIT; it++) {
        {
            A1s[k2 + 0][lr] = pa.x;
            A1s[k2 + 1][lr] = pa.y;
            unsigned h, l;
            split_f16(pb0.x, pb0.y, h, l); B2s[k2 + 0][lr] = make_uint2(h, l);
            split_f16(pb0.z, pb0.w, h, l); B2s[k2 + 1][lr] = make_uint2(h, l);
            split_f16(pb1.x, pb1.y, h, l); B2s[k2 + 0][lr + 64] = make_uint2(h, l);
            split_f16(pb1.z, pb1.w, h, l); B2s[k2 + 1][lr + 64] = make_uint2(h, l);
            split_f16(pb2.x, pb2.y, h, l); B2s[k2 + 0][lr + 128] = make_uint2(h, l);
            split_f16(pb2.z, pb2.w, h, l); B2s[k2 + 1][lr + 128] = make_uint2(h, l);
        }
        __syncthreads();
        if (it + 1 < NIT) {
            int kn = kbeg + (it + 1) * 16;
            pa  = *(const uint2*)&A[(size_t)(m0 + lr) * K + kn + lkq];
            pb0 = *(const float4*)&Bp[(size_t)(lr) * K + kn + lkq];
            pb1 = *(const float4*)&Bp[(size_t)(lr + 64) * K + kn + lkq];
            pb2 = *(const float4*)&Bp[(size_t)(lr + 128) * K + kn + lkq];
        }
        {
            unsigned af[2][4];
#pragma unroll
            for (int mi = 0; mi < 2; mi++) {
                int mb = wm + mi * 16 + grp;
                af[mi][0] = A1s[tig][mb];
                af[mi][1] = A1s[tig][mb + 8];
                af[mi][2] = A1s[tig + 4][mb];
                af[mi][3] = A1s[tig + 4][mb + 8];
            }
#pragma unroll
            for (int ni = 0; ni < 6; ni++) {
                int nb = wn + ni * 8 + grp;
                uint2 b0 = B2s[tig][nb];
                uint2 b1 = B2s[tig + 4][nb];
                unsigned bfh[2] = {b0.x, b1.x};
                unsigned bfl[2] = {b0.y, b1.y};
#pragma unroll
                for (int mi = 0; mi < 2; mi++) {
                    mma_f16(acc[mi][ni], af[mi], bfl);
                    mma_f16(acc[mi][ni], af[mi], bfh);
                }
            }
        }
        __syncthreads();
    }

    float* out = g_part + (size_t)kz * PART_STRIDE;
#pragma unroll
    for (int mi = 0; mi < 2; mi++) {
#pragma unroll
        for (int ni = 0; ni < 6; ni++) {
            int col = wn + ni * 8 + 2 * tig;
            int row0 = m0 + wm + mi * 16 + grp;
            float2 v0 = make_float2(acc[mi][ni][0], acc[mi][ni][1]);
            float2 v1 = make_float2(acc[mi][ni][2], acc[mi][ni][3]);
            *(float2*)&out[(size_t)row0 * 192 + col] = v0;
            *(float2*)&out[(size_t)(row0 + 8) * 192 + col] = v1;
        }
    }
}

// ---------------- GRU scan (fused split-K reduce + bias) ----------------
__global__ void __launch_bounds__(192) gru_kernel(const float* __restrict__ h0,
                                                  const float* __restrict__ Wh,
                                                  const float* __restrict__ bn,
                                                  const float* __restrict__ bi,
                                                  float* __restrict__ hfinal) {
    int b = blockIdx.x, g = threadIdx.x;
    __shared__ float h[64];
    __shared__ float hg[192];
    __shared__ float sig[192];
    float w[64];
#pragma unroll
    for (int k = 0; k < 64; k++) w[k] = Wh[g * 64 + k];
    float bnv = (g < 64) ? bn[g] : 0.f;
    float biv = bi[g];
    if (g < 64) h[g] = h0[b * 64 + g];
    const float* P = g_part;
    int idx = (b * 128 + 0) * 192 + g;
    float q0 = P[idx], q1 = P[PART_STRIDE + idx];
    float q2 = P[2 * PART_STRIDE + idx], q3 = P[3 * PART_STRIDE + idx];
    __syncthreads();
    for (int t = 0; t < 128; t++) {
        float a0 = 0.f, a1 = 0.f, a2 = 0.f, a3 = 0.f;
#pragma unroll
        for (int k = 0; k < 64; k += 4) {
            a0 += w[k] * h[k];
            a1 += w[k + 1] * h[k + 1];
            a2 += w[k + 2] * h[k + 2];
            a3 += w[k + 3] * h[k + 3];
        }
        hg[g] = (a0 + a1) + (a2 + a3);
        sig[g] = biv + q0 + q1 + q2 + q3;
        __syncthreads();
        int tn = (t < 127) ? t + 1 : 127;
        int idxn = (b * 128 + tn) * 192 + g;
        q0 = P[idxn]; q1 = P[PART_STRIDE + idxn];
        q2 = P[2 * PART_STRIDE + idxn]; q3 = P[3 * PART_STRIDE + idxn];
        if (g < 64) {
            float rr = 1.f / (1.f + __expf(-(sig[g] + hg[g])));
            float zz = 1.f / (1.f + __expf(-(sig[64 + g] + hg[64 + g])));
            float nn = tanhf(sig[128 + g] + rr * (hg[128 + g] + bnv));
            float hn = (1.f - zz) * nn + zz * h[g];
            h[g] = hn;
            g_allh[(b * 128 + t) * 64 + g] = hn;
        }
        __syncthreads();
    }
    if (g < 64) hfinal[b * 64 + g] = h[g];
}

// ---------------- heads (256 CTAs x 16 rows) ----------------
#define HEADS_SMEM_BYTES (14816 * 4)
__global__ void __launch_bounds__(128) heads_kernel(
    const float* __restrict__ Wa1, const float* __restrict__ ba1,
    const float* __restrict__ Wa2, const float* __restrict__ ba2,
    const float* __restrict__ Wc1, const float* __restrict__ bc1,
    const float* __restrict__ Wc2, const float* __restrict__ bc2,
    float* __restrict__ logits, float* __restrict__ values) {
    extern __shared__ float s[];
    float* sWa1 = s;
    float* sWc1 = s + 4096;
    float* sWa2 = s + 8192;
    float* sWc2 = s + 14336;
    float* sba1 = s + 14400;
    float* sbc1 = s + 14464;
    float* sba2 = s + 14528;
    float* sh   = s + 14624;
    float* sa   = s + 14688;
    float* sc   = s + 14752;
    int tid = threadIdx.x;
    for (int i = tid; i < 4096; i += 128) { sWa1[i] = Wa1[i]; sWc1[i] = Wc1[i]; }
    for (int i = tid; i < 6144; i += 128) sWa2[i] = Wa2[i];
    if (tid < 64) { sWc2[tid] = Wc2[tid]; sba1[tid] = ba1[tid]; sbc1[tid] = bc1[tid]; }
    if (tid < 96) sba2[tid] = ba2[tid];
    float bc2v = bc2[0];
    __syncthreads();
    for (int r = blockIdx.x * 16; r < blockIdx.x * 16 + 16; r++) {
        if (tid < 64) sh[tid] = g_allh[r * 64 + tid];
        __syncthreads();
        {
            int j = tid & 63;
            const float* W = (tid < 64) ? sWa1 : sWc1;
            float acc = 0.f;
#pragma unroll
            for (int i = 0; i < 64; i++) acc += sh[i] * W[i * 64 + j];
            float v = tanhf(acc + ((tid < 64) ? sba1[j] : sbc1[j]));
            if (tid < 64) sa[j] = v; else sc[j] = v;
        }
        __syncthreads();
        if (tid < 96) {
            float acc = sba2[tid];
#pragma unroll
            for (int j = 0; j < 64; j++) acc += sa[j] * sWa2[j * 96 + tid];
            logits[r * 96 + tid] = acc;
        } else if (tid == 96) {
            float acc = bc2v;
#pragma unroll
            for (int j = 0; j < 64; j++) acc += sc[j] * sWc2[j];
            values[r] = acc;
        }
        __syncthreads();
    }
}

// ---------------- launch ----------------
extern "C" void kernel_launch(void* const* d_in, const int* in_sizes, int n_in,
                              void* d_out, int out_size) {
    const int*   positions = (const int*)d_in[0];
    const void*  umask     = d_in[1];
    const int*   tile      = (const int*)d_in[2];
    const int*   rpos      = (const int*)d_in[3];
    const void*  rmask     = d_in[4];
    const float* reward    = (const float*)d_in[5];
    const float* hidden    = (const float*)d_in[6];
    const float* emb_tile  = (const float*)d_in[7];
    const float* emb_unit  = (const float*)d_in[8];
    const float* w1 = (const float*)d_in[9];
    const float* b1 = (const float*)d_in[10];
    const float* w2 = (const float*)d_in[11];
    const float* b2 = (const float*)d_in[12];
    const float* w3 = (const float*)d_in[13];
    const float* b3 = (const float*)d_in[14];
    const float* Wi = (const float*)d_in[15];
    const float* Wh = (const float*)d_in[16];
    const float* bi = (const float*)d_in[17];
    const float* bn = (const float*)d_in[18];
    const float* Wa1 = (const float*)d_in[19];
    const float* ba1 = (const float*)d_in[20];
    const float* Wa2 = (const float*)d_in[21];
    const float* ba2 = (const float*)d_in[22];
    const float* Wc1 = (const float*)d_in[23];
    const float* bc1 = (const float*)d_in[24];
    const float* Wc2 = (const float*)d_in[25];
    const float* bc2 = (const float*)d_in[26];
    float* out = (float*)d_out;

    float* out_logits = out;
    float* out_values = out + 393216;
    float* out_hidden = out + 397312;

    const int conv_smem = CONV_SMEM_FLOATS * (int)sizeof(float);
    cudaFuncSetAttribute(conv_kernel, cudaFuncAttributeMaxDynamicSharedMemorySize, conv_smem);
    cudaFuncSetAttribute(heads_kernel, cudaFuncAttributeMaxDynamicSharedMemorySize, HEADS_SMEM_BYTES);

    conv_kernel<<<BS_, 256, conv_smem>>>(positions, umask, tile, rpos, rmask, reward,
                                         emb_tile, emb_unit, w1, b1, w2, b2, w3, b3);
    gemm_f16_kernel<<<dim3(64, 1, SPLITK), 256>>>(Wi);
    gru_kernel<<<32, 192>>>(hidden, Wh, bn, bi, out_hidden);
    heads_kernel<<<256, 128, HEADS_SMEM_BYTES>>>(Wa1, ba1, Wa2, ba2, Wc1, bc1, Wc2, bc2,
                                                 out_logits, out_values);
}

// round 16
// speedup vs baseline: 2.8991x; 1.0842x over previous
#include <cuda_runtime.h>
#include <cuda_fp16.h>
#include <stdint.h>
#include <math.h>

#define B_ 32
#define S_ 128
#define BS_ 4096
#define FEAT_D_ 28224
#define SPLITK 4
#define KSPLIT_LEN (FEAT_D_ / SPLITK)   // 7056
#define PART_STRIDE (BS_ * 192)

// ---------------- scratch ----------------
__device__ __half g_feat[(size_t)BS_ * FEAT_D_];   // fp16 conv output (231 MB)
__device__ float g_part[(size_t)SPLITK * BS_ * 192];
__device__ float g_allh[BS_ * 64];

// ---------------- bool-mask dtype detection ----------------
__device__ __forceinline__ int detect_bool_mode(const unsigned char* p) {
    bool any80 = false, nz = false;
    for (int i = 0; i < 256; i++) {
        unsigned char v = p[i];
        int m = i & 3;
        if (m == 2 && v == 0x80) any80 = true;
        if (m != 0 && v != 0) nz = true;
    }
    if (!nz) return 1;
    if (any80) return 2;
    return 0;
}
__device__ __forceinline__ bool get_mask(const void* p, int i, int mode) {
    if (mode == 1) return ((const int*)p)[i] != 0;
    if (mode == 2) return ((const float*)p)[i] != 0.0f;
    return ((const unsigned char*)p)[i] != 0;
}

// ---------------- fp16 helpers ----------------
__device__ __forceinline__ unsigned pack_f16x2(float e, float o) {
    unsigned r;
    asm("cvt.rn.f16x2.f32 %0, %1, %2;" : "=r"(r) : "f"(o), "f"(e));  // lo=e, hi=o
    return r;
}
__device__ __forceinline__ void split_f16(float e, float o, unsigned& h, unsigned& l) {
    h = pack_f16x2(e, o);
    __half2 hh = *reinterpret_cast<__half2*>(&h);
    float he = __low2float(hh), ho = __high2float(hh);
    l = pack_f16x2(e - he, o - ho);
}
__device__ __forceinline__ void mma_f16(float* acc, const unsigned* a, const unsigned* b) {
    asm volatile(
        "mma.sync.aligned.m16n8k16.row.col.f32.f16.f16.f32 "
        "{%0,%1,%2,%3}, {%4,%5,%6,%7}, {%8,%9}, {%0,%1,%2,%3};"
        : "+f"(acc[0]), "+f"(acc[1]), "+f"(acc[2]), "+f"(acc[3])
        : "r"(a[0]), "r"(a[1]), "r"(a[2]), "r"(a[3]), "r"(b[0]), "r"(b[1]));
}

// ---------------- conv kernel smem layout (floats / u32 units) ----------------
// Region1 [0..15360): grid 13824 + wb1 1536  ==> overlaid by sA3 (u32 16x488 = 7808)
// Region2 [15360..20928): sA2 (u32 8x536 = 4288) + wB2 (u32 32x40 = 1280)
//                         ==> overlaid by wB3 (u32 64x72 = 4608)
// bias [20928..21056)
#define OFF_GRID 0
#define OFF_WB1  13824
#define OFF_A3   0
#define OFF_A2   15360
#define OFF_WB2  19648
#define OFF_WB3  15360
#define OFF_BIAS 20928
#define CONV_SMEM_FLOATS 21056   // 84224 B -> 2 CTAs/SM

__global__ void __launch_bounds__(256, 2) conv_kernel(
    const int* __restrict__ positions, const void* __restrict__ umask,
    const int* __restrict__ tile_type, const int* __restrict__ rpos,
    const void* __restrict__ rmask, const float* __restrict__ reward,
    const float* __restrict__ emb_tile, const float* __restrict__ emb_unit,
    const float* __restrict__ w1, const float* __restrict__ b1,
    const float* __restrict__ w2, const float* __restrict__ b2,
    const float* __restrict__ w3, const float* __restrict__ b3) {
    extern __shared__ float sm[];
    int tid = threadIdx.x, bs = blockIdx.x;
    float* grid = sm + OFF_GRID;
    float* wb1  = sm + OFF_WB1;
    float* sb   = sm + OFF_BIAS;   // b1[0:16) b2[16:48) b3[48:112)

    for (int i = tid; i < 1536; i += 256) wb1[i] = w1[i];
    {   // wB2: single fp16x2 pairs over cin
        unsigned* wB2h = (unsigned*)(sm + OFF_WB2);
        for (int i = tid; i < 32 * 32; i += 256) {
            int r = i >> 5, n = i & 31;
            int d = r >> 3, ci2 = r & 7;
            float e = w2[(d * 16 + 2 * ci2) * 32 + n];
            float o = w2[(d * 16 + 2 * ci2 + 1) * 32 + n];
            wB2h[r * 40 + n] = pack_f16x2(e, o);
        }
    }
    if (tid < 16) sb[tid] = b1[tid];
    else if (tid < 48) sb[tid] = b2[tid - 16];
    else if (tid < 112) sb[tid] = b3[tid - 48];

    for (int i = tid; i < 19 * 576; i += 256) grid[4 * 576 + i] = 0.f;
    float rw = reward[bs];
    for (int p = tid; p < 576; p += 256) {
        int tt = tile_type[bs * 576 + p] * 4;
        grid[p] = emb_tile[tt];
        grid[576 + p] = emb_tile[tt + 1];
        grid[1152 + p] = emb_tile[tt + 2];
        grid[1728 + p] = emb_tile[tt + 3];
        grid[23 * 576 + p] = rw;
    }
    __syncthreads();
    if (tid < 32) {
        int mode = detect_bool_mode((const unsigned char*)umask);
        if (get_mask(umask, bs * 32 + tid, mode)) {
            int t = tid >> 4, u = tid & 15;
            int pb = (bs * 32 + tid) * 2;
            int y = positions[pb], x = positions[pb + 1];
            int cell = y * 24 + x;
            atomicAdd(&grid[(4 + t) * 576 + cell], 0.0625f);
#pragma unroll
            for (int e = 0; e < 8; e++)
                atomicAdd(&grid[(6 + t * 8 + e) * 576 + cell], emb_unit[u * 8 + e]);
        }
    } else if (tid < 38) {
        int r = tid - 32;
        int mode = detect_bool_mode((const unsigned char*)rmask);
        if (get_mask(rmask, bs * 6 + r, mode)) {
            int pb = (bs * 6 + r) * 2;
            int y = rpos[pb], x = rpos[pb + 1];
            atomicAdd(&grid[22 * 576 + y * 24 + x], 1.0f);
        }
    }
    __syncthreads();

    // ---- conv1: FFMA 24->16ch, 24x24 -> 23x23 (529). 3 pixels x 177 threads ----
    {
        unsigned* sA2 = (unsigned*)(sm + OFF_A2);
        if (tid < 177) {
            int p[3], base[3]; bool val[3];
#pragma unroll
            for (int j = 0; j < 3; j++) {
                p[j] = tid + j * 177;
                val[j] = (p[j] < 529);
                int pc = val[j] ? p[j] : 0;
                int y = pc / 23;
                base[j] = y * 24 + (pc - y * 23);
            }
            float acc[3][16];
#pragma unroll
            for (int j = 0; j < 3; j++)
#pragma unroll
                for (int q = 0; q < 16; q++) acc[j][q] = 0.f;
#pragma unroll
            for (int d = 0; d < 4; d++) {
                int off = (d >> 1) * 24 + (d & 1);
#pragma unroll 8
                for (int ci = 0; ci < 24; ci++) {
                    float v0 = grid[ci * 576 + base[0] + off];
                    float v1 = grid[ci * 576 + base[1] + off];
                    float v2 = grid[ci * 576 + base[2] + off];
                    const float4* wq = (const float4*)(wb1 + (d * 24 + ci) * 16);
                    float4 wv[4] = {wq[0], wq[1], wq[2], wq[3]};
#pragma unroll
                    for (int q = 0; q < 4; q++) {
                        acc[0][q * 4 + 0] += v0 * wv[q].x; acc[0][q * 4 + 1] += v0 * wv[q].y;
                        acc[0][q * 4 + 2] += v0 * wv[q].z; acc[0][q * 4 + 3] += v0 * wv[q].w;
                        acc[1][q * 4 + 0] += v1 * wv[q].x; acc[1][q * 4 + 1] += v1 * wv[q].y;
                        acc[1][q * 4 + 2] += v1 * wv[q].z; acc[1][q * 4 + 3] += v1 * wv[q].w;
                        acc[2][q * 4 + 0] += v2 * wv[q].x; acc[2][q * 4 + 1] += v2 * wv[q].y;
                        acc[2][q * 4 + 2] += v2 * wv[q].z; acc[2][q * 4 + 3] += v2 * wv[q].w;
                    }
                }
            }
#pragma unroll
            for (int j = 0; j < 3; j++) {
                if (!val[j]) continue;
#pragma unroll
                for (int q2 = 0; q2 < 8; q2++) {
                    float e = fmaxf(acc[j][2 * q2] + sb[2 * q2], 0.f);
                    float o = fmaxf(acc[j][2 * q2 + 1] + sb[2 * q2 + 1], 0.f);
                    sA2[q2 * 536 + p[j]] = pack_f16x2(e, o);
                }
            }
        }
    }
    __syncthreads();

    int wid = tid >> 5, lane = tid & 31;
    int grp = lane >> 2, tig = lane & 3;
    int wm = wid & 3, wn = wid >> 2;

    // ---- conv2: fp16 MMA 16->32ch, 23x23 -> 22x22 (484). 1 MMA per logical ----
    {
        const unsigned* sA2 = (const unsigned*)(sm + OFF_A2);
        const unsigned* wB2h = (const unsigned*)(sm + OFF_WB2);
        float acc2[8][2][4];
#pragma unroll
        for (int mt = 0; mt < 8; mt++)
#pragma unroll
            for (int ni = 0; ni < 2; ni++)
#pragma unroll
                for (int q = 0; q < 4; q++) acc2[mt][ni][q] = 0.f;
        int i0[8], i1[8];
#pragma unroll
        for (int mt = 0; mt < 8; mt++) {
            int tile = wm + mt * 4;
            int p0 = tile * 16 + grp, p1 = p0 + 8;
            int q0 = (p0 < 484) ? p0 : 0; i0[mt] = q0 + q0 / 22;
            int q1 = (p1 < 484) ? p1 : 0; i1[mt] = q1 + q1 / 22;
        }
#pragma unroll 1
        for (int d = 0; d < 4; d++) {
            int off = (d >> 1) * 23 + (d & 1);
            unsigned bh[2][2];
#pragma unroll
            for (int ni = 0; ni < 2; ni++) {
                int nb = wn * 16 + ni * 8 + grp;
                bh[ni][0] = wB2h[(d * 8 + tig) * 40 + nb];
                bh[ni][1] = wB2h[(d * 8 + tig + 4) * 40 + nb];
            }
#pragma unroll
            for (int mt = 0; mt < 8; mt++) {
                if (wm + mt * 4 < 31) {
                    unsigned ah[4];
                    ah[0] = sA2[tig * 536 + i0[mt] + off];
                    ah[1] = sA2[tig * 536 + i1[mt] + off];
                    ah[2] = sA2[(tig + 4) * 536 + i0[mt] + off];
                    ah[3] = sA2[(tig + 4) * 536 + i1[mt] + off];
#pragma unroll
                    for (int ni = 0; ni < 2; ni++)
                        mma_f16(acc2[mt][ni], ah, bh[ni]);
                }
            }
        }
        unsigned* sA3 = (unsigned*)(sm + OFF_A3);
        const float* b2s = sb + 16;
#pragma unroll
        for (int mt = 0; mt < 8; mt++) {
            int tile = wm + mt * 4;
            if (tile < 31) {
                int p0 = tile * 16 + grp, p1 = p0 + 8;
#pragma unroll
                for (int ni = 0; ni < 2; ni++) {
                    int c0 = wn * 16 + ni * 8 + 2 * tig;
                    float be = b2s[c0], bo = b2s[c0 + 1];
                    int c2 = c0 >> 1;
                    if (p0 < 484)
                        sA3[c2 * 488 + p0] = pack_f16x2(fmaxf(acc2[mt][ni][0] + be, 0.f),
                                                        fmaxf(acc2[mt][ni][1] + bo, 0.f));
                    if (p1 < 484)
                        sA3[c2 * 488 + p1] = pack_f16x2(fmaxf(acc2[mt][ni][2] + be, 0.f),
                                                        fmaxf(acc2[mt][ni][3] + bo, 0.f));
                }
            }
        }
    }
    __syncthreads();

    // ---- load wB3h (single fp16 pairs; overlays sA2/wB2 — dead) ----
    {
        unsigned* wB3h = (unsigned*)(sm + OFF_WB3);
        for (int i = tid; i < 64 * 64; i += 256) {
            int r = i >> 6, n = i & 63;
            int d = r >> 4, ci2 = r & 15;
            float e = w3[(d * 32 + 2 * ci2) * 64 + n];
            float o = w3[(d * 32 + 2 * ci2 + 1) * 64 + n];
            wB3h[r * 72 + n] = pack_f16x2(e, o);
        }
    }
    __syncthreads();

    // ---- conv3: fp16 MMA 32->64ch, 22x22 -> 21x21 (441), 2 n-passes; fp16 epilogue ----
    {
        const unsigned* sA3 = (const unsigned*)(sm + OFF_A3);
        const unsigned* wB3h = (const unsigned*)(sm + OFF_WB3);
        const float* b3s = sb + 48;
        __half* go = g_feat + (size_t)bs * FEAT_D_;
        int i0[7], i1[7];
#pragma unroll
        for (int mt = 0; mt < 7; mt++) {
            int p0 = (wm + mt * 4) * 16 + grp, p1 = p0 + 8;
            int q0 = (p0 < 441) ? p0 : 0; i0[mt] = q0 + q0 / 21;
            int q1 = (p1 < 441) ? p1 : 0; i1[mt] = q1 + q1 / 21;
        }
#pragma unroll 1
        for (int pass = 0; pass < 2; pass++) {
            int n0 = wn * 32 + pass * 16;
            float acc3[7][2][4];
#pragma unroll
            for (int mt = 0; mt < 7; mt++)
#pragma unroll
                for (int ni = 0; ni < 2; ni++)
#pragma unroll
                    for (int q = 0; q < 4; q++) acc3[mt][ni][q] = 0.f;
#pragma unroll 1
            for (int dk = 0; dk < 8; dk++) {
                int d = dk >> 1, h8 = dk & 1;
                int off = (d >> 1) * 22 + (d & 1);
                int kb = h8 * 8;
                unsigned bh[2][2];
#pragma unroll
                for (int ni = 0; ni < 2; ni++) {
                    int nb = n0 + ni * 8 + grp;
                    bh[ni][0] = wB3h[(d * 16 + kb + tig) * 72 + nb];
                    bh[ni][1] = wB3h[(d * 16 + kb + tig + 4) * 72 + nb];
                }
#pragma unroll
                for (int mt = 0; mt < 7; mt++) {
                    unsigned ah[4];
                    ah[0] = sA3[(kb + tig) * 488 + i0[mt] + off];
                    ah[1] = sA3[(kb + tig) * 488 + i1[mt] + off];
                    ah[2] = sA3[(kb + tig + 4) * 488 + i0[mt] + off];
                    ah[3] = sA3[(kb + tig + 4) * 488 + i1[mt] + off];
#pragma unroll
                    for (int ni = 0; ni < 2; ni++)
                        mma_f16(acc3[mt][ni], ah, bh[ni]);
                }
            }
#pragma unroll
            for (int mt = 0; mt < 7; mt++) {
                int p0 = (wm + mt * 4) * 16 + grp, p1 = p0 + 8;
#pragma unroll
                for (int ni = 0; ni < 2; ni++) {
                    int c0 = n0 + ni * 8 + 2 * tig;
                    float be = b3s[c0], bo = b3s[c0 + 1];
                    if (p0 < 441) {
                        unsigned v = pack_f16x2(fmaxf(acc3[mt][ni][0] + be, 0.f),
                                                fmaxf(acc3[mt][ni][1] + bo, 0.f));
                        *(unsigned*)(go + p0 * 64 + c0) = v;
                    }
                    if (p1 < 441) {
                        unsigned v = pack_f16x2(fmaxf(acc3[mt][ni][2] + be, 0.f),
                                                fmaxf(acc3[mt][ni][3] + bo, 0.f));
                        *(unsigned*)(go + p1 * 64 + c0) = v;
                    }
                }
            }
        }
    }
}

// ---------------- fp16 GEMM, BN=192: A single fp16, B = Wi split fp16 hi+lo ----------------
#define APAD 76
#define BPAD 196

__global__ void __launch_bounds__(256) gemm_f16_kernel(const float* __restrict__ Bmat) {
    __shared__ unsigned A1s[8][APAD];
    __shared__ uint2 B2s[8][BPAD];
    const int K = FEAT_D_;
    int tid = threadIdx.x;
    int m0 = blockIdx.x * 64;
    int kz = blockIdx.z;
    int kbeg = kz * KSPLIT_LEN;

    int warp = tid >> 5, lane = tid & 31;
    int wm = (warp & 1) * 32;
    int wn = (warp >> 1) * 48;
    int grp = lane >> 2, tig = lane & 3;

    int lr = tid >> 2;
    int lkq = (tid & 3) * 4;
    int k2 = lkq >> 1;

    const __half* A = g_feat;
    const float* Bp = Bmat;

    uint2 pa = *(const uint2*)&A[(size_t)(m0 + lr) * K + kbeg + lkq];
    float4 pb0 = *(const float4*)&Bp[(size_t)(lr) * K + kbeg + lkq];
    float4 pb1 = *(const float4*)&Bp[(size_t)(lr + 64) * K + kbeg + lkq];
    float4 pb2 = *(const float4*)&Bp[(size_t)(lr + 128) * K + kbeg + lkq];

    float acc[2][6][4];
#pragma unroll
    for (int i = 0; i < 2; i++)
#pragma unroll
        for (int j = 0; j < 6; j++)
#pragma unroll
            for (int q = 0; q < 4; q++) acc[i][j][q] = 0.f;

    const int NIT = KSPLIT_LEN / 16;
    for (int it = 0; it < NIT; it++) {
        {
            A1s[k2 + 0][lr] = pa.x;
            A1s[k2 + 1][lr] = pa.y;
            unsigned h, l;
            split_f16(pb0.x, pb0.y, h, l); B2s[k2 + 0][lr] = make_uint2(h, l);
            split_f16(pb0.z, pb0.w, h, l); B2s[k2 + 1][lr] = make_uint2(h, l);
            split_f16(pb1.x, pb1.y, h, l); B2s[k2 + 0][lr + 64] = make_uint2(h, l);
            split_f16(pb1.z, pb1.w, h, l); B2s[k2 + 1][lr + 64] = make_uint2(h, l);
            split_f16(pb2.x, pb2.y, h, l); B2s[k2 + 0][lr + 128] = make_uint2(h, l);
            split_f16(pb2.z, pb2.w, h, l); B2s[k2 + 1][lr + 128] = make_uint2(h, l);
        }
        __syncthreads();
        if (it + 1 < NIT) {
            int kn = kbeg + (it + 1) * 16;
            pa  = *(const uint2*)&A[(size_t)(m0 + lr) * K + kn + lkq];
            pb0 = *(const float4*)&Bp[(size_t)(lr) * K + kn + lkq];
            pb1 = *(const float4*)&Bp[(size_t)(lr + 64) * K + kn + lkq];
            pb2 = *(const float4*)&Bp[(size_t)(lr + 128) * K + kn + lkq];
        }
        {
            unsigned af[2][4];
#pragma unroll
            for (int mi = 0; mi < 2; mi++) {
                int mb = wm + mi * 16 + grp;
                af[mi][0] = A1s[tig][mb];
                af[mi][1] = A1s[tig][mb + 8];
                af[mi][2] = A1s[tig + 4][mb];
                af[mi][3] = A1s[tig + 4][mb + 8];
            }
#pragma unroll
            for (int ni = 0; ni < 6; ni++) {
                int nb = wn + ni * 8 + grp;
                uint2 b0 = B2s[tig][nb];
                uint2 b1 = B2s[tig + 4][nb];
                unsigned bfh[2] = {b0.x, b1.x};
                unsigned bfl[2] = {b0.y, b1.y};
#pragma unroll
                for (int mi = 0; mi < 2; mi++) {
                    mma_f16(acc[mi][ni], af[mi], bfl);
                    mma_f16(acc[mi][ni], af[mi], bfh);
                }
            }
        }
        __syncthreads();
    }

    float* out = g_part + (size_t)kz * PART_STRIDE;
#pragma unroll
    for (int mi = 0; mi < 2; mi++) {
#pragma unroll
        for (int ni = 0; ni < 6; ni++) {
            int col = wn + ni * 8 + 2 * tig;
            int row0 = m0 + wm + mi * 16 + grp;
            float2 v0 = make_float2(acc[mi][ni][0], acc[mi][ni][1]);
            float2 v1 = make_float2(acc[mi][ni][2], acc[mi][ni][3]);
            *(float2*)&out[(size_t)row0 * 192 + col] = v0;
            *(float2*)&out[(size_t)(row0 + 8) * 192 + col] = v1;
        }
    }
}

// ---------------- GRU scan (fused split-K reduce + bias) ----------------
__global__ void __launch_bounds__(192) gru_kernel(const float* __restrict__ h0,
                                                  const float* __restrict__ Wh,
                                                  const float* __restrict__ bn,
                                                  const float* __restrict__ bi,
                                                  float* __restrict__ hfinal) {
    int b = blockIdx.x, g = threadIdx.x;
    __shared__ float h[64];
    __shared__ float hg[192];
    __shared__ float sig[192];
    float w[64];
#pragma unroll
    for (int k = 0; k < 64; k++) w[k] = Wh[g * 64 + k];
    float bnv = (g < 64) ? bn[g] : 0.f;
    float biv = bi[g];
    if (g < 64) h[g] = h0[b * 64 + g];
    const float* P = g_part;
    int idx = (b * 128 + 0) * 192 + g;
    float q0 = P[idx], q1 = P[PART_STRIDE + idx];
    float q2 = P[2 * PART_STRIDE + idx], q3 = P[3 * PART_STRIDE + idx];
    __syncthreads();
    for (int t = 0; t < 128; t++) {
        float a0 = 0.f, a1 = 0.f, a2 = 0.f, a3 = 0.f;
#pragma unroll
        for (int k = 0; k < 64; k += 4) {
            a0 += w[k] * h[k];
            a1 += w[k + 1] * h[k + 1];
            a2 += w[k + 2] * h[k + 2];
            a3 += w[k + 3] * h[k + 3];
        }
        hg[g] = (a0 + a1) + (a2 + a3);
        sig[g] = biv + q0 + q1 + q2 + q3;
        __syncthreads();
        int tn = (t < 127) ? t + 1 : 127;
        int idxn = (b * 128 + tn) * 192 + g;
        q0 = P[idxn]; q1 = P[PART_STRIDE + idxn];
        q2 = P[2 * PART_STRIDE + idxn]; q3 = P[3 * PART_STRIDE + idxn];
        if (g < 64) {
            float rr = 1.f / (1.f + __expf(-(sig[g] + hg[g])));
            float zz = 1.f / (1.f + __expf(-(sig[64 + g] + hg[64 + g])));
            float nn = tanhf(sig[128 + g] + rr * (hg[128 + g] + bnv));
            float hn = (1.f - zz) * nn + zz * h[g];
            h[g] = hn;
            g_allh[(b * 128 + t) * 64 + g] = hn;
        }
        __syncthreads();
    }
    if (g < 64) hfinal[b * 64 + g] = h[g];
}

// ---------------- heads (256 CTAs x 16 rows) ----------------
#define HEADS_SMEM_BYTES (14816 * 4)
__global__ void __launch_bounds__(128) heads_kernel(
    const float* __restrict__ Wa1, const float* __restrict__ ba1,
    const float* __restrict__ Wa2, const float* __restrict__ ba2,
    const float* __restrict__ Wc1, const float* __restrict__ bc1,
    const float* __restrict__ Wc2, const float* __restrict__ bc2,
    float* __restrict__ logits, float* __restrict__ values) {
    extern __shared__ float s[];
    float* sWa1 = s;
    float* sWc1 = s + 4096;
    float* sWa2 = s + 8192;
    float* sWc2 = s + 14336;
    float* sba1 = s + 14400;
    float* sbc1 = s + 14464;
    float* sba2 = s + 14528;
    float* sh   = s + 14624;
    float* sa   = s + 14688;
    float* sc   = s + 14752;
    int tid = threadIdx.x;
    for (int i = tid; i < 4096; i += 128) { sWa1[i] = Wa1[i]; sWc1[i] = Wc1[i]; }
    for (int i = tid; i < 6144; i += 128) sWa2[i] = Wa2[i];
    if (tid < 64) { sWc2[tid] = Wc2[tid]; sba1[tid] = ba1[tid]; sbc1[tid] = bc1[tid]; }
    if (tid < 96) sba2[tid] = ba2[tid];
    float bc2v = bc2[0];
    __syncthreads();
    for (int r = blockIdx.x * 16; r < blockIdx.x * 16 + 16; r++) {
        if (tid < 64) sh[tid] = g_allh[r * 64 + tid];
        __syncthreads();
        {
            int j = tid & 63;
            const float* W = (tid < 64) ? sWa1 : sWc1;
            float acc = 0.f;
#pragma unroll
            for (int i = 0; i < 64; i++) acc += sh[i] * W[i * 64 + j];
            float v = tanhf(acc + ((tid < 64) ? sba1[j] : sbc1[j]));
            if (tid < 64) sa[j] = v; else sc[j] = v;
        }
        __syncthreads();
        if (tid < 96) {
            float acc = sba2[tid];
#pragma unroll
            for (int j = 0; j < 64; j++) acc += sa[j] * sWa2[j * 96 + tid];
            logits[r * 96 + tid] = acc;
        } else if (tid == 96) {
            float acc = bc2v;
#pragma unroll
            for (int j = 0; j < 64; j++) acc += sc[j] * sWc2[j];
            values[r] = acc;
        }
        __syncthreads();
    }
}

// ---------------- launch ----------------
extern "C" void kernel_launch(void* const* d_in, const int* in_sizes, int n_in,
                              void* d_out, int out_size) {
    const int*   positions = (const int*)d_in[0];
    const void*  umask     = d_in[1];
    const int*   tile      = (const int*)d_in[2];
    const int*   rpos      = (const int*)d_in[3];
    const void*  rmask     = d_in[4];
    const float* reward    = (const float*)d_in[5];
    const float* hidden    = (const float*)d_in[6];
    const float* emb_tile  = (const float*)d_in[7];
    const float* emb_unit  = (const float*)d_in[8];
    const float* w1 = (const float*)d_in[9];
    const float* b1 = (const float*)d_in[10];
    const float* w2 = (const float*)d_in[11];
    const float* b2 = (const float*)d_in[12];
    const float* w3 = (const float*)d_in[13];
    const float* b3 = (const float*)d_in[14];
    const float* Wi = (const float*)d_in[15];
    const float* Wh = (const float*)d_in[16];
    const float* bi = (const float*)d_in[17];
    const float* bn = (const float*)d_in[18];
    const float* Wa1 = (const float*)d_in[19];
    const float* ba1 = (const float*)d_in[20];
    const float* Wa2 = (const float*)d_in[21];
    const float* ba2 = (const float*)d_in[22];
    const float* Wc1 = (const float*)d_in[23];
    const float* bc1 = (const float*)d_in[24];
    const float* Wc2 = (const float*)d_in[25];
    const float* bc2 = (const float*)d_in[26];
    float* out = (float*)d_out;

    float* out_logits = out;
    float* out_values = out + 393216;
    float* out_hidden = out + 397312;

    const int conv_smem = CONV_SMEM_FLOATS * (int)sizeof(float);
    cudaFuncSetAttribute(conv_kernel, cudaFuncAttributeMaxDynamicSharedMemorySize, conv_smem);
    cudaFuncSetAttribute(heads_kernel, cudaFuncAttributeMaxDynamicSharedMemorySize, HEADS_SMEM_BYTES);

    conv_kernel<<<BS_, 256, conv_smem>>>(positions, umask, tile, rpos, rmask, reward,
                                         emb_tile, emb_unit, w1, b1, w2, b2, w3, b3);
    gemm_f16_kernel<<<dim3(64, 1, SPLITK), 256>>>(Wi);
    gru_kernel<<<32, 192>>>(hidden, Wh, bn, bi, out_hidden);
    heads_kernel<<<256, 128, HEADS_SMEM_BYTES>>>(Wa1, ba1, Wa2, ba2, Wc1, bc1, Wc2, bc2,
                                                 out_logits, out_values);
}

// round 17
// speedup vs baseline: 3.3394x; 1.1519x over previous
#include <cuda_runtime.h>
#include <cuda_fp16.h>
#include <stdint.h>
#include <math.h>

#define B_ 32
#define S_ 128
#define BS_ 4096
#define FEAT_D_ 28224
#define SPLITK 4
#define KSPLIT_LEN (FEAT_D_ / SPLITK)   // 7056
#define PART_STRIDE (BS_ * 192)

// ---------------- scratch ----------------
__device__ __half g_feat[(size_t)BS_ * FEAT_D_];   // fp16 conv output (231 MB)
__device__ float g_part[(size_t)SPLITK * BS_ * 192];
__device__ float g_allh[BS_ * 64];

// ---------------- bool-mask dtype detection ----------------
__device__ __forceinline__ int detect_bool_mode(const unsigned char* p) {
    bool any80 = false, nz = false;
    for (int i = 0; i < 256; i++) {
        unsigned char v = p[i];
        int m = i & 3;
        if (m == 2 && v == 0x80) any80 = true;
        if (m != 0 && v != 0) nz = true;
    }
    if (!nz) return 1;
    if (any80) return 2;
    return 0;
}
__device__ __forceinline__ bool get_mask(const void* p, int i, int mode) {
    if (mode == 1) return ((const int*)p)[i] != 0;
    if (mode == 2) return ((const float*)p)[i] != 0.0f;
    return ((const unsigned char*)p)[i] != 0;
}

// ---------------- fp16 helpers ----------------
__device__ __forceinline__ unsigned pack_f16x2(float e, float o) {
    unsigned r;
    asm("cvt.rn.f16x2.f32 %0, %1, %2;" : "=r"(r) : "f"(o), "f"(e));  // lo=e, hi=o
    return r;
}
__device__ __forceinline__ void split_f16(float e, float o, unsigned& h, unsigned& l) {
    h = pack_f16x2(e, o);
    __half2 hh = *reinterpret_cast<__half2*>(&h);
    float he = __low2float(hh), ho = __high2float(hh);
    l = pack_f16x2(e - he, o - ho);
}
__device__ __forceinline__ void mma_f16(float* acc, const unsigned* a, const unsigned* b) {
    asm volatile(
        "mma.sync.aligned.m16n8k16.row.col.f32.f16.f16.f32 "
        "{%0,%1,%2,%3}, {%4,%5,%6,%7}, {%8,%9}, {%0,%1,%2,%3};"
        : "+f"(acc[0]), "+f"(acc[1]), "+f"(acc[2]), "+f"(acc[3])
        : "r"(a[0]), "r"(a[1]), "r"(a[2]), "r"(a[3]), "r"(b[0]), "r"(b[1]));
}

// ---------------- conv kernel smem layout (float units) ----------------
// [0..13824)  grid fp32 (phase0/scatter) ==> dead after pack ==> sA3 (u32 16x488=7808)
// [13824..14976) wb1p (u32 48x24=1152)   (dead after conv1)
// [15360..19648) sA2 (u32 8x536=4288)    (dead after conv2)
// [19648..20928) wB2 (u32 32x40=1280)    (dead after conv2)
//   wB3 (u32 64x72=4608) overlays [15360..19968) after conv2
// [20928..21056) bias
// [21056..28064) gp (u32 12x584=7008)    (dead after conv1)
#define OFF_GRID 0
#define OFF_A3   0
#define OFF_WB1  13824
#define OFF_A2   15360
#define OFF_WB2  19648
#define OFF_WB3  15360
#define OFF_BIAS 20928
#define OFF_GP   21056
#define CONV_SMEM_FLOATS 28064   // 112256 B -> 2 CTAs/SM

__global__ void __launch_bounds__(256, 2) conv_kernel(
    const int* __restrict__ positions, const void* __restrict__ umask,
    const int* __restrict__ tile_type, const int* __restrict__ rpos,
    const void* __restrict__ rmask, const float* __restrict__ reward,
    const float* __restrict__ emb_tile, const float* __restrict__ emb_unit,
    const float* __restrict__ w1, const float* __restrict__ b1,
    const float* __restrict__ w2, const float* __restrict__ b2,
    const float* __restrict__ w3, const float* __restrict__ b3) {
    extern __shared__ float sm[];
    int tid = threadIdx.x, bs = blockIdx.x;
    float* grid = sm + OFF_GRID;
    float* sb   = sm + OFF_BIAS;   // b1[0:16) b2[16:48) b3[48:112)

    // ---- phase 0: weight packs + bias + grid build ----
    {   // wb1p: pairs over cin for each tap: row kp = d*12+ci2 (48), stride 24
        unsigned* wb1p = (unsigned*)(sm + OFF_WB1);
        for (int i = tid; i < 48 * 16; i += 256) {
            int r = i >> 4, n = i & 15;
            int d = r / 12, ci2 = r % 12;
            float e = w1[(d * 24 + 2 * ci2) * 16 + n];
            float o = w1[(d * 24 + 2 * ci2 + 1) * 16 + n];
            wb1p[r * 24 + n] = pack_f16x2(e, o);
        }
    }
    {   // wB2: single fp16x2 pairs over cin
        unsigned* wB2h = (unsigned*)(sm + OFF_WB2);
        for (int i = tid; i < 32 * 32; i += 256) {
            int r = i >> 5, n = i & 31;
            int d = r >> 3, ci2 = r & 7;
            float e = w2[(d * 16 + 2 * ci2) * 32 + n];
            float o = w2[(d * 16 + 2 * ci2 + 1) * 32 + n];
            wB2h[r * 40 + n] = pack_f16x2(e, o);
        }
    }
    if (tid < 16) sb[tid] = b1[tid];
    else if (tid < 48) sb[tid] = b2[tid - 16];
    else if (tid < 112) sb[tid] = b3[tid - 48];

    for (int i = tid; i < 19 * 576; i += 256) grid[4 * 576 + i] = 0.f;
    float rw = reward[bs];
    for (int p = tid; p < 576; p += 256) {
        int tt = tile_type[bs * 576 + p] * 4;
        grid[p] = emb_tile[tt];
        grid[576 + p] = emb_tile[tt + 1];
        grid[1152 + p] = emb_tile[tt + 2];
        grid[1728 + p] = emb_tile[tt + 3];
        grid[23 * 576 + p] = rw;
    }
    __syncthreads();
    if (tid < 32) {
        int mode = detect_bool_mode((const unsigned char*)umask);
        if (get_mask(umask, bs * 32 + tid, mode)) {
            int t = tid >> 4, u = tid & 15;
            int pb = (bs * 32 + tid) * 2;
            int y = positions[pb], x = positions[pb + 1];
            int cell = y * 24 + x;
            atomicAdd(&grid[(4 + t) * 576 + cell], 0.0625f);
#pragma unroll
            for (int e = 0; e < 8; e++)
                atomicAdd(&grid[(6 + t * 8 + e) * 576 + cell], emb_unit[u * 8 + e]);
        }
    } else if (tid < 38) {
        int r = tid - 32;
        int mode = detect_bool_mode((const unsigned char*)rmask);
        if (get_mask(rmask, bs * 6 + r, mode)) {
            int pb = (bs * 6 + r) * 2;
            int y = rpos[pb], x = rpos[pb + 1];
            atomicAdd(&grid[22 * 576 + y * 24 + x], 1.0f);
        }
    }
    __syncthreads();

    // ---- pack grid -> gp (channel-pair f16x2 planes) ----
    {
        unsigned* gp = (unsigned*)(sm + OFF_GP);
        for (int i = tid; i < 12 * 576; i += 256) {
            int ci2 = i / 576, pix = i - ci2 * 576;
            gp[ci2 * 584 + pix] = pack_f16x2(grid[(2 * ci2) * 576 + pix],
                                             (2 * ci2 + 1 < 24) ? grid[(2 * ci2 + 1) * 576 + pix] : 0.f);
        }
    }
    __syncthreads();

    int wid = tid >> 5, lane = tid & 31;
    int grp = lane >> 2, tig = lane & 3;
    int wm = wid & 3, wn = wid >> 2;

    // ---- conv1: fp16 MMA 24->16ch, 24x24 -> 23x23 (529). M-tiles 34, N=16, K=96 ----
    {
        const unsigned* gp = (const unsigned*)(sm + OFF_GP);
        const unsigned* wb1p = (const unsigned*)(sm + OFF_WB1);
        unsigned* sA2 = (unsigned*)(sm + OFF_A2);
        float acc1[5][2][4];
#pragma unroll
        for (int j = 0; j < 5; j++)
#pragma unroll
            for (int ni = 0; ni < 2; ni++)
#pragma unroll
                for (int q = 0; q < 4; q++) acc1[j][ni][q] = 0.f;
        int i0[5], i1[5], p0a[5], p1a[5];
#pragma unroll
        for (int j = 0; j < 5; j++) {
            int tile = wid + 8 * j;
            int p0 = tile * 16 + grp, p1 = p0 + 8;
            p0a[j] = p0; p1a[j] = p1;
            int q0 = (p0 < 529) ? p0 : 0; i0[j] = q0 + q0 / 23;
            int q1 = (p1 < 529) ? p1 : 0; i1[j] = q1 + q1 / 23;
        }
#pragma unroll
        for (int c = 0; c < 6; c++) {
            int kplo = 8 * c + tig, kphi = kplo + 4;
            int dlo = kplo / 12, clo = kplo - dlo * 12;
            int dhi = kphi / 12, chi = kphi - dhi * 12;
            int alo = clo * 584 + (dlo >> 1) * 24 + (dlo & 1);
            int ahi = chi * 584 + (dhi >> 1) * 24 + (dhi & 1);
            unsigned bh[2][2];
#pragma unroll
            for (int ni = 0; ni < 2; ni++) {
                int nb = ni * 8 + grp;
                bh[ni][0] = wb1p[kplo * 24 + nb];
                bh[ni][1] = wb1p[kphi * 24 + nb];
            }
#pragma unroll
            for (int j = 0; j < 5; j++) {
                if (wid + 8 * j < 34) {
                    unsigned a[4];
                    a[0] = gp[alo + i0[j]];
                    a[1] = gp[alo + i1[j]];
                    a[2] = gp[ahi + i0[j]];
                    a[3] = gp[ahi + i1[j]];
#pragma unroll
                    for (int ni = 0; ni < 2; ni++)
                        mma_f16(acc1[j][ni], a, bh[ni]);
                }
            }
        }
        // epilogue -> sA2 [cout-pair][pixel]
#pragma unroll
        for (int j = 0; j < 5; j++) {
            if (wid + 8 * j < 34) {
#pragma unroll
                for (int ni = 0; ni < 2; ni++) {
                    int c0 = ni * 8 + 2 * tig;
                    float be = sb[c0], bo = sb[c0 + 1];
                    int c2 = c0 >> 1;
                    if (p0a[j] < 529)
                        sA2[c2 * 536 + p0a[j]] = pack_f16x2(fmaxf(acc1[j][ni][0] + be, 0.f),
                                                            fmaxf(acc1[j][ni][1] + bo, 0.f));
                    if (p1a[j] < 529)
                        sA2[c2 * 536 + p1a[j]] = pack_f16x2(fmaxf(acc1[j][ni][2] + be, 0.f),
                                                            fmaxf(acc1[j][ni][3] + bo, 0.f));
                }
            }
        }
    }
    __syncthreads();

    // ---- conv2: fp16 MMA 16->32ch, 23x23 -> 22x22 (484) ----
    {
        const unsigned* sA2 = (const unsigned*)(sm + OFF_A2);
        const unsigned* wB2h = (const unsigned*)(sm + OFF_WB2);
        float acc2[8][2][4];
#pragma unroll
        for (int mt = 0; mt < 8; mt++)
#pragma unroll
            for (int ni = 0; ni < 2; ni++)
#pragma unroll
                for (int q = 0; q < 4; q++) acc2[mt][ni][q] = 0.f;
        int i0[8], i1[8];
#pragma unroll
        for (int mt = 0; mt < 8; mt++) {
            int tile = wm + mt * 4;
            int p0 = tile * 16 + grp, p1 = p0 + 8;
            int q0 = (p0 < 484) ? p0 : 0; i0[mt] = q0 + q0 / 22;
            int q1 = (p1 < 484) ? p1 : 0; i1[mt] = q1 + q1 / 22;
        }
#pragma unroll 1
        for (int d = 0; d < 4; d++) {
            int off = (d >> 1) * 23 + (d & 1);
            unsigned bh[2][2];
#pragma unroll
            for (int ni = 0; ni < 2; ni++) {
                int nb = wn * 16 + ni * 8 + grp;
                bh[ni][0] = wB2h[(d * 8 + tig) * 40 + nb];
                bh[ni][1] = wB2h[(d * 8 + tig + 4) * 40 + nb];
            }
#pragma unroll
            for (int mt = 0; mt < 8; mt++) {
                if (wm + mt * 4 < 31) {
                    unsigned ah[4];
                    ah[0] = sA2[tig * 536 + i0[mt] + off];
                    ah[1] = sA2[tig * 536 + i1[mt] + off];
                    ah[2] = sA2[(tig + 4) * 536 + i0[mt] + off];
                    ah[3] = sA2[(tig + 4) * 536 + i1[mt] + off];
#pragma unroll
                    for (int ni = 0; ni < 2; ni++)
                        mma_f16(acc2[mt][ni], ah, bh[ni]);
                }
            }
        }
        unsigned* sA3 = (unsigned*)(sm + OFF_A3);
        const float* b2s = sb + 16;
#pragma unroll
        for (int mt = 0; mt < 8; mt++) {
            int tile = wm + mt * 4;
            if (tile < 31) {
                int p0 = tile * 16 + grp, p1 = p0 + 8;
#pragma unroll
                for (int ni = 0; ni < 2; ni++) {
                    int c0 = wn * 16 + ni * 8 + 2 * tig;
                    float be = b2s[c0], bo = b2s[c0 + 1];
                    int c2 = c0 >> 1;
                    if (p0 < 484)
                        sA3[c2 * 488 + p0] = pack_f16x2(fmaxf(acc2[mt][ni][0] + be, 0.f),
                                                        fmaxf(acc2[mt][ni][1] + bo, 0.f));
                    if (p1 < 484)
                        sA3[c2 * 488 + p1] = pack_f16x2(fmaxf(acc2[mt][ni][2] + be, 0.f),
                                                        fmaxf(acc2[mt][ni][3] + bo, 0.f));
                }
            }
        }
    }
    __syncthreads();

    // ---- load wB3h (overlays sA2/wB2 — dead) ----
    {
        unsigned* wB3h = (unsigned*)(sm + OFF_WB3);
        for (int i = tid; i < 64 * 64; i += 256) {
            int r = i >> 6, n = i & 63;
            int d = r >> 4, ci2 = r & 15;
            float e = w3[(d * 32 + 2 * ci2) * 64 + n];
            float o = w3[(d * 32 + 2 * ci2 + 1) * 64 + n];
            wB3h[r * 72 + n] = pack_f16x2(e, o);
        }
    }
    __syncthreads();

    // ---- conv3: fp16 MMA 32->64ch, 22x22 -> 21x21 (441), 2 n-passes; fp16 epilogue ----
    {
        const unsigned* sA3 = (const unsigned*)(sm + OFF_A3);
        const unsigned* wB3h = (const unsigned*)(sm + OFF_WB3);
        const float* b3s = sb + 48;
        __half* go = g_feat + (size_t)bs * FEAT_D_;
        int i0[7], i1[7];
#pragma unroll
        for (int mt = 0; mt < 7; mt++) {
            int p0 = (wm + mt * 4) * 16 + grp, p1 = p0 + 8;
            int q0 = (p0 < 441) ? p0 : 0; i0[mt] = q0 + q0 / 21;
            int q1 = (p1 < 441) ? p1 : 0; i1[mt] = q1 + q1 / 21;
        }
#pragma unroll 1
        for (int pass = 0; pass < 2; pass++) {
            int n0 = wn * 32 + pass * 16;
            float acc3[7][2][4];
#pragma unroll
            for (int mt = 0; mt < 7; mt++)
#pragma unroll
                for (int ni = 0; ni < 2; ni++)
#pragma unroll
                    for (int q = 0; q < 4; q++) acc3[mt][ni][q] = 0.f;
#pragma unroll 1
            for (int dk = 0; dk < 8; dk++) {
                int d = dk >> 1, h8 = dk & 1;
                int off = (d >> 1) * 22 + (d & 1);
                int kb = h8 * 8;
                unsigned bh[2][2];
#pragma unroll
                for (int ni = 0; ni < 2; ni++) {
                    int nb = n0 + ni * 8 + grp;
                    bh[ni][0] = wB3h[(d * 16 + kb + tig) * 72 + nb];
                    bh[ni][1] = wB3h[(d * 16 + kb + tig + 4) * 72 + nb];
                }
#pragma unroll
                for (int mt = 0; mt < 7; mt++) {
                    unsigned ah[4];
                    ah[0] = sA3[(kb + tig) * 488 + i0[mt] + off];
                    ah[1] = sA3[(kb + tig) * 488 + i1[mt] + off];
                    ah[2] = sA3[(kb + tig + 4) * 488 + i0[mt] + off];
                    ah[3] = sA3[(kb + tig + 4) * 488 + i1[mt] + off];
#pragma unroll
                    for (int ni = 0; ni < 2; ni++)
                        mma_f16(acc3[mt][ni], ah, bh[ni]);
                }
            }
#pragma unroll
            for (int mt = 0; mt < 7; mt++) {
                int p0 = (wm + mt * 4) * 16 + grp, p1 = p0 + 8;
#pragma unroll
                for (int ni = 0; ni < 2; ni++) {
                    int c0 = n0 + ni * 8 + 2 * tig;
                    float be = b3s[c0], bo = b3s[c0 + 1];
                    if (p0 < 441) {
                        unsigned v = pack_f16x2(fmaxf(acc3[mt][ni][0] + be, 0.f),
                                                fmaxf(acc3[mt][ni][1] + bo, 0.f));
                        *(unsigned*)(go + p0 * 64 + c0) = v;
                    }
                    if (p1 < 441) {
                        unsigned v = pack_f16x2(fmaxf(acc3[mt][ni][2] + be, 0.f),
                                                fmaxf(acc3[mt][ni][3] + bo, 0.f));
                        *(unsigned*)(go + p1 * 64 + c0) = v;
                    }
                }
            }
        }
    }
}

// ---------------- fp16 GEMM, BN=192: A single fp16, B = Wi split fp16 hi+lo ----------------
#define APAD 76
#define BPAD 196

__global__ void __launch_bounds__(256) gemm_f16_kernel(const float* __restrict__ Bmat) {
    __shared__ unsigned A1s[8][APAD];
    __shared__ uint2 B2s[8][BPAD];
    const int K = FEAT_D_;
    int tid = threadIdx.x;
    int m0 = blockIdx.x * 64;
    int kz = blockIdx.z;
    int kbeg = kz * KSPLIT_LEN;

    int warp = tid >> 5, lane = tid & 31;
    int wm = (warp & 1) * 32;
    int wn = (warp >> 1) * 48;
    int grp = lane >> 2, tig = lane & 3;

    int lr = tid >> 2;
    int lkq = (tid & 3) * 4;
    int k2 = lkq >> 1;

    const __half* A = g_feat;
    const float* Bp = Bmat;

    uint2 pa = *(const uint2*)&A[(size_t)(m0 + lr) * K + kbeg + lkq];
    float4 pb0 = *(const float4*)&Bp[(size_t)(lr) * K + kbeg + lkq];
    float4 pb1 = *(const float4*)&Bp[(size_t)(lr + 64) * K + kbeg + lkq];
    float4 pb2 = *(const float4*)&Bp[(size_t)(lr + 128) * K + kbeg + lkq];

    float acc[2][6][4];
#pragma unroll
    for (int i = 0; i < 2; i++)
#pragma unroll
        for (int j = 0; j < 6; j++)
#pragma unroll
            for (int q = 0; q < 4; q++) acc[i][j][q] = 0.f;

    const int NIT = KSPLIT_LEN / 16;
    for (int it = 0; it < NIT; it++) {
        {
            A1s[k2 + 0][lr] = pa.x;
            A1s[k2 + 1][lr] = pa.y;
            unsigned h, l;
            split_f16(pb0.x, pb0.y, h, l); B2s[k2 + 0][lr] = make_uint2(h, l);
            split_f16(pb0.z, pb0.w, h, l); B2s[k2 + 1][lr] = make_uint2(h, l);
            split_f16(pb1.x, pb1.y, h, l); B2s[k2 + 0][lr + 64] = make_uint2(h, l);
            split_f16(pb1.z, pb1.w, h, l); B2s[k2 + 1][lr + 64] = make_uint2(h, l);
            split_f16(pb2.x, pb2.y, h, l); B2s[k2 + 0][lr + 128] = make_uint2(h, l);
            split_f16(pb2.z, pb2.w, h, l); B2s[k2 + 1][lr + 128] = make_uint2(h, l);
        }
        __syncthreads();
        if (it + 1 < NIT) {
            int kn = kbeg + (it + 1) * 16;
            pa  = *(const uint2*)&A[(size_t)(m0 + lr) * K + kn + lkq];
            pb0 = *(const float4*)&Bp[(size_t)(lr) * K + kn + lkq];
            pb1 = *(const float4*)&Bp[(size_t)(lr + 64) * K + kn + lkq];
            pb2 = *(const float4*)&Bp[(size_t)(lr + 128) * K + kn + lkq];
        }
        {
            unsigned af[2][4];
#pragma unroll
            for (int mi = 0; mi < 2; mi++) {
                int mb = wm + mi * 16 + grp;
                af[mi][0] = A1s[tig][mb];
                af[mi][1] = A1s[tig][mb + 8];
                af[mi][2] = A1s[tig + 4][mb];
                af[mi][3] = A1s[tig + 4][mb + 8];
            }
#pragma unroll
            for (int ni = 0; ni < 6; ni++) {
                int nb = wn + ni * 8 + grp;
                uint2 b0 = B2s[tig][nb];
                uint2 b1 = B2s[tig + 4][nb];
                unsigned bfh[2] = {b0.x, b1.x};
                unsigned bfl[2] = {b0.y, b1.y};
#pragma unroll
                for (int mi = 0; mi < 2; mi++) {
                    mma_f16(acc[mi][ni], af[mi], bfl);
                    mma_f16(acc[mi][ni], af[mi], bfh);
                }
            }
        }
        __syncthreads();
    }

    float* out = g_part + (size_t)kz * PART_STRIDE;
#pragma unroll
    for (int mi = 0; mi < 2; mi++) {
#pragma unroll
        for (int ni = 0; ni < 6; ni++) {
            int col = wn + ni * 8 + 2 * tig;
            int row0 = m0 + wm + mi * 16 + grp;
            float2 v0 = make_float2(acc[mi][ni][0], acc[mi][ni][1]);
            float2 v1 = make_float2(acc[mi][ni][2], acc[mi][ni][3]);
            *(float2*)&out[(size_t)row0 * 192 + col] = v0;
            *(float2*)&out[(size_t)(row0 + 8) * 192 + col] = v1;
        }
    }
}

// ---------------- GRU scan (fused split-K reduce + bias) ----------------
__global__ void __launch_bounds__(192) gru_kernel(const float* __restrict__ h0,
                                                  const float* __restrict__ Wh,
                                                  const float* __restrict__ bn,
                                                  const float* __restrict__ bi,
                                                  float* __restrict__ hfinal) {
    int b = blockIdx.x, g = threadIdx.x;
    __shared__ float h[64];
    __shared__ float hg[192];
    __shared__ float sig[192];
    float w[64];
#pragma unroll
    for (int k = 0; k < 64; k++) w[k] = Wh[g * 64 + k];
    float bnv = (g < 64) ? bn[g] : 0.f;
    float biv = bi[g];
    if (g < 64) h[g] = h0[b * 64 + g];
    const float* P = g_part;
    int idx = (b * 128 + 0) * 192 + g;
    float q0 = P[idx], q1 = P[PART_STRIDE + idx];
    float q2 = P[2 * PART_STRIDE + idx], q3 = P[3 * PART_STRIDE + idx];
    __syncthreads();
    for (int t = 0; t < 128; t++) {
        float a0 = 0.f, a1 = 0.f, a2 = 0.f, a3 = 0.f;
#pragma unroll
        for (int k = 0; k < 64; k += 4) {
            a0 += w[k] * h[k];
            a1 += w[k + 1] * h[k + 1];
            a2 += w[k + 2] * h[k + 2];
            a3 += w[k + 3] * h[k + 3];
        }
        hg[g] = (a0 + a1) + (a2 + a3);
        sig[g] = biv + q0 + q1 + q2 + q3;
        __syncthreads();
        int tn = (t < 127) ? t + 1 : 127;
        int idxn = (b * 128 + tn) * 192 + g;
        q0 = P[idxn]; q1 = P[PART_STRIDE + idxn];
        q2 = P[2 * PART_STRIDE + idxn]; q3 = P[3 * PART_STRIDE + idxn];
        if (g < 64) {
            float rr = 1.f / (1.f + __expf(-(sig[g] + hg[g])));
            float zz = 1.f / (1.f + __expf(-(sig[64 + g] + hg[64 + g])));
            float nn = tanhf(sig[128 + g] + rr * (hg[128 + g] + bnv));
            float hn = (1.f - zz) * nn + zz * h[g];
            h[g] = hn;
            g_allh[(b * 128 + t) * 64 + g] = hn;
        }
        __syncthreads();
    }
    if (g < 64) hfinal[b * 64 + g] = h[g];
}

// ---------------- heads (256 CTAs x 16 rows) ----------------
#define HEADS_SMEM_BYTES (14816 * 4)
__global__ void __launch_bounds__(128) heads_kernel(
    const float* __restrict__ Wa1, const float* __restrict__ ba1,
    const float* __restrict__ Wa2, const float* __restrict__ ba2,
    const float* __restrict__ Wc1, const float* __restrict__ bc1,
    const float* __restrict__ Wc2, const float* __restrict__ bc2,
    float* __restrict__ logits, float* __restrict__ values) {
    extern __shared__ float s[];
    float* sWa1 = s;
    float* sWc1 = s + 4096;
    float* sWa2 = s + 8192;
    float* sWc2 = s + 14336;
    float* sba1 = s + 14400;
    float* sbc1 = s + 14464;
    float* sba2 = s + 14528;
    float* sh   = s + 14624;
    float* sa   = s + 14688;
    float* sc   = s + 14752;
    int tid = threadIdx.x;
    for (int i = tid; i < 4096; i += 128) { sWa1[i] = Wa1[i]; sWc1[i] = Wc1[i]; }
    for (int i = tid; i < 6144; i += 128) sWa2[i] = Wa2[i];
    if (tid < 64) { sWc2[tid] = Wc2[tid]; sba1[tid] = ba1[tid]; sbc1[tid] = bc1[tid]; }
    if (tid < 96) sba2[tid] = ba2[tid];
    float bc2v = bc2[0];
    __syncthreads();
    for (int r = blockIdx.x * 16; r < blockIdx.x * 16 + 16; r++) {
        if (tid < 64) sh[tid] = g_allh[r * 64 + tid];
        __syncthreads();
        {
            int j = tid & 63;
            const float* W = (tid < 64) ? sWa1 : sWc1;
            float acc = 0.f;
#pragma unroll
            for (int i = 0; i < 64; i++) acc += sh[i] * W[i * 64 + j];
            float v = tanhf(acc + ((tid < 64) ? sba1[j] : sbc1[j]));
            if (tid < 64) sa[j] = v; else sc[j] = v;
        }
        __syncthreads();
        if (tid < 96) {
            float acc = sba2[tid];
#pragma unroll
            for (int j = 0; j < 64; j++) acc += sa[j] * sWa2[j * 96 + tid];
            logits[r * 96 + tid] = acc;
        } else if (tid == 96) {
            float acc = bc2v;
#pragma unroll
            for (int j = 0; j < 64; j++) acc += sc[j] * sWc2[j];
            values[r] = acc;
        }
        __syncthreads();
    }
}

// ---------------- launch ----------------
extern "C" void kernel_launch(void* const* d_in, const int* in_sizes, int n_in,
                              void* d_out, int out_size) {
    const int*   positions = (const int*)d_in[0];
    const void*  umask     = d_in[1];
    const int*   tile      = (const int*)d_in[2];
    const int*   rpos      = (const int*)d_in[3];
    const void*  rmask     = d_in[4];
    const float* reward    = (const float*)d_in[5];
    const float* hidden    = (const float*)d_in[6];
    const float* emb_tile  = (const float*)d_in[7];
    const float* emb_unit  = (const float*)d_in[8];
    const float* w1 = (const float*)d_in[9];
    const float* b1 = (const float*)d_in[10];
    const float* w2 = (const float*)d_in[11];
    const float* b2 = (const float*)d_in[12];
    const float* w3 = (const float*)d_in[13];
    const float* b3 = (const float*)d_in[14];
    const float* Wi = (const float*)d_in[15];
    const float* Wh = (const float*)d_in[16];
    const float* bi = (const float*)d_in[17];
    const float* bn = (const float*)d_in[18];
    const float* Wa1 = (const float*)d_in[19];
    const float* ba1 = (const float*)d_in[20];
    const float* Wa2 = (const float*)d_in[21];
    const float* ba2 = (const float*)d_in[22];
    const float* Wc1 = (const float*)d_in[23];
    const float* bc1 = (const float*)d_in[24];
    const float* Wc2 = (const float*)d_in[25];
    const float* bc2 = (const float*)d_in[26];
    float* out = (float*)d_out;

    float* out_logits = out;
    float* out_values = out + 393216;
    float* out_hidden = out + 397312;

    const int conv_smem = CONV_SMEM_FLOATS * (int)sizeof(float);
    cudaFuncSetAttribute(conv_kernel, cudaFuncAttributeMaxDynamicSharedMemorySize, conv_smem);
    cudaFuncSetAttribute(heads_kernel, cudaFuncAttributeMaxDynamicSharedMemorySize, HEADS_SMEM_BYTES);

    conv_kernel<<<BS_, 256, conv_smem>>>(positions, umask, tile, rpos, rmask, reward,
                                         emb_tile, emb_unit, w1, b1, w2, b2, w3, b3);
    gemm_f16_kernel<<<dim3(64, 1, SPLITK), 256>>>(Wi);
    gru_kernel<<<32, 192>>>(hidden, Wh, bn, bi, out_hidden);
    heads_kernel<<<256, 128, HEADS_SMEM_BYTES>>>(Wa1, ba1, Wa2, ba2, Wc1, bc1, Wc2, bc2,
                                                 out_logits, out_values);
}